// round 1
// baseline (speedup 1.0000x reference)
#include <cuda_runtime.h>
#include <math.h>

#define Bsz 64
#define Nn  1029
#define Dd  768
#define Hh  12
#define dh  64
#define Kk  128
#define Rr  5
#define Mm  4
#define Pp  1024          // N - R
#define CTX 133           // R + K

// ---------------- scratch (static device globals: allocation-free) ----------
__device__ int   g_idx[Bsz];
__device__ float g_qctx[(size_t)Bsz * Kk * Dd];          // 6.29M
__device__ float g_scores[(size_t)Bsz * Kk * Pp];        // 8.39M
__device__ float g_ctx[(size_t)Bsz * CTX * Dd];          // 6.54M
__device__ float g_kv[(size_t)Bsz * CTX * 2 * Dd];       // 13.1M
__device__ float g_q[(size_t)Bsz * Nn * Dd];             // 50.6M
__device__ float g_y[(size_t)Bsz * Nn * Dd];             // 50.6M

// ---------------- kernel 1: cls_n, sims, argmax -----------------------------
__global__ void cls_kernel(const float* __restrict__ x,
                           const float* __restrict__ cent,
                           float* __restrict__ cls_out,   // may be null
                           float* __restrict__ idx_out)   // may be null
{
    int b = blockIdx.x;
    int tid = threadIdx.x;                 // 256 threads
    __shared__ float xs[Dd];
    __shared__ float red[256];
    __shared__ float sims[Mm];
    __shared__ float inv_s;

    float ss = 0.f;
    for (int i = tid; i < Dd; i += 256) {
        float v = x[(size_t)b * Nn * Dd + i];
        xs[i] = v;
        ss += v * v;
    }
    red[tid] = ss; __syncthreads();
    for (int s = 128; s > 0; s >>= 1) { if (tid < s) red[tid] += red[tid + s]; __syncthreads(); }
    if (tid == 0) {
        float nrm = sqrtf(red[0]);
        inv_s = 1.f / fmaxf(nrm, 1e-12f);
    }
    __syncthreads();
    float inv = inv_s;

    for (int m = 0; m < Mm; m++) {
        float p = 0.f;
        for (int i = tid; i < Dd; i += 256) p += xs[i] * cent[m * Dd + i];
        red[tid] = p; __syncthreads();
        for (int s = 128; s > 0; s >>= 1) { if (tid < s) red[tid] += red[tid + s]; __syncthreads(); }
        if (tid == 0) sims[m] = red[0] * inv;
        __syncthreads();
    }
    if (tid == 0) {
        int best = 0; float bv = sims[0];
        for (int m = 1; m < Mm; m++) if (sims[m] > bv) { bv = sims[m]; best = m; }
        g_idx[b] = best;
        if (idx_out) idx_out[b] = (float)best;
    }
    if (cls_out)
        for (int i = tid; i < Dd; i += 256)
            cls_out[(size_t)b * Dd + i] = xs[i] * inv;
}

// ---------------- kernel 2: gather Q_banks[idx] + copy xreg into ctx --------
__global__ void gather_qctx_kernel(const float* __restrict__ Qb)
{
    size_t total = (size_t)Bsz * Kk * Dd;
    for (size_t i = (size_t)blockIdx.x * blockDim.x + threadIdx.x; i < total;
         i += (size_t)gridDim.x * blockDim.x) {
        int b = (int)(i / ((size_t)Kk * Dd));
        size_t r = i - (size_t)b * Kk * Dd;
        g_qctx[i] = Qb[(size_t)g_idx[b] * Kk * Dd + r];
    }
}

__global__ void xreg_kernel(const float* __restrict__ x)
{
    int i = blockIdx.x * blockDim.x + threadIdx.x;
    const int total = Bsz * Rr * Dd;
    if (i < total) {
        int b = i / (Rr * Dd);
        int r = i - b * (Rr * Dd);
        g_ctx[(size_t)b * CTX * Dd + r] = x[(size_t)b * Nn * Dd + r];
    }
}

// ---------------- generic tiled fp32 GEMM ------------------------------------
// C[M,N] = A[M,K] @ op(B) (+ bias), op = B[K,N] (NN) or B[N,K]^T (NT).
// Tiles: 128x64x16, 256 threads, 8x4 microtile.
template<bool TRANSB, bool BIAS>
__global__ __launch_bounds__(256)
void gemm_kernel(const float* __restrict__ A, const float* __restrict__ Bm,
                 const float* __restrict__ bias, float* __restrict__ C,
                 int M, int N, int Kd, int lda, int ldb, int ldc,
                 long long sA, long long sB, long long sC)
{
    const int BM = 128, BN = 64, BK = 16;
    __shared__ float As[BK][BM + 4];
    __shared__ float Bs[BK][BN + 4];

    const float* Ab = A  + (long long)blockIdx.z * sA;
    const float* Bb = Bm + (long long)blockIdx.z * sB;
    float*       Cb = C  + (long long)blockIdx.z * sC;

    int row0 = blockIdx.y * BM;
    int col0 = blockIdx.x * BN;
    int tid = threadIdx.x;
    int ty = tid >> 4, tx = tid & 15;

    float acc[8][4];
#pragma unroll
    for (int i = 0; i < 8; i++)
#pragma unroll
        for (int j = 0; j < 4; j++) acc[i][j] = 0.f;

    for (int k0 = 0; k0 < Kd; k0 += BK) {
        // A tile: 128x16, two float4 per thread (Kd is always a multiple of 16)
#pragma unroll
        for (int it = 0; it < 2; it++) {
            int lin = tid + it * 256;      // 0..511
            int r  = lin >> 2;             // 0..127
            int c4 = lin & 3;              // 0..3
            float4 v = make_float4(0.f, 0.f, 0.f, 0.f);
            if (row0 + r < M)
                v = *reinterpret_cast<const float4*>(&Ab[(size_t)(row0 + r) * lda + k0 + c4 * 4]);
            As[c4 * 4 + 0][r] = v.x;
            As[c4 * 4 + 1][r] = v.y;
            As[c4 * 4 + 2][r] = v.z;
            As[c4 * 4 + 3][r] = v.w;
        }
        // B tile
        if (!TRANSB) {
            int r  = tid >> 4;             // k 0..15
            int c4 = tid & 15;             // col group
            float4 v = make_float4(0.f, 0.f, 0.f, 0.f);
            if (col0 + c4 * 4 < N)
                v = *reinterpret_cast<const float4*>(&Bb[(size_t)(k0 + r) * ldb + col0 + c4 * 4]);
            Bs[r][c4 * 4 + 0] = v.x;
            Bs[r][c4 * 4 + 1] = v.y;
            Bs[r][c4 * 4 + 2] = v.z;
            Bs[r][c4 * 4 + 3] = v.w;
        } else {
            int n  = tid >> 2;             // 0..63 (B row = output col)
            int c4 = tid & 3;              // k group
            float4 v = make_float4(0.f, 0.f, 0.f, 0.f);
            if (col0 + n < N)
                v = *reinterpret_cast<const float4*>(&Bb[(size_t)(col0 + n) * ldb + k0 + c4 * 4]);
            Bs[c4 * 4 + 0][n] = v.x;
            Bs[c4 * 4 + 1][n] = v.y;
            Bs[c4 * 4 + 2][n] = v.z;
            Bs[c4 * 4 + 3][n] = v.w;
        }
        __syncthreads();

#pragma unroll
        for (int kk = 0; kk < BK; kk++) {
            float4 a0 = *reinterpret_cast<const float4*>(&As[kk][ty * 8]);
            float4 a1 = *reinterpret_cast<const float4*>(&As[kk][ty * 8 + 4]);
            float4 bv = *reinterpret_cast<const float4*>(&Bs[kk][tx * 4]);
            float a[8] = {a0.x, a0.y, a0.z, a0.w, a1.x, a1.y, a1.z, a1.w};
            float bb[4] = {bv.x, bv.y, bv.z, bv.w};
#pragma unroll
            for (int i = 0; i < 8; i++)
#pragma unroll
                for (int j = 0; j < 4; j++)
                    acc[i][j] += a[i] * bb[j];
        }
        __syncthreads();
    }

#pragma unroll
    for (int i = 0; i < 8; i++) {
        int r = row0 + ty * 8 + i;
        if (r >= M) continue;
#pragma unroll
        for (int j = 0; j < 4; j++) {
            int c = col0 + tx * 4 + j;
            if (c >= N) continue;
            float v = acc[i][j];
            if (BIAS) v += bias[c];
            Cb[(size_t)r * ldc + c] = v;
        }
    }
}

// ---------------- kernel: row softmax over P=1024 ---------------------------
__global__ void softmax_kernel(float* __restrict__ s)
{
    int row = blockIdx.x;                  // B*K rows
    float4* p4 = reinterpret_cast<float4*>(s + (size_t)row * Pp);
    int tid = threadIdx.x;                 // 256
    __shared__ float red[256];

    float4 v = p4[tid];
    float mx = fmaxf(fmaxf(v.x, v.y), fmaxf(v.z, v.w));
    red[tid] = mx; __syncthreads();
    for (int st = 128; st > 0; st >>= 1) { if (tid < st) red[tid] = fmaxf(red[tid], red[tid + st]); __syncthreads(); }
    mx = red[0]; __syncthreads();

    v.x = __expf(v.x - mx); v.y = __expf(v.y - mx);
    v.z = __expf(v.z - mx); v.w = __expf(v.w - mx);
    float sm = v.x + v.y + v.z + v.w;
    red[tid] = sm; __syncthreads();
    for (int st = 128; st > 0; st >>= 1) { if (tid < st) red[tid] += red[tid + st]; __syncthreads(); }
    float inv = 1.f / red[0];
    v.x *= inv; v.y *= inv; v.z *= inv; v.w *= inv;
    p4[tid] = v;
}

// ---------------- fused attention: softmax(q k^T / 8) v ---------------------
// grid: (ceil(N/128), B*H), 128 threads, one query row per thread.
__global__ __launch_bounds__(128)
void attn_kernel(float* __restrict__ y)
{
    int bh = blockIdx.y;
    int b = bh / Hh, h = bh % Hh;
    int n = blockIdx.x * 128 + threadIdx.x;
    bool valid = (n < Nn);

    __shared__ float Ks[64][64];
    __shared__ float Vs[64][64];

    float q[64];
    const float* qrow = &g_q[((size_t)b * Nn + (valid ? n : 0)) * Dd + h * dh];
#pragma unroll
    for (int i = 0; i < 64; i += 4) {
        float4 v = valid ? *reinterpret_cast<const float4*>(&qrow[i])
                         : make_float4(0.f, 0.f, 0.f, 0.f);
        q[i] = v.x; q[i + 1] = v.y; q[i + 2] = v.z; q[i + 3] = v.w;
    }

    float mrun = -1e30f, l = 0.f;
    float acc[64];
#pragma unroll
    for (int i = 0; i < 64; i++) acc[i] = 0.f;
    const float scale = 0.125f;

    for (int m0 = 0; m0 < CTX; m0 += 64) {
        int cnt = min(64, CTX - m0);
        __syncthreads();
        for (int i = threadIdx.x; i < cnt * 64; i += 128) {
            int mm = i >> 6, dd = i & 63;
            size_t base = ((size_t)b * CTX + m0 + mm) * (2 * Dd) + h * dh + dd;
            Ks[mm][dd] = g_kv[base];
            Vs[mm][dd] = g_kv[base + Dd];
        }
        __syncthreads();

        for (int mm = 0; mm < cnt; mm++) {
            float s0 = 0.f, s1 = 0.f, s2 = 0.f, s3 = 0.f;
#pragma unroll
            for (int i = 0; i < 64; i += 4) {
                float4 kk = *reinterpret_cast<const float4*>(&Ks[mm][i]);
                s0 += q[i] * kk.x;  s1 += q[i + 1] * kk.y;
                s2 += q[i + 2] * kk.z; s3 += q[i + 3] * kk.w;
            }
            float s = (s0 + s1 + s2 + s3) * scale;
            if (s <= mrun) {
                float p = __expf(s - mrun);
                l += p;
#pragma unroll
                for (int i = 0; i < 64; i += 4) {
                    float4 vv = *reinterpret_cast<const float4*>(&Vs[mm][i]);
                    acc[i]     += p * vv.x;  acc[i + 1] += p * vv.y;
                    acc[i + 2] += p * vv.z;  acc[i + 3] += p * vv.w;
                }
            } else {
                float f = __expf(mrun - s);
                l = l * f + 1.f;
#pragma unroll
                for (int i = 0; i < 64; i += 4) {
                    float4 vv = *reinterpret_cast<const float4*>(&Vs[mm][i]);
                    acc[i]     = acc[i]     * f + vv.x;
                    acc[i + 1] = acc[i + 1] * f + vv.y;
                    acc[i + 2] = acc[i + 2] * f + vv.z;
                    acc[i + 3] = acc[i + 3] * f + vv.w;
                }
                mrun = s;
            }
        }
    }

    if (valid) {
        float inv = 1.f / l;
        float* yo = &y[((size_t)b * Nn + n) * Dd + h * dh];
#pragma unroll
        for (int i = 0; i < 64; i++) yo[i] = acc[i] * inv;
    }
}

// ---------------- launch -----------------------------------------------------
extern "C" void kernel_launch(void* const* d_in, const int* in_sizes, int n_in,
                              void* d_out, int out_size)
{
    const float* x    = (const float*)d_in[0];
    const float* Qb   = (const float*)d_in[1];
    const float* Wq   = (const float*)d_in[2];
    const float* Wctx = (const float*)d_in[3];
    const float* bctx = (const float*)d_in[4];
    const float* Wout = (const float*)d_in[5];
    const float* bout = (const float*)d_in[6];
    const float* cent = (const float*)d_in[7];
    float* out = (float*)d_out;

    float *p_qctx, *p_scores, *p_ctx, *p_kv, *p_q, *p_y;
    cudaGetSymbolAddress((void**)&p_qctx,   g_qctx);
    cudaGetSymbolAddress((void**)&p_scores, g_scores);
    cudaGetSymbolAddress((void**)&p_ctx,    g_ctx);
    cudaGetSymbolAddress((void**)&p_kv,     g_kv);
    cudaGetSymbolAddress((void**)&p_q,      g_q);
    cudaGetSymbolAddress((void**)&p_y,      g_y);

    const size_t main_sz = (size_t)Bsz * Nn * Dd;           // 50,577,408
    float* cls_out = nullptr;
    float* idx_out = nullptr;
    if ((size_t)out_size >= main_sz + (size_t)Bsz * Dd + Bsz) {
        cls_out = out + main_sz;
        idx_out = out + main_sz + (size_t)Bsz * Dd;
    }

    // 1) cls_n / sims / argmax
    cls_kernel<<<Bsz, 256>>>(x, cent, cls_out, idx_out);

    // 2) gather Q_banks[idx] ; copy xreg into ctx[:, :R, :]
    gather_qctx_kernel<<<4096, 256>>>(Qb);
    xreg_kernel<<<(Bsz * Rr * Dd + 255) / 256, 256>>>(x);

    // 3) scores[b] = q_ctx[b] @ xp[b]^T   (NT, batched over B)
    gemm_kernel<true, false><<<dim3(Pp / 64, 1, Bsz), 256>>>(
        p_qctx, x + (size_t)Rr * Dd, nullptr, p_scores,
        Kk, Pp, Dd, Dd, Dd, Pp,
        (long long)Kk * Dd, (long long)Nn * Dd, (long long)Kk * Pp);

    // 4) softmax over p
    softmax_kernel<<<Bsz * Kk, 256>>>(p_scores);

    // 5) ctx[:, R:, :] = attn @ xp   (NN, batched)
    gemm_kernel<false, false><<<dim3(Dd / 64, 1, Bsz), 256>>>(
        p_scores, x + (size_t)Rr * Dd, nullptr, p_ctx + (size_t)Rr * Dd,
        Kk, Dd, Pp, Pp, Dd, Dd,
        (long long)Kk * Pp, (long long)Nn * Dd, (long long)CTX * Dd);

    // 6) kv = ctx @ Wctx + bctx   (single GEMM, M = B*133)
    gemm_kernel<false, true><<<dim3((2 * Dd) / 64, (Bsz * CTX + 127) / 128, 1), 256>>>(
        p_ctx, Wctx, bctx, p_kv,
        Bsz * CTX, 2 * Dd, Dd, Dd, 2 * Dd, 2 * Dd, 0, 0, 0);

    // 7) q = x @ Wq   (M = B*N)
    gemm_kernel<false, false><<<dim3(Dd / 64, (Bsz * Nn + 127) / 128, 1), 256>>>(
        x, Wq, nullptr, p_q,
        Bsz * Nn, Dd, Dd, Dd, Dd, Dd, 0, 0, 0);

    // 8) fused attention -> y (already in [B, N, H*d] layout)
    attn_kernel<<<dim3((Nn + 127) / 128, Bsz * Hh), 128>>>(p_y);

    // 9) out = y @ Wout + bout
    gemm_kernel<false, true><<<dim3(Dd / 64, (Bsz * Nn + 127) / 128, 1), 256>>>(
        p_y, Wout, bout, out,
        Bsz * Nn, Dd, Dd, Dd, Dd, Dd, 0, 0, 0);
}

// round 2
// speedup vs baseline: 1.8329x; 1.8329x over previous
#include <cuda_runtime.h>
#include <math.h>

#define Bsz 64
#define Nn  1029
#define Dd  768
#define Hh  12
#define dh  64
#define Kk  128
#define Rr  5
#define Mm  4
#define Pp  1024          // N - R
#define CTX 133           // R + K

// ---------------- scratch (static device globals: allocation-free) ----------
__device__ int   g_idx[Bsz];
__device__ float g_qctx[(size_t)Bsz * Kk * Dd];
__device__ float g_scores[(size_t)Bsz * Kk * Pp];
__device__ float g_ctx[(size_t)Bsz * CTX * Dd];
__device__ float g_kv[(size_t)Bsz * CTX * 2 * Dd];
__device__ float g_q[(size_t)Bsz * Nn * Dd];
__device__ float g_y[(size_t)Bsz * Nn * Dd];

// ---------------- helpers ----------------------------------------------------
__device__ __forceinline__ unsigned f2tf(float x) {
    unsigned r;
    asm("cvt.rna.tf32.f32 %0, %1;" : "=r"(r) : "f"(x));
    return r;
}

__device__ __forceinline__ void mma_tf32(float* c, const unsigned* a, const unsigned* b) {
    asm volatile(
        "mma.sync.aligned.m16n8k8.row.col.f32.tf32.tf32.f32 "
        "{%0,%1,%2,%3}, {%4,%5,%6,%7}, {%8,%9}, {%0,%1,%2,%3};\n"
        : "+f"(c[0]), "+f"(c[1]), "+f"(c[2]), "+f"(c[3])
        : "r"(a[0]), "r"(a[1]), "r"(a[2]), "r"(a[3]), "r"(b[0]), "r"(b[1]));
}

// ---------------- kernel 1: cls_n, sims, argmax -----------------------------
__global__ void cls_kernel(const float* __restrict__ x,
                           const float* __restrict__ cent,
                           float* __restrict__ cls_out,
                           float* __restrict__ idx_out)
{
    int b = blockIdx.x;
    int tid = threadIdx.x;                 // 256 threads
    __shared__ float xs[Dd];
    __shared__ float red[256];
    __shared__ float sims[Mm];
    __shared__ float inv_s;

    float ss = 0.f;
    for (int i = tid; i < Dd; i += 256) {
        float v = x[(size_t)b * Nn * Dd + i];
        xs[i] = v;
        ss += v * v;
    }
    red[tid] = ss; __syncthreads();
    for (int s = 128; s > 0; s >>= 1) { if (tid < s) red[tid] += red[tid + s]; __syncthreads(); }
    if (tid == 0) {
        float nrm = sqrtf(red[0]);
        inv_s = 1.f / fmaxf(nrm, 1e-12f);
    }
    __syncthreads();
    float inv = inv_s;

    for (int m = 0; m < Mm; m++) {
        float p = 0.f;
        for (int i = tid; i < Dd; i += 256) p += xs[i] * cent[m * Dd + i];
        red[tid] = p; __syncthreads();
        for (int s = 128; s > 0; s >>= 1) { if (tid < s) red[tid] += red[tid + s]; __syncthreads(); }
        if (tid == 0) sims[m] = red[0] * inv;
        __syncthreads();
    }
    if (tid == 0) {
        int best = 0; float bv = sims[0];
        for (int m = 1; m < Mm; m++) if (sims[m] > bv) { bv = sims[m]; best = m; }
        g_idx[b] = best;
        if (idx_out) idx_out[b] = (float)best;
    }
    if (cls_out)
        for (int i = tid; i < Dd; i += 256)
            cls_out[(size_t)b * Dd + i] = xs[i] * inv;
}

// ---------------- kernel 2: gather + xreg ------------------------------------
__global__ void gather_qctx_kernel(const float* __restrict__ Qb)
{
    size_t total = (size_t)Bsz * Kk * Dd;
    for (size_t i = (size_t)blockIdx.x * blockDim.x + threadIdx.x; i < total;
         i += (size_t)gridDim.x * blockDim.x) {
        int b = (int)(i / ((size_t)Kk * Dd));
        size_t r = i - (size_t)b * Kk * Dd;
        g_qctx[i] = Qb[(size_t)g_idx[b] * Kk * Dd + r];
    }
}

__global__ void xreg_kernel(const float* __restrict__ x)
{
    int i = blockIdx.x * blockDim.x + threadIdx.x;
    const int total = Bsz * Rr * Dd;
    if (i < total) {
        int b = i / (Rr * Dd);
        int r = i - b * (Rr * Dd);
        g_ctx[(size_t)b * CTX * Dd + r] = x[(size_t)b * Nn * Dd + r];
    }
}

// ---------------- tf32 tensor-core GEMM --------------------------------------
// C[M,N] = A[M,K] @ op(B) (+bias). op = B[K,N] (NN) or B[N,K]^T (NT, TRANSB).
// Block tile 128x128x32, 256 threads (8 warps as 4m x 2n), warp tile 32x64,
// mma.sync m16n8k8 tf32. N and K must be multiples of 128 / 32 (true for all
// call sites); M is guarded.
template<bool TRANSB, bool BIAS>
__global__ __launch_bounds__(256)
void mma_gemm(const float* __restrict__ A, const float* __restrict__ Bm,
              const float* __restrict__ bias, float* __restrict__ C,
              int M, int N, int Kd, int lda, int ldb, int ldc,
              long long sA, long long sB, long long sC)
{
    // As: [128][36] (m-major, padded) ; Bs: NT [128][36], NN [32][136]
    __shared__ unsigned As[128 * 36];
    __shared__ unsigned Bs[TRANSB ? 128 * 36 : 32 * 136];

    const float* Ab = A  + (long long)blockIdx.z * sA;
    const float* Bb = Bm + (long long)blockIdx.z * sB;
    float*       Cb = C  + (long long)blockIdx.z * sC;

    const int row0 = blockIdx.y * 128;
    const int col0 = blockIdx.x * 128;
    const int tid  = threadIdx.x;
    const int lane = tid & 31;
    const int warp = tid >> 5;
    const int wm = warp >> 1;       // 0..3
    const int wn = warp & 1;        // 0..1
    const int g   = lane >> 2;      // 0..7
    const int tig = lane & 3;       // 0..3

    float acc[2][8][4];
#pragma unroll
    for (int im = 0; im < 2; im++)
#pragma unroll
        for (int in = 0; in < 8; in++)
#pragma unroll
            for (int j = 0; j < 4; j++) acc[im][in][j] = 0.f;

    float4 aR[4], bR[4];

    const int nk = Kd >> 5;

    // ---- staging loads --------------------------------------------------
    auto loadA = [&](int k0) {
#pragma unroll
        for (int it = 0; it < 4; it++) {
            int id = tid + it * 256;          // 0..1023
            int r  = id >> 3;                 // 0..127
            int c4 = id & 7;                  // 0..7
            if (row0 + r < M)
                aR[it] = *reinterpret_cast<const float4*>(&Ab[(size_t)(row0 + r) * lda + k0 + c4 * 4]);
            else
                aR[it] = make_float4(0.f, 0.f, 0.f, 0.f);
        }
    };
    auto loadB = [&](int k0) {
#pragma unroll
        for (int it = 0; it < 4; it++) {
            int id = tid + it * 256;
            if (TRANSB) {
                int n  = id >> 3;
                int c4 = id & 7;
                bR[it] = *reinterpret_cast<const float4*>(&Bb[(size_t)(col0 + n) * ldb + k0 + c4 * 4]);
            } else {
                int k  = id >> 5;             // 0..31
                int n4 = id & 31;             // 0..31
                bR[it] = *reinterpret_cast<const float4*>(&Bb[(size_t)(k0 + k) * ldb + col0 + n4 * 4]);
            }
        }
    };
    auto storeA = [&]() {
#pragma unroll
        for (int it = 0; it < 4; it++) {
            int id = tid + it * 256;
            int r  = id >> 3;
            int c4 = id & 7;
            unsigned* p = &As[r * 36 + c4 * 4];
            p[0] = f2tf(aR[it].x); p[1] = f2tf(aR[it].y);
            p[2] = f2tf(aR[it].z); p[3] = f2tf(aR[it].w);
        }
    };
    auto storeB = [&]() {
#pragma unroll
        for (int it = 0; it < 4; it++) {
            int id = tid + it * 256;
            if (TRANSB) {
                int n  = id >> 3;
                int c4 = id & 7;
                unsigned* p = &Bs[n * 36 + c4 * 4];
                p[0] = f2tf(bR[it].x); p[1] = f2tf(bR[it].y);
                p[2] = f2tf(bR[it].z); p[3] = f2tf(bR[it].w);
            } else {
                int k  = id >> 5;
                int n4 = id & 31;
                unsigned* p = &Bs[k * 136 + n4 * 4];
                p[0] = f2tf(bR[it].x); p[1] = f2tf(bR[it].y);
                p[2] = f2tf(bR[it].z); p[3] = f2tf(bR[it].w);
            }
        }
    };

    loadA(0); loadB(0);

    for (int i = 0; i < nk; i++) {
        storeA(); storeB();
        __syncthreads();
        if (i + 1 < nk) { loadA((i + 1) * 32); loadB((i + 1) * 32); }

#pragma unroll
        for (int kk = 0; kk < 4; kk++) {
            const int ka = kk * 8 + tig;
            unsigned afr[2][4], bfr[8][2];
#pragma unroll
            for (int im = 0; im < 2; im++) {
                int r = wm * 32 + im * 16 + g;
                afr[im][0] = As[r * 36 + ka];
                afr[im][1] = As[(r + 8) * 36 + ka];
                afr[im][2] = As[r * 36 + ka + 4];
                afr[im][3] = As[(r + 8) * 36 + ka + 4];
            }
#pragma unroll
            for (int in = 0; in < 8; in++) {
                int bn = wn * 64 + in * 8 + g;
                if (TRANSB) {
                    bfr[in][0] = Bs[bn * 36 + ka];
                    bfr[in][1] = Bs[bn * 36 + ka + 4];
                } else {
                    bfr[in][0] = Bs[ka * 136 + bn];
                    bfr[in][1] = Bs[(ka + 4) * 136 + bn];
                }
            }
#pragma unroll
            for (int im = 0; im < 2; im++)
#pragma unroll
                for (int in = 0; in < 8; in++)
                    mma_tf32(acc[im][in], afr[im], bfr[in]);
        }
        __syncthreads();
    }

    // ---- epilogue ---------------------------------------------------------
#pragma unroll
    for (int im = 0; im < 2; im++) {
        int rb = row0 + wm * 32 + im * 16 + g;
#pragma unroll
        for (int in = 0; in < 8; in++) {
            int cb = col0 + wn * 64 + in * 8 + 2 * tig;
            float b0 = BIAS ? bias[cb] : 0.f;
            float b1 = BIAS ? bias[cb + 1] : 0.f;
            if (rb < M) {
                Cb[(size_t)rb * ldc + cb]     = acc[im][in][0] + b0;
                Cb[(size_t)rb * ldc + cb + 1] = acc[im][in][1] + b1;
            }
            if (rb + 8 < M) {
                Cb[(size_t)(rb + 8) * ldc + cb]     = acc[im][in][2] + b0;
                Cb[(size_t)(rb + 8) * ldc + cb + 1] = acc[im][in][3] + b1;
            }
        }
    }
}

// ---------------- kernel: row softmax over P=1024 ---------------------------
__global__ void softmax_kernel(float* __restrict__ s)
{
    int row = blockIdx.x;                  // B*K rows
    float4* p4 = reinterpret_cast<float4*>(s + (size_t)row * Pp);
    int tid = threadIdx.x;                 // 256
    __shared__ float red[256];

    float4 v = p4[tid];
    float mx = fmaxf(fmaxf(v.x, v.y), fmaxf(v.z, v.w));
    red[tid] = mx; __syncthreads();
    for (int st = 128; st > 0; st >>= 1) { if (tid < st) red[tid] = fmaxf(red[tid], red[tid + st]); __syncthreads(); }
    mx = red[0]; __syncthreads();

    v.x = __expf(v.x - mx); v.y = __expf(v.y - mx);
    v.z = __expf(v.z - mx); v.w = __expf(v.w - mx);
    float sm = v.x + v.y + v.z + v.w;
    red[tid] = sm; __syncthreads();
    for (int st = 128; st > 0; st >>= 1) { if (tid < st) red[tid] += red[tid + st]; __syncthreads(); }
    float inv = 1.f / red[0];
    v.x *= inv; v.y *= inv; v.z *= inv; v.w *= inv;
    p4[tid] = v;
}

// ---------------- fused attention: softmax(q k^T / 8) v ---------------------
__global__ __launch_bounds__(128)
void attn_kernel(float* __restrict__ y)
{
    int bh = blockIdx.y;
    int b = bh / Hh, h = bh % Hh;
    int n = blockIdx.x * 128 + threadIdx.x;
    bool valid = (n < Nn);

    __shared__ float Ks[64][64];
    __shared__ float Vs[64][64];

    float q[64];
    const float* qrow = &g_q[((size_t)b * Nn + (valid ? n : 0)) * Dd + h * dh];
#pragma unroll
    for (int i = 0; i < 64; i += 4) {
        float4 v = valid ? *reinterpret_cast<const float4*>(&qrow[i])
                         : make_float4(0.f, 0.f, 0.f, 0.f);
        q[i] = v.x; q[i + 1] = v.y; q[i + 2] = v.z; q[i + 3] = v.w;
    }

    float mrun = -1e30f, l = 0.f;
    float acc[64];
#pragma unroll
    for (int i = 0; i < 64; i++) acc[i] = 0.f;
    const float scale = 0.125f;

    for (int m0 = 0; m0 < CTX; m0 += 64) {
        int cnt = min(64, CTX - m0);
        __syncthreads();
        for (int i = threadIdx.x; i < cnt * 64; i += 128) {
            int mm = i >> 6, dd = i & 63;
            size_t base = ((size_t)b * CTX + m0 + mm) * (2 * Dd) + h * dh + dd;
            Ks[mm][dd] = g_kv[base];
            Vs[mm][dd] = g_kv[base + Dd];
        }
        __syncthreads();

        for (int mm = 0; mm < cnt; mm++) {
            float s0 = 0.f, s1 = 0.f, s2 = 0.f, s3 = 0.f;
#pragma unroll
            for (int i = 0; i < 64; i += 4) {
                float4 kk = *reinterpret_cast<const float4*>(&Ks[mm][i]);
                s0 += q[i] * kk.x;  s1 += q[i + 1] * kk.y;
                s2 += q[i + 2] * kk.z; s3 += q[i + 3] * kk.w;
            }
            float s = (s0 + s1 + s2 + s3) * scale;
            if (s <= mrun) {
                float p = __expf(s - mrun);
                l += p;
#pragma unroll
                for (int i = 0; i < 64; i += 4) {
                    float4 vv = *reinterpret_cast<const float4*>(&Vs[mm][i]);
                    acc[i]     += p * vv.x;  acc[i + 1] += p * vv.y;
                    acc[i + 2] += p * vv.z;  acc[i + 3] += p * vv.w;
                }
            } else {
                float f = __expf(mrun - s);
                l = l * f + 1.f;
#pragma unroll
                for (int i = 0; i < 64; i += 4) {
                    float4 vv = *reinterpret_cast<const float4*>(&Vs[mm][i]);
                    acc[i]     = acc[i]     * f + vv.x;
                    acc[i + 1] = acc[i + 1] * f + vv.y;
                    acc[i + 2] = acc[i + 2] * f + vv.z;
                    acc[i + 3] = acc[i + 3] * f + vv.w;
                }
                mrun = s;
            }
        }
    }

    if (valid) {
        float inv = 1.f / l;
        float* yo = &y[((size_t)b * Nn + n) * Dd + h * dh];
#pragma unroll
        for (int i = 0; i < 64; i++) yo[i] = acc[i] * inv;
    }
}

// ---------------- launch -----------------------------------------------------
extern "C" void kernel_launch(void* const* d_in, const int* in_sizes, int n_in,
                              void* d_out, int out_size)
{
    const float* x    = (const float*)d_in[0];
    const float* Qb   = (const float*)d_in[1];
    const float* Wq   = (const float*)d_in[2];
    const float* Wctx = (const float*)d_in[3];
    const float* bctx = (const float*)d_in[4];
    const float* Wout = (const float*)d_in[5];
    const float* bout = (const float*)d_in[6];
    const float* cent = (const float*)d_in[7];
    float* out = (float*)d_out;

    float *p_qctx, *p_scores, *p_ctx, *p_kv, *p_q, *p_y;
    cudaGetSymbolAddress((void**)&p_qctx,   g_qctx);
    cudaGetSymbolAddress((void**)&p_scores, g_scores);
    cudaGetSymbolAddress((void**)&p_ctx,    g_ctx);
    cudaGetSymbolAddress((void**)&p_kv,     g_kv);
    cudaGetSymbolAddress((void**)&p_q,      g_q);
    cudaGetSymbolAddress((void**)&p_y,      g_y);

    const size_t main_sz = (size_t)Bsz * Nn * Dd;
    float* cls_out = nullptr;
    float* idx_out = nullptr;
    if ((size_t)out_size >= main_sz + (size_t)Bsz * Dd + Bsz) {
        cls_out = out + main_sz;
        idx_out = out + main_sz + (size_t)Bsz * Dd;
    }

    // 1) cls_n / sims / argmax
    cls_kernel<<<Bsz, 256>>>(x, cent, cls_out, idx_out);

    // 2) gather Q_banks[idx] ; copy xreg into ctx[:, :R, :]
    gather_qctx_kernel<<<4096, 256>>>(Qb);
    xreg_kernel<<<(Bsz * Rr * Dd + 255) / 256, 256>>>(x);

    // 3) scores[b] = q_ctx[b] @ xp[b]^T   (NT, batched over B)
    mma_gemm<true, false><<<dim3(Pp / 128, 1, Bsz), 256>>>(
        p_qctx, x + (size_t)Rr * Dd, nullptr, p_scores,
        Kk, Pp, Dd, Dd, Dd, Pp,
        (long long)Kk * Dd, (long long)Nn * Dd, (long long)Kk * Pp);

    // 4) softmax over p
    softmax_kernel<<<Bsz * Kk, 256>>>(p_scores);

    // 5) ctx[:, R:, :] = attn @ xp   (NN, batched)
    mma_gemm<false, false><<<dim3(Dd / 128, 1, Bsz), 256>>>(
        p_scores, x + (size_t)Rr * Dd, nullptr, p_ctx + (size_t)Rr * Dd,
        Kk, Dd, Pp, Pp, Dd, Dd,
        (long long)Kk * Pp, (long long)Nn * Dd, (long long)CTX * Dd);

    // 6) kv = ctx @ Wctx + bctx
    mma_gemm<false, true><<<dim3((2 * Dd) / 128, (Bsz * CTX + 127) / 128, 1), 256>>>(
        p_ctx, Wctx, bctx, p_kv,
        Bsz * CTX, 2 * Dd, Dd, Dd, 2 * Dd, 2 * Dd, 0, 0, 0);

    // 7) q = x @ Wq
    mma_gemm<false, false><<<dim3(Dd / 128, (Bsz * Nn + 127) / 128, 1), 256>>>(
        x, Wq, nullptr, p_q,
        Bsz * Nn, Dd, Dd, Dd, Dd, Dd, 0, 0, 0);

    // 8) fused attention -> y
    attn_kernel<<<dim3((Nn + 127) / 128, Bsz * Hh), 128>>>(p_y);

    // 9) out = y @ Wout + bout
    mma_gemm<false, true><<<dim3(Dd / 128, (Bsz * Nn + 127) / 128, 1), 256>>>(
        p_y, Wout, bout, out,
        Bsz * Nn, Dd, Dd, Dd, Dd, Dd, 0, 0, 0);
}

// round 3
// speedup vs baseline: 3.3966x; 1.8531x over previous
#include <cuda_runtime.h>
#include <math.h>

#define Bsz 64
#define Nn  1029
#define Dd  768
#define Hh  12
#define dh  64
#define Kk  128
#define Rr  5
#define Mm  4
#define Pp  1024          // N - R
#define CTX 133           // R + K
#define CTXP 136          // padded keys

// ---------------- scratch (static device globals: allocation-free) ----------
__device__ int   g_idx[Bsz];
__device__ float g_xtf[(size_t)Bsz * Nn * Dd];
__device__ float g_wq[Dd * Dd];
__device__ float g_wctx[Dd * 2 * Dd];
__device__ float g_wout[Dd * Dd];
__device__ float g_qctx[(size_t)Bsz * Kk * Dd];
__device__ float g_scores[(size_t)Bsz * Kk * Pp];
__device__ float g_ctx[(size_t)Bsz * CTX * Dd];
__device__ float g_kv[(size_t)Bsz * CTX * 2 * Dd];
__device__ float g_q[(size_t)Bsz * Nn * Dd];
__device__ float g_y[(size_t)Bsz * Nn * Dd];

// ---------------- helpers ----------------------------------------------------
__device__ __forceinline__ float rnaf(float x) {
    unsigned r;
    asm("cvt.rna.tf32.f32 %0, %1;" : "=r"(r) : "f"(x));
    return __uint_as_float(r);
}

__device__ __forceinline__ void mma_tf32(float* c, const unsigned* a, const unsigned* b) {
    asm volatile(
        "mma.sync.aligned.m16n8k8.row.col.f32.tf32.tf32.f32 "
        "{%0,%1,%2,%3}, {%4,%5,%6,%7}, {%8,%9}, {%0,%1,%2,%3};\n"
        : "+f"(c[0]), "+f"(c[1]), "+f"(c[2]), "+f"(c[3])
        : "r"(a[0]), "r"(a[1]), "r"(a[2]), "r"(a[3]), "r"(b[0]), "r"(b[1]));
}

__device__ __forceinline__ void cp16(void* smem_dst, const void* gsrc, unsigned bytes) {
    unsigned saddr = (unsigned)__cvta_generic_to_shared(smem_dst);
    asm volatile("cp.async.cg.shared.global [%0], [%1], 16, %2;\n"
                 :: "r"(saddr), "l"(gsrc), "r"(bytes));
}
__device__ __forceinline__ void cp_commit() { asm volatile("cp.async.commit_group;\n"); }
template<int N> __device__ __forceinline__ void cp_wait() {
    asm volatile("cp.async.wait_group %0;\n" :: "n"(N));
}

// ---------------- rna copy (tf32 pre-round) ----------------------------------
__global__ void rna_copy(const float4* __restrict__ src, float4* __restrict__ dst, int n4)
{
    int i = blockIdx.x * blockDim.x + threadIdx.x;
    if (i < n4) {
        float4 v = src[i];
        v.x = rnaf(v.x); v.y = rnaf(v.y); v.z = rnaf(v.z); v.w = rnaf(v.w);
        dst[i] = v;
    }
}

// ---------------- kernel 1: cls_n, sims, argmax (fp32 exact) -----------------
__global__ void cls_kernel(const float* __restrict__ x,
                           const float* __restrict__ cent,
                           float* __restrict__ cls_out,
                           float* __restrict__ idx_out)
{
    int b = blockIdx.x;
    int tid = threadIdx.x;
    __shared__ float xs[Dd];
    __shared__ float red[256];
    __shared__ float sims[Mm];
    __shared__ float inv_s;

    float ss = 0.f;
    for (int i = tid; i < Dd; i += 256) {
        float v = x[(size_t)b * Nn * Dd + i];
        xs[i] = v;
        ss += v * v;
    }
    red[tid] = ss; __syncthreads();
    for (int s = 128; s > 0; s >>= 1) { if (tid < s) red[tid] += red[tid + s]; __syncthreads(); }
    if (tid == 0) inv_s = 1.f / fmaxf(sqrtf(red[0]), 1e-12f);
    __syncthreads();
    float inv = inv_s;

    for (int m = 0; m < Mm; m++) {
        float p = 0.f;
        for (int i = tid; i < Dd; i += 256) p += xs[i] * cent[m * Dd + i];
        red[tid] = p; __syncthreads();
        for (int s = 128; s > 0; s >>= 1) { if (tid < s) red[tid] += red[tid + s]; __syncthreads(); }
        if (tid == 0) sims[m] = red[0] * inv;
        __syncthreads();
    }
    if (tid == 0) {
        int best = 0; float bv = sims[0];
        for (int m = 1; m < Mm; m++) if (sims[m] > bv) { bv = sims[m]; best = m; }
        g_idx[b] = best;
        if (idx_out) idx_out[b] = (float)best;
    }
    if (cls_out)
        for (int i = tid; i < Dd; i += 256)
            cls_out[(size_t)b * Dd + i] = xs[i] * inv;
}

// ---------------- gather Q_banks[idx] (rna) + xreg (from xtf) ----------------
__global__ void gather_qctx_kernel(const float* __restrict__ Qb)
{
    size_t total = (size_t)Bsz * Kk * Dd;
    for (size_t i = (size_t)blockIdx.x * blockDim.x + threadIdx.x; i < total;
         i += (size_t)gridDim.x * blockDim.x) {
        int b = (int)(i / ((size_t)Kk * Dd));
        size_t r = i - (size_t)b * Kk * Dd;
        g_qctx[i] = rnaf(Qb[(size_t)g_idx[b] * Kk * Dd + r]);
    }
}

__global__ void xreg_kernel()
{
    int i = blockIdx.x * blockDim.x + threadIdx.x;
    const int total = Bsz * Rr * Dd;
    if (i < total) {
        int b = i / (Rr * Dd);
        int r = i - b * (Rr * Dd);
        g_ctx[(size_t)b * CTX * Dd + r] = g_xtf[(size_t)b * Nn * Dd + r];
    }
}

// ---------------- tf32 tensor-core GEMM, cp.async double-buffered -----------
// C[M,N] = A[M,K] @ op(B) (+bias). Inputs pre-rounded to tf32 precision.
// Block 128x128x32, 256 threads, warp tile 32x64, mma m16n8k8.
// N % 128 == 0 and K % 32 == 0 at all call sites; M guarded.
template<bool TRANSB, bool BIAS, bool RNA>
__global__ __launch_bounds__(256, 2)
void mma_gemm(const float* __restrict__ A, const float* __restrict__ Bm,
              const float* __restrict__ bias, float* __restrict__ C,
              int M, int N, int Kd, int lda, int ldb, int ldc,
              long long sA, long long sB, long long sC)
{
    extern __shared__ float sm[];
    const int ASTG = 128 * 36;                       // floats per A stage
    const int BSTG = TRANSB ? 128 * 36 : 32 * 136;
    float* As = sm;                                  // 2 stages
    float* Bs = sm + 2 * ASTG;                       // 2 stages

    const float* Ab = A  + (long long)blockIdx.z * sA;
    const float* Bb = Bm + (long long)blockIdx.z * sB;
    float*       Cb = C  + (long long)blockIdx.z * sC;

    const int row0 = blockIdx.y * 128;
    const int col0 = blockIdx.x * 128;
    const int tid  = threadIdx.x;
    const int lane = tid & 31;
    const int warp = tid >> 5;
    const int wm = warp >> 1;
    const int wn = warp & 1;
    const int g   = lane >> 2;
    const int tig = lane & 3;

    float acc[2][8][4];
#pragma unroll
    for (int im = 0; im < 2; im++)
#pragma unroll
        for (int in = 0; in < 8; in++)
#pragma unroll
            for (int j = 0; j < 4; j++) acc[im][in][j] = 0.f;

    auto cpA = [&](int stg, int k0) {
        float* dst0 = As + stg * ASTG;
#pragma unroll
        for (int it = 0; it < 4; it++) {
            int id = tid + it * 256;              // 0..1023
            int r  = id >> 3;                     // 0..127
            int c  = (id & 7) * 4;                // 0..28
            int gr = row0 + r;
            unsigned ok = (gr < M) ? 16u : 0u;
            const float* src = Ab + (size_t)(gr < M ? gr : 0) * lda + k0 + c;
            cp16(dst0 + r * 36 + c, src, ok);
        }
    };
    auto cpB = [&](int stg, int k0) {
        float* dst0 = Bs + stg * BSTG;
#pragma unroll
        for (int it = 0; it < 4; it++) {
            int id = tid + it * 256;
            if (TRANSB) {
                int n = id >> 3;
                int c = (id & 7) * 4;
                cp16(dst0 + n * 36 + c, Bb + (size_t)(col0 + n) * ldb + k0 + c, 16u);
            } else {
                int k  = id >> 5;                 // 0..31
                int n4 = (id & 31) * 4;           // 0..124
                cp16(dst0 + k * 136 + n4, Bb + (size_t)(k0 + k) * ldb + col0 + n4, 16u);
            }
        }
    };

    cpA(0, 0); cpB(0, 0); cp_commit();

    const int nk = Kd >> 5;
    for (int i = 0; i < nk; i++) {
        if (i + 1 < nk) {
            cpA((i + 1) & 1, (i + 1) * 32);
            cpB((i + 1) & 1, (i + 1) * 32);
            cp_commit();
            cp_wait<1>();
        } else {
            cp_wait<0>();
        }
        __syncthreads();

        const float* Asl = As + (i & 1) * ASTG;
        const float* Bsl = Bs + (i & 1) * BSTG;

#pragma unroll
        for (int kk = 0; kk < 4; kk++) {
            const int ka = kk * 8 + tig;
            unsigned afr[2][4], bfr[8][2];
#pragma unroll
            for (int im = 0; im < 2; im++) {
                int r = wm * 32 + im * 16 + g;
                afr[im][0] = __float_as_uint(Asl[r * 36 + ka]);
                afr[im][1] = __float_as_uint(Asl[(r + 8) * 36 + ka]);
                afr[im][2] = __float_as_uint(Asl[r * 36 + ka + 4]);
                afr[im][3] = __float_as_uint(Asl[(r + 8) * 36 + ka + 4]);
            }
#pragma unroll
            for (int in = 0; in < 8; in++) {
                int bn = wn * 64 + in * 8 + g;
                if (TRANSB) {
                    bfr[in][0] = __float_as_uint(Bsl[bn * 36 + ka]);
                    bfr[in][1] = __float_as_uint(Bsl[bn * 36 + ka + 4]);
                } else {
                    bfr[in][0] = __float_as_uint(Bsl[ka * 136 + bn]);
                    bfr[in][1] = __float_as_uint(Bsl[(ka + 4) * 136 + bn]);
                }
            }
#pragma unroll
            for (int im = 0; im < 2; im++)
#pragma unroll
                for (int in = 0; in < 8; in++)
                    mma_tf32(acc[im][in], afr[im], bfr[in]);
        }
        __syncthreads();
    }

#pragma unroll
    for (int im = 0; im < 2; im++) {
        int rb = row0 + wm * 32 + im * 16 + g;
#pragma unroll
        for (int in = 0; in < 8; in++) {
            int cb = col0 + wn * 64 + in * 8 + 2 * tig;
            float b0 = BIAS ? bias[cb] : 0.f;
            float b1 = BIAS ? bias[cb + 1] : 0.f;
            float v0 = acc[im][in][0] + b0, v1 = acc[im][in][1] + b1;
            float v2 = acc[im][in][2] + b0, v3 = acc[im][in][3] + b1;
            if (RNA) { v0 = rnaf(v0); v1 = rnaf(v1); v2 = rnaf(v2); v3 = rnaf(v3); }
            if (rb < M) {
                Cb[(size_t)rb * ldc + cb]     = v0;
                Cb[(size_t)rb * ldc + cb + 1] = v1;
            }
            if (rb + 8 < M) {
                Cb[(size_t)(rb + 8) * ldc + cb]     = v2;
                Cb[(size_t)(rb + 8) * ldc + cb + 1] = v3;
            }
        }
    }
}

// ---------------- row softmax over P=1024 (rna output) -----------------------
__global__ void softmax_kernel(float* __restrict__ s)
{
    int row = blockIdx.x;
    float4* p4 = reinterpret_cast<float4*>(s + (size_t)row * Pp);
    int tid = threadIdx.x;
    __shared__ float red[256];

    float4 v = p4[tid];
    float mx = fmaxf(fmaxf(v.x, v.y), fmaxf(v.z, v.w));
    red[tid] = mx; __syncthreads();
    for (int st = 128; st > 0; st >>= 1) { if (tid < st) red[tid] = fmaxf(red[tid], red[tid + st]); __syncthreads(); }
    mx = red[0]; __syncthreads();

    v.x = __expf(v.x - mx); v.y = __expf(v.y - mx);
    v.z = __expf(v.z - mx); v.w = __expf(v.w - mx);
    float sm = v.x + v.y + v.z + v.w;
    red[tid] = sm; __syncthreads();
    for (int st = 128; st > 0; st >>= 1) { if (tid < st) red[tid] += red[tid + st]; __syncthreads(); }
    float inv = 1.f / red[0];
    v.x = rnaf(v.x * inv); v.y = rnaf(v.y * inv);
    v.z = rnaf(v.z * inv); v.w = rnaf(v.w * inv);
    p4[tid] = v;
}

// ---------------- tensor-core fused attention --------------------------------
// grid (9, B*H), 256 threads (8 warps, 16 query rows each). Exact softmax:
// all 133 keys resident. S = Q K^T via mma, softmax in regs, P (rna) -> smem,
// O = P V via mma. g_q/g_kv pre-rounded tf32.
__global__ __launch_bounds__(256)
void attn_mma(float* __restrict__ y)
{
    extern __shared__ float sm[];
    float* Vs = sm;                  // [136][72]
    float* Ks = sm + 9792;           // [136][68]
    float* Qs = sm + 19040;          // [128][68]
    float* Ps = sm + 9792;           // [128][140] overlays Ks+Qs (phase 2)

    const int bh = blockIdx.y;
    const int b = bh / Hh, h = bh % Hh;
    const int n0 = blockIdx.x * 128;
    const int tid = threadIdx.x;
    const int lane = tid & 31;
    const int w = tid >> 5;
    const int g = lane >> 2;
    const int tig = lane & 3;
    const int rbase = w * 16;

    // ---- loads: Q (128x64), K/V (136x64, zfill pad) -------------------------
#pragma unroll
    for (int it = 0; it < 8; it++) {
        int id = tid + it * 256;           // 0..2047
        int r  = id >> 4;                  // 0..127
        int c  = (id & 15) * 4;            // 0..60
        int n  = n0 + r;
        unsigned ok = (n < Nn) ? 16u : 0u;
        const float* src = g_q + ((size_t)b * Nn + (n < Nn ? n : 0)) * Dd + h * dh + c;
        cp16(Qs + r * 68 + c, src, ok);
    }
#pragma unroll
    for (int it = 0; it < 17; it++) {
        int id = tid + it * 256;           // 0..4351
        int key  = id >> 5;                // 0..135
        int half = (id >> 4) & 1;          // 0=K 1=V
        int c    = (id & 15) * 4;
        unsigned ok = (key < CTX) ? 16u : 0u;
        const float* src = g_kv + ((size_t)b * CTX + (key < CTX ? key : 0)) * (2 * Dd)
                         + half * Dd + h * dh + c;
        float* dst = half ? (Vs + key * 72 + c) : (Ks + key * 68 + c);
        cp16(dst, src, ok);
    }
    cp_commit();
    cp_wait<0>();
    __syncthreads();

    // ---- phase 1: S = Q K^T ---------------------------------------------------
    unsigned afr[8][4];
#pragma unroll
    for (int ks = 0; ks < 8; ks++) {
        afr[ks][0] = __float_as_uint(Qs[(rbase + g) * 68 + ks * 8 + tig]);
        afr[ks][1] = __float_as_uint(Qs[(rbase + g + 8) * 68 + ks * 8 + tig]);
        afr[ks][2] = __float_as_uint(Qs[(rbase + g) * 68 + ks * 8 + tig + 4]);
        afr[ks][3] = __float_as_uint(Qs[(rbase + g + 8) * 68 + ks * 8 + tig + 4]);
    }

    float sacc[17][4];
#pragma unroll
    for (int nt = 0; nt < 17; nt++)
#pragma unroll
        for (int j = 0; j < 4; j++) sacc[nt][j] = 0.f;

#pragma unroll
    for (int nt = 0; nt < 17; nt++) {
#pragma unroll
        for (int ks = 0; ks < 8; ks++) {
            unsigned bfr[2];
            bfr[0] = __float_as_uint(Ks[(nt * 8 + g) * 68 + ks * 8 + tig]);
            bfr[1] = __float_as_uint(Ks[(nt * 8 + g) * 68 + ks * 8 + tig + 4]);
            mma_tf32(sacc[nt], afr[ks], bfr);
        }
    }

    // ---- softmax (exact, per-row over 133 keys) -------------------------------
    const float scale = 0.125f;
    float mlo = -1e30f, mhi = -1e30f;
#pragma unroll
    for (int nt = 0; nt < 17; nt++) {
        int c0 = nt * 8 + 2 * tig;
        float s0 = (c0     < CTX) ? sacc[nt][0] * scale : -1e30f;
        float s1 = (c0 + 1 < CTX) ? sacc[nt][1] * scale : -1e30f;
        float s2 = (c0     < CTX) ? sacc[nt][2] * scale : -1e30f;
        float s3 = (c0 + 1 < CTX) ? sacc[nt][3] * scale : -1e30f;
        sacc[nt][0] = s0; sacc[nt][1] = s1; sacc[nt][2] = s2; sacc[nt][3] = s3;
        mlo = fmaxf(mlo, fmaxf(s0, s1));
        mhi = fmaxf(mhi, fmaxf(s2, s3));
    }
    mlo = fmaxf(mlo, __shfl_xor_sync(0xffffffffu, mlo, 1));
    mlo = fmaxf(mlo, __shfl_xor_sync(0xffffffffu, mlo, 2));
    mhi = fmaxf(mhi, __shfl_xor_sync(0xffffffffu, mhi, 1));
    mhi = fmaxf(mhi, __shfl_xor_sync(0xffffffffu, mhi, 2));

    float llo = 0.f, lhi = 0.f;
#pragma unroll
    for (int nt = 0; nt < 17; nt++) {
        float p0 = __expf(sacc[nt][0] - mlo);
        float p1 = __expf(sacc[nt][1] - mlo);
        float p2 = __expf(sacc[nt][2] - mhi);
        float p3 = __expf(sacc[nt][3] - mhi);
        llo += p0 + p1; lhi += p2 + p3;
        sacc[nt][0] = p0; sacc[nt][1] = p1; sacc[nt][2] = p2; sacc[nt][3] = p3;
    }
    llo += __shfl_xor_sync(0xffffffffu, llo, 1);
    llo += __shfl_xor_sync(0xffffffffu, llo, 2);
    lhi += __shfl_xor_sync(0xffffffffu, lhi, 1);
    lhi += __shfl_xor_sync(0xffffffffu, lhi, 2);

    __syncthreads();   // all warps done reading Ks/Qs before Ps overlay write

#pragma unroll
    for (int nt = 0; nt < 17; nt++) {
        int c0 = nt * 8 + 2 * tig;
        Ps[(rbase + g) * 140 + c0]         = rnaf(sacc[nt][0]);
        Ps[(rbase + g) * 140 + c0 + 1]     = rnaf(sacc[nt][1]);
        Ps[(rbase + g + 8) * 140 + c0]     = rnaf(sacc[nt][2]);
        Ps[(rbase + g + 8) * 140 + c0 + 1] = rnaf(sacc[nt][3]);
    }
    __syncthreads();

    // ---- phase 2: O = P V ------------------------------------------------------
    float oacc[8][4];
#pragma unroll
    for (int nt = 0; nt < 8; nt++)
#pragma unroll
        for (int j = 0; j < 4; j++) oacc[nt][j] = 0.f;

#pragma unroll
    for (int ks = 0; ks < 17; ks++) {
        unsigned a2[4];
        a2[0] = __float_as_uint(Ps[(rbase + g) * 140 + ks * 8 + tig]);
        a2[1] = __float_as_uint(Ps[(rbase + g + 8) * 140 + ks * 8 + tig]);
        a2[2] = __float_as_uint(Ps[(rbase + g) * 140 + ks * 8 + tig + 4]);
        a2[3] = __float_as_uint(Ps[(rbase + g + 8) * 140 + ks * 8 + tig + 4]);
#pragma unroll
        for (int nt = 0; nt < 8; nt++) {
            unsigned bfr[2];
            bfr[0] = __float_as_uint(Vs[(ks * 8 + tig) * 72 + nt * 8 + g]);
            bfr[1] = __float_as_uint(Vs[(ks * 8 + tig + 4) * 72 + nt * 8 + g]);
            mma_tf32(oacc[nt], a2, bfr);
        }
    }

    // ---- output (rna, consumed by out-GEMM) -----------------------------------
    float invlo = 1.f / llo, invhi = 1.f / lhi;
    int row_lo = n0 + rbase + g;
    int row_hi = row_lo + 8;
#pragma unroll
    for (int nt = 0; nt < 8; nt++) {
        int col = h * dh + nt * 8 + 2 * tig;
        if (row_lo < Nn) {
            float2 v = make_float2(rnaf(oacc[nt][0] * invlo), rnaf(oacc[nt][1] * invlo));
            *reinterpret_cast<float2*>(&y[((size_t)b * Nn + row_lo) * Dd + col]) = v;
        }
        if (row_hi < Nn) {
            float2 v = make_float2(rnaf(oacc[nt][2] * invhi), rnaf(oacc[nt][3] * invhi));
            *reinterpret_cast<float2*>(&y[((size_t)b * Nn + row_hi) * Dd + col]) = v;
        }
    }
}

// ---------------- launch -----------------------------------------------------
extern "C" void kernel_launch(void* const* d_in, const int* in_sizes, int n_in,
                              void* d_out, int out_size)
{
    const float* x    = (const float*)d_in[0];
    const float* Qb   = (const float*)d_in[1];
    const float* Wq   = (const float*)d_in[2];
    const float* Wctx = (const float*)d_in[3];
    const float* bctx = (const float*)d_in[4];
    const float* Wout = (const float*)d_in[5];
    const float* bout = (const float*)d_in[6];
    const float* cent = (const float*)d_in[7];
    float* out = (float*)d_out;

    float *p_xtf, *p_wq, *p_wctx, *p_wout;
    float *p_qctx, *p_scores, *p_ctx, *p_kv, *p_q, *p_y;
    cudaGetSymbolAddress((void**)&p_xtf,    g_xtf);
    cudaGetSymbolAddress((void**)&p_wq,     g_wq);
    cudaGetSymbolAddress((void**)&p_wctx,   g_wctx);
    cudaGetSymbolAddress((void**)&p_wout,   g_wout);
    cudaGetSymbolAddress((void**)&p_qctx,   g_qctx);
    cudaGetSymbolAddress((void**)&p_scores, g_scores);
    cudaGetSymbolAddress((void**)&p_ctx,    g_ctx);
    cudaGetSymbolAddress((void**)&p_kv,     g_kv);
    cudaGetSymbolAddress((void**)&p_q,      g_q);
    cudaGetSymbolAddress((void**)&p_y,      g_y);

    // opt-in dynamic smem (idempotent host calls; not stream ops)
    const int GEMM_SMEM_NT = (2 * 128 * 36 + 2 * 128 * 36) * 4;   // 73728
    const int GEMM_SMEM_NN = (2 * 128 * 36 + 2 * 32 * 136) * 4;   // 71680
    const int ATTN_SMEM    = 27744 * 4;                           // 110976
    cudaFuncSetAttribute((const void*)mma_gemm<true,  false, true >, cudaFuncAttributeMaxDynamicSharedMemorySize, GEMM_SMEM_NT);
    cudaFuncSetAttribute((const void*)mma_gemm<false, false, true >, cudaFuncAttributeMaxDynamicSharedMemorySize, GEMM_SMEM_NN);
    cudaFuncSetAttribute((const void*)mma_gemm<false, true,  true >, cudaFuncAttributeMaxDynamicSharedMemorySize, GEMM_SMEM_NN);
    cudaFuncSetAttribute((const void*)mma_gemm<false, true,  false>, cudaFuncAttributeMaxDynamicSharedMemorySize, GEMM_SMEM_NN);
    cudaFuncSetAttribute((const void*)attn_mma, cudaFuncAttributeMaxDynamicSharedMemorySize, ATTN_SMEM);

    const size_t main_sz = (size_t)Bsz * Nn * Dd;
    float* cls_out = nullptr;
    float* idx_out = nullptr;
    if ((size_t)out_size >= main_sz + (size_t)Bsz * Dd + Bsz) {
        cls_out = out + main_sz;
        idx_out = out + main_sz + (size_t)Bsz * Dd;
    }

    // 0) pre-round inputs to tf32 precision
    {
        int n4 = (int)(main_sz / 4);
        rna_copy<<<(n4 + 255) / 256, 256>>>((const float4*)x, (float4*)p_xtf, n4);
        rna_copy<<<(Dd * Dd / 4 + 255) / 256, 256>>>((const float4*)Wq, (float4*)p_wq, Dd * Dd / 4);
        rna_copy<<<(Dd * 2 * Dd / 4 + 255) / 256, 256>>>((const float4*)Wctx, (float4*)p_wctx, Dd * 2 * Dd / 4);
        rna_copy<<<(Dd * Dd / 4 + 255) / 256, 256>>>((const float4*)Wout, (float4*)p_wout, Dd * Dd / 4);
    }

    // 1) cls / argmax (exact fp32 from original x)
    cls_kernel<<<Bsz, 256>>>(x, cent, cls_out, idx_out);

    // 2) gather (rna) + xreg (already rounded)
    gather_qctx_kernel<<<4096, 256>>>(Qb);
    xreg_kernel<<<(Bsz * Rr * Dd + 255) / 256, 256>>>();

    // 3) scores = q_ctx @ xp^T (NT, batched)
    mma_gemm<true, false, true><<<dim3(Pp / 128, 1, Bsz), 256, GEMM_SMEM_NT>>>(
        p_qctx, p_xtf + (size_t)Rr * Dd, nullptr, p_scores,
        Kk, Pp, Dd, Dd, Dd, Pp,
        (long long)Kk * Dd, (long long)Nn * Dd, (long long)Kk * Pp);

    // 4) softmax (rna output)
    softmax_kernel<<<Bsz * Kk, 256>>>(p_scores);

    // 5) ctx_p = attn @ xp (NN, batched)
    mma_gemm<false, false, true><<<dim3(Dd / 128, 1, Bsz), 256, GEMM_SMEM_NN>>>(
        p_scores, p_xtf + (size_t)Rr * Dd, nullptr, p_ctx + (size_t)Rr * Dd,
        Kk, Dd, Pp, Pp, Dd, Dd,
        (long long)Kk * Pp, (long long)Nn * Dd, (long long)CTX * Dd);

    // 6) kv = ctx @ Wctx + bctx (rna output)
    mma_gemm<false, true, true><<<dim3((2 * Dd) / 128, (Bsz * CTX + 127) / 128, 1), 256, GEMM_SMEM_NN>>>(
        p_ctx, p_wctx, bctx, p_kv,
        Bsz * CTX, 2 * Dd, Dd, Dd, 2 * Dd, 2 * Dd, 0, 0, 0);

    // 7) q = x @ Wq (rna output)
    mma_gemm<false, false, true><<<dim3(Dd / 128, (Bsz * Nn + 127) / 128, 1), 256, GEMM_SMEM_NN>>>(
        p_xtf, p_wq, nullptr, p_q,
        Bsz * Nn, Dd, Dd, Dd, Dd, Dd, 0, 0, 0);

    // 8) fused tensor-core attention -> y (rna output)
    attn_mma<<<dim3((Nn + 127) / 128, Bsz * Hh), 256, ATTN_SMEM>>>(p_y);

    // 9) out = y @ Wout + bout (fp32 output)
    mma_gemm<false, true, false><<<dim3(Dd / 128, (Bsz * Nn + 127) / 128, 1), 256, GEMM_SMEM_NN>>>(
        p_y, p_wout, bout, out,
        Bsz * Nn, Dd, Dd, Dd, Dd, Dd, 0, 0, 0);
}

// round 5
// speedup vs baseline: 4.6831x; 1.3787x over previous
#include <cuda_runtime.h>
#include <cuda_fp16.h>
#include <math.h>
#include <stdint.h>

#define Bsz 64
#define Nn  1029
#define Dd  768
#define Hh  12
#define dh  64
#define Kk  128
#define Rr  5
#define Mm  4
#define Pp  1024          // N - R
#define CTX 133           // R + K

// ---------------- scratch (static device globals: allocation-free) ----------
__device__ int    g_idx[Bsz];
__device__ __half g_xh[(size_t)Bsz * Nn * Dd];
__device__ __half g_wqT[Dd * Dd];          // Wq^T   [N=768,  K=768]
__device__ __half g_wctxT[2 * Dd * Dd];    // Wctx^T [N=1536, K=768]
__device__ __half g_woutT[Dd * Dd];        // Wout^T
__device__ __half g_qctx[(size_t)Bsz * Kk * Dd];
__device__ float  g_scores[(size_t)Bsz * Kk * Pp];
__device__ __half g_probs[(size_t)Bsz * Kk * Pp];
__device__ __half g_ctx[(size_t)Bsz * CTX * Dd];
__device__ __half g_kv[(size_t)Bsz * CTX * 2 * Dd];
__device__ __half g_q[(size_t)Bsz * Nn * Dd];
__device__ __half g_y[(size_t)Bsz * Nn * Dd];

// ---------------- helpers ----------------------------------------------------
__device__ __forceinline__ uint32_t pk2(float a, float b) {
    __half2 h = __floats2half2_rn(a, b);
    return *reinterpret_cast<uint32_t*>(&h);
}

__device__ __forceinline__ void mma_f16(float* c, const uint32_t* a, const uint32_t* b) {
    asm volatile(
        "mma.sync.aligned.m16n8k16.row.col.f32.f16.f16.f32 "
        "{%0,%1,%2,%3}, {%4,%5,%6,%7}, {%8,%9}, {%0,%1,%2,%3};\n"
        : "+f"(c[0]), "+f"(c[1]), "+f"(c[2]), "+f"(c[3])
        : "r"(a[0]), "r"(a[1]), "r"(a[2]), "r"(a[3]), "r"(b[0]), "r"(b[1]));
}

__device__ __forceinline__ void cp16(void* smem_dst, const void* gsrc, unsigned bytes) {
    unsigned saddr = (unsigned)__cvta_generic_to_shared(smem_dst);
    asm volatile("cp.async.cg.shared.global [%0], [%1], 16, %2;\n"
                 :: "r"(saddr), "l"(gsrc), "r"(bytes));
}
__device__ __forceinline__ void cp_commit() { asm volatile("cp.async.commit_group;\n"); }
template<int N> __device__ __forceinline__ void cp_wait() {
    asm volatile("cp.async.wait_group %0;\n" :: "n"(N));
}

// ---------------- conversion kernels ------------------------------------------
__global__ void f2h_kernel(const float4* __restrict__ src, uint2* __restrict__ dst, int n4)
{
    int i = blockIdx.x * blockDim.x + threadIdx.x;
    if (i < n4) {
        float4 v = src[i];
        uint2 o;
        o.x = pk2(v.x, v.y);
        o.y = pk2(v.z, v.w);
        dst[i] = o;
    }
}

// dst_half[n*K + k] = half(src[k*N + n])
__global__ void transpose_h(const float* __restrict__ src, __half* __restrict__ dst,
                            int K, int N)
{
    __shared__ float t[32][33];
    int k0 = blockIdx.y * 32, n0 = blockIdx.x * 32;
    int tx = threadIdx.x, ty = threadIdx.y;   // 32 x 8
    for (int i = ty; i < 32; i += 8)
        t[i][tx] = src[(size_t)(k0 + i) * N + n0 + tx];
    __syncthreads();
    for (int i = ty; i < 32; i += 8)
        dst[(size_t)(n0 + i) * K + k0 + tx] = __float2half_rn(t[tx][i]);
}

// ---------------- cls_n, sims, argmax (fp32 exact) ---------------------------
__global__ void cls_kernel(const float* __restrict__ x,
                           const float* __restrict__ cent,
                           float* __restrict__ cls_out,
                           float* __restrict__ idx_out)
{
    int b = blockIdx.x;
    int tid = threadIdx.x;
    __shared__ float xs[Dd];
    __shared__ float red[256];
    __shared__ float sims[Mm];
    __shared__ float inv_s;

    float ss = 0.f;
    for (int i = tid; i < Dd; i += 256) {
        float v = x[(size_t)b * Nn * Dd + i];
        xs[i] = v;
        ss += v * v;
    }
    red[tid] = ss; __syncthreads();
    for (int s = 128; s > 0; s >>= 1) { if (tid < s) red[tid] += red[tid + s]; __syncthreads(); }
    if (tid == 0) inv_s = 1.f / fmaxf(sqrtf(red[0]), 1e-12f);
    __syncthreads();
    float inv = inv_s;

    for (int m = 0; m < Mm; m++) {
        float p = 0.f;
        for (int i = tid; i < Dd; i += 256) p += xs[i] * cent[m * Dd + i];
        red[tid] = p; __syncthreads();
        for (int s = 128; s > 0; s >>= 1) { if (tid < s) red[tid] += red[tid + s]; __syncthreads(); }
        if (tid == 0) sims[m] = red[0] * inv;
        __syncthreads();
    }
    if (tid == 0) {
        int best = 0; float bv = sims[0];
        for (int m = 1; m < Mm; m++) if (sims[m] > bv) { bv = sims[m]; best = m; }
        g_idx[b] = best;
        if (idx_out) idx_out[b] = (float)best;
    }
    if (cls_out)
        for (int i = tid; i < Dd; i += 256)
            cls_out[(size_t)b * Dd + i] = xs[i] * inv;
}

// ---------------- gather Q_banks[idx] (half) + xreg --------------------------
__global__ void gather_qctx_kernel(const float* __restrict__ Qb)
{
    size_t total = (size_t)Bsz * Kk * Dd;
    for (size_t i = (size_t)blockIdx.x * blockDim.x + threadIdx.x; i < total;
         i += (size_t)gridDim.x * blockDim.x) {
        int b = (int)(i / ((size_t)Kk * Dd));
        size_t r = i - (size_t)b * Kk * Dd;
        g_qctx[i] = __float2half_rn(Qb[(size_t)g_idx[b] * Kk * Dd + r]);
    }
}

__global__ void xreg_kernel()
{
    int i = blockIdx.x * blockDim.x + threadIdx.x;       // u32 units
    const int total = Bsz * Rr * Dd / 2;
    if (i < total) {
        int b = i / (Rr * Dd / 2);
        int r = i - b * (Rr * Dd / 2);
        reinterpret_cast<uint32_t*>(g_ctx)[(size_t)b * CTX * Dd / 2 + r] =
            reinterpret_cast<const uint32_t*>(g_xh)[(size_t)b * Nn * Dd / 2 + r];
    }
}

// ---------------- fp16 tensor-core GEMM, 3-stage cp.async --------------------
// C[M,N] = A[M,Kd] @ op(B) (+bias). op = B[Kd,N] (NN) or B[N,Kd]^T (NT).
// Block 128x128x32 halfs, 256 threads (8 warps 4x2), warp tile 32x64,
// mma m16n8k16 f16 -> f32. N%128==0, Kd%32==0; M guarded.
template<bool TRANSB, bool BIAS, bool OUTHALF>
__global__ __launch_bounds__(256, 2)
void hgemm(const __half* __restrict__ A, const __half* __restrict__ Bm,
           const float* __restrict__ bias, void* __restrict__ Cv,
           int M, int N, int Kd, int lda, int ldb, int ldc,
           long long sA, long long sB, long long sC)
{
    extern __shared__ uint32_t smu[];
    const int ASTG = 128 * 20;                        // u32 per A stage (pad 20)
    const int BSTG = TRANSB ? 128 * 20 : 32 * 68;     // NN: halfs [32][136] = 2176 u32
    uint32_t* smA = smu;
    uint32_t* smB = smu + 3 * ASTG;

    const __half* Ab = A  + (long long)blockIdx.z * sA;
    const __half* Bb = Bm + (long long)blockIdx.z * sB;

    const int row0 = blockIdx.y * 128;
    const int col0 = blockIdx.x * 128;
    const int tid  = threadIdx.x;
    const int lane = tid & 31;
    const int warp = tid >> 5;
    const int wm = warp >> 1;
    const int wn = warp & 1;
    const int g   = lane >> 2;
    const int tig = lane & 3;

    float acc[2][8][4];
#pragma unroll
    for (int im = 0; im < 2; im++)
#pragma unroll
        for (int in = 0; in < 8; in++)
#pragma unroll
            for (int j = 0; j < 4; j++) acc[im][in][j] = 0.f;

    auto loadA = [&](int stg, int k0) {
        uint32_t* dst = smA + stg * ASTG;
#pragma unroll
        for (int it = 0; it < 2; it++) {
            int id = tid + it * 256;              // 0..511
            int r  = id >> 2;                     // 0..127
            int c  = (id & 3) * 4;                // u32 col 0,4,8,12
            int gr = row0 + r;
            unsigned ok = (gr < M) ? 16u : 0u;
            const __half* src = Ab + (size_t)(gr < M ? gr : 0) * lda + k0 + c * 2;
            cp16(dst + r * 20 + c, src, ok);
        }
    };
    auto loadB = [&](int stg, int k0) {
        uint32_t* dst = smB + stg * BSTG;
#pragma unroll
        for (int it = 0; it < 2; it++) {
            int id = tid + it * 256;
            if (TRANSB) {
                int n = id >> 2;
                int c = (id & 3) * 4;
                cp16(dst + n * 20 + c, Bb + (size_t)(col0 + n) * ldb + k0 + c * 2, 16u);
            } else {
                int kr = id >> 4;                 // 0..31
                int ch = id & 15;                 // 16B chunks
                cp16(dst + kr * 68 + ch * 4, Bb + (size_t)(k0 + kr) * ldb + col0 + ch * 8, 16u);
            }
        }
    };

    loadA(0, 0); loadB(0, 0); cp_commit();
    loadA(1, 32); loadB(1, 32); cp_commit();

    const int nk = Kd >> 5;
    for (int i = 0; i < nk; i++) {
        if (i + 1 < nk) cp_wait<1>(); else cp_wait<0>();
        __syncthreads();
        if (i + 2 < nk) {
            int s3 = (i + 2) % 3;
            loadA(s3, (i + 2) * 32);
            loadB(s3, (i + 2) * 32);
            cp_commit();
        }

        const uint32_t* Asl = smA + (i % 3) * ASTG;
        const uint32_t* Bsl = smB + (i % 3) * BSTG;
        const unsigned short* Bsh = reinterpret_cast<const unsigned short*>(Bsl);

#pragma unroll
        for (int s = 0; s < 2; s++) {             // two k16 steps per 32-k block
            uint32_t afr[2][4], bfr[8][2];
#pragma unroll
            for (int im = 0; im < 2; im++) {
                int r = wm * 32 + im * 16 + g;
                afr[im][0] = Asl[r * 20 + tig + 8 * s];
                afr[im][1] = Asl[(r + 8) * 20 + tig + 8 * s];
                afr[im][2] = Asl[r * 20 + tig + 4 + 8 * s];
                afr[im][3] = Asl[(r + 8) * 20 + tig + 4 + 8 * s];
            }
#pragma unroll
            for (int in = 0; in < 8; in++) {
                int bn = wn * 64 + in * 8 + g;
                if (TRANSB) {
                    bfr[in][0] = Bsl[bn * 20 + tig + 8 * s];
                    bfr[in][1] = Bsl[bn * 20 + tig + 4 + 8 * s];
                } else {
                    int kb = 2 * tig + 16 * s;
                    bfr[in][0] = (uint32_t)Bsh[kb * 136 + bn]
                               | ((uint32_t)Bsh[(kb + 1) * 136 + bn] << 16);
                    bfr[in][1] = (uint32_t)Bsh[(kb + 8) * 136 + bn]
                               | ((uint32_t)Bsh[(kb + 9) * 136 + bn] << 16);
                }
            }
#pragma unroll
            for (int im = 0; im < 2; im++)
#pragma unroll
                for (int in = 0; in < 8; in++)
                    mma_f16(acc[im][in], afr[im], bfr[in]);
        }
        __syncthreads();
    }

    // ---- epilogue ----------------------------------------------------------
#pragma unroll
    for (int im = 0; im < 2; im++) {
        int rb = row0 + wm * 32 + im * 16 + g;
#pragma unroll
        for (int in = 0; in < 8; in++) {
            int cb = col0 + wn * 64 + in * 8 + 2 * tig;
            float b0 = BIAS ? bias[cb] : 0.f;
            float b1 = BIAS ? bias[cb + 1] : 0.f;
            float v0 = acc[im][in][0] + b0, v1 = acc[im][in][1] + b1;
            float v2 = acc[im][in][2] + b0, v3 = acc[im][in][3] + b1;
            if (OUTHALF) {
                __half* C = (__half*)Cv + (long long)blockIdx.z * sC;
                if (rb < M)
                    *reinterpret_cast<uint32_t*>(&C[(size_t)rb * ldc + cb]) = pk2(v0, v1);
                if (rb + 8 < M)
                    *reinterpret_cast<uint32_t*>(&C[(size_t)(rb + 8) * ldc + cb]) = pk2(v2, v3);
            } else {
                float* C = (float*)Cv + (long long)blockIdx.z * sC;
                if (rb < M)
                    *reinterpret_cast<float2*>(&C[(size_t)rb * ldc + cb]) = make_float2(v0, v1);
                if (rb + 8 < M)
                    *reinterpret_cast<float2*>(&C[(size_t)(rb + 8) * ldc + cb]) = make_float2(v2, v3);
            }
        }
    }
}

// ---------------- row softmax over P=1024: fp32 in, half out ------------------
__global__ void softmax_kernel(const float* __restrict__ s, __half* __restrict__ pr)
{
    int row = blockIdx.x;
    const float4* p4 = reinterpret_cast<const float4*>(s + (size_t)row * Pp);
    uint32_t* o2 = reinterpret_cast<uint32_t*>(pr + (size_t)row * Pp);
    int tid = threadIdx.x;
    __shared__ float red[256];

    float4 v = p4[tid];
    float mx = fmaxf(fmaxf(v.x, v.y), fmaxf(v.z, v.w));
    red[tid] = mx; __syncthreads();
    for (int st = 128; st > 0; st >>= 1) { if (tid < st) red[tid] = fmaxf(red[tid], red[tid + st]); __syncthreads(); }
    mx = red[0]; __syncthreads();

    v.x = __expf(v.x - mx); v.y = __expf(v.y - mx);
    v.z = __expf(v.z - mx); v.w = __expf(v.w - mx);
    float sm = v.x + v.y + v.z + v.w;
    red[tid] = sm; __syncthreads();
    for (int st = 128; st > 0; st >>= 1) { if (tid < st) red[tid] += red[tid + st]; __syncthreads(); }
    float inv = 1.f / red[0];
    o2[2 * tid]     = pk2(v.x * inv, v.y * inv);
    o2[2 * tid + 1] = pk2(v.z * inv, v.w * inv);
}

// ---------------- fp16 tensor-core fused attention ----------------------------
// grid (9, B*H), 256 threads (8 warps x 16 query rows). Exact softmax over all
// 133 keys (padded to 144). S = Q K^T (mma), softmax in regs, P->smem half,
// O = P V (mma, V transposed in smem).
__global__ __launch_bounds__(256)
void attn_mma(__half* __restrict__ y)
{
    extern __shared__ uint32_t smu[];
    uint32_t* Qs = smu;                    // [128][36] u32 (k-pairs of 64 d)
    uint32_t* Ks = smu + 128 * 36;         // [136][36]
    uint32_t* Vt = Ks + 136 * 36;          // [64 d][77] u32 (154 halfs: 144 keys + pad)
    uint32_t* Ps = Vt + 64 * 77;           // [128][76] u32 (144 key-halves + pad)

    const int bh = blockIdx.y;
    const int b = bh / Hh, h = bh % Hh;
    const int n0 = blockIdx.x * 128;
    const int tid = threadIdx.x;
    const int lane = tid & 31;
    const int w = tid >> 5;
    const int g = lane >> 2;
    const int tig = lane & 3;
    const int rbase = w * 16;

    // ---- Q tile 128x64 halfs (cp.async, zfill OOB rows) ----------------------
#pragma unroll
    for (int it = 0; it < 4; it++) {
        int id = tid + it * 256;           // 0..1023
        int r  = id >> 3;                  // 0..127
        int ch = id & 7;                   // 8 x 16B chunks
        int n  = n0 + r;
        unsigned ok = (n < Nn) ? 16u : 0u;
        const __half* src = g_q + ((size_t)b * Nn + (n < Nn ? n : 0)) * Dd + h * dh + ch * 8;
        cp16(Qs + r * 36 + ch * 4, src, ok);
    }
    // ---- K tile 136x64 halfs (rows >= CTX zero-filled) ------------------------
#pragma unroll
    for (int it = 0; it < 5; it++) {
        int id = tid + it * 256;           // 0..1279 (need 1088)
        if (id < 136 * 8) {
            int key = id >> 3;
            int ch  = id & 7;
            unsigned ok = (key < CTX) ? 16u : 0u;
            const __half* src = g_kv + ((size_t)b * CTX + (key < CTX ? key : 0)) * (2 * Dd)
                              + h * dh + ch * 8;
            cp16(Ks + key * 36 + ch * 4, src, ok);
        }
    }
    cp_commit();

    // ---- V transposed into Vt_half[d][key] (regs, scalar stores) -------------
    unsigned short* Vth = reinterpret_cast<unsigned short*>(Vt);
    for (int id = tid; id < CTX * 32; id += 256) {
        int key = id >> 5;
        int dp  = id & 31;                 // d pair
        uint32_t v = *reinterpret_cast<const uint32_t*>(
            g_kv + ((size_t)b * CTX + key) * (2 * Dd) + Dd + h * dh + 2 * dp);
        Vth[(2 * dp) * 154 + key]     = (unsigned short)(v & 0xffff);
        Vth[(2 * dp + 1) * 154 + key] = (unsigned short)(v >> 16);
    }
    for (int id = tid; id < 64 * 11; id += 256) {   // zero keys 133..143
        int d = id / 11, key = CTX + id % 11;
        Vth[d * 154 + key] = 0;
    }
    cp_wait<0>();
    __syncthreads();

    // ---- phase 1: S = Q K^T (4 ksteps of 16 over d=64) -----------------------
    uint32_t afr[4][4];
#pragma unroll
    for (int ks = 0; ks < 4; ks++) {
        afr[ks][0] = Qs[(rbase + g) * 36 + tig + 8 * ks];
        afr[ks][1] = Qs[(rbase + g + 8) * 36 + tig + 8 * ks];
        afr[ks][2] = Qs[(rbase + g) * 36 + tig + 4 + 8 * ks];
        afr[ks][3] = Qs[(rbase + g + 8) * 36 + tig + 4 + 8 * ks];
    }

    float sacc[17][4];
#pragma unroll
    for (int nt = 0; nt < 17; nt++)
#pragma unroll
        for (int j = 0; j < 4; j++) sacc[nt][j] = 0.f;

#pragma unroll
    for (int nt = 0; nt < 17; nt++) {
#pragma unroll
        for (int ks = 0; ks < 4; ks++) {
            uint32_t bfr[2];
            bfr[0] = Ks[(nt * 8 + g) * 36 + tig + 8 * ks];
            bfr[1] = Ks[(nt * 8 + g) * 36 + tig + 4 + 8 * ks];
            mma_f16(sacc[nt], afr[ks], bfr);
        }
    }

    // ---- exact softmax over 133 keys ------------------------------------------
    const float scale = 0.125f;
    float mlo = -1e30f, mhi = -1e30f;
#pragma unroll
    for (int nt = 0; nt < 17; nt++) {
        int c0 = nt * 8 + 2 * tig;
        float s0 = (c0     < CTX) ? sacc[nt][0] * scale : -1e30f;
        float s1 = (c0 + 1 < CTX) ? sacc[nt][1] * scale : -1e30f;
        float s2 = (c0     < CTX) ? sacc[nt][2] * scale : -1e30f;
        float s3 = (c0 + 1 < CTX) ? sacc[nt][3] * scale : -1e30f;
        sacc[nt][0] = s0; sacc[nt][1] = s1; sacc[nt][2] = s2; sacc[nt][3] = s3;
        mlo = fmaxf(mlo, fmaxf(s0, s1));
        mhi = fmaxf(mhi, fmaxf(s2, s3));
    }
    mlo = fmaxf(mlo, __shfl_xor_sync(0xffffffffu, mlo, 1));
    mlo = fmaxf(mlo, __shfl_xor_sync(0xffffffffu, mlo, 2));
    mhi = fmaxf(mhi, __shfl_xor_sync(0xffffffffu, mhi, 1));
    mhi = fmaxf(mhi, __shfl_xor_sync(0xffffffffu, mhi, 2));

    float llo = 0.f, lhi = 0.f;
#pragma unroll
    for (int nt = 0; nt < 17; nt++) {
        float p0 = __expf(sacc[nt][0] - mlo);
        float p1 = __expf(sacc[nt][1] - mlo);
        float p2 = __expf(sacc[nt][2] - mhi);
        float p3 = __expf(sacc[nt][3] - mhi);
        llo += p0 + p1; lhi += p2 + p3;
        sacc[nt][0] = p0; sacc[nt][1] = p1; sacc[nt][2] = p2; sacc[nt][3] = p3;
    }
    llo += __shfl_xor_sync(0xffffffffu, llo, 1);
    llo += __shfl_xor_sync(0xffffffffu, llo, 2);
    lhi += __shfl_xor_sync(0xffffffffu, lhi, 1);
    lhi += __shfl_xor_sync(0xffffffffu, lhi, 2);

    // ---- P -> smem (half pairs); pad cols 136..143 zero -----------------------
#pragma unroll
    for (int nt = 0; nt < 17; nt++) {
        Ps[(rbase + g) * 76 + nt * 4 + tig]     = pk2(sacc[nt][0], sacc[nt][1]);
        Ps[(rbase + g + 8) * 76 + nt * 4 + tig] = pk2(sacc[nt][2], sacc[nt][3]);
    }
    Ps[(rbase + g) * 76 + 68 + tig] = 0u;
    Ps[(rbase + g + 8) * 76 + 68 + tig] = 0u;
    __syncwarp();

    // ---- phase 2: O = P V (9 ksteps of 16 over 144 keys) ----------------------
    float oacc[8][4];
#pragma unroll
    for (int nt = 0; nt < 8; nt++)
#pragma unroll
        for (int j = 0; j < 4; j++) oacc[nt][j] = 0.f;

#pragma unroll
    for (int ks = 0; ks < 9; ks++) {
        uint32_t a2[4];
        a2[0] = Ps[(rbase + g) * 76 + tig + 8 * ks];
        a2[1] = Ps[(rbase + g + 8) * 76 + tig + 8 * ks];
        a2[2] = Ps[(rbase + g) * 76 + tig + 4 + 8 * ks];
        a2[3] = Ps[(rbase + g + 8) * 76 + tig + 4 + 8 * ks];
#pragma unroll
        for (int nt = 0; nt < 8; nt++) {
            uint32_t bfr[2];
            bfr[0] = Vt[(nt * 8 + g) * 77 + tig + 8 * ks];
            bfr[1] = Vt[(nt * 8 + g) * 77 + tig + 4 + 8 * ks];
            mma_f16(oacc[nt], a2, bfr);
        }
    }

    // ---- output y (half) -------------------------------------------------------
    float invlo = 1.f / llo, invhi = 1.f / lhi;
    int row_lo = n0 + rbase + g;
    int row_hi = row_lo + 8;
#pragma unroll
    for (int nt = 0; nt < 8; nt++) {
        int col = h * dh + nt * 8 + 2 * tig;
        if (row_lo < Nn)
            *reinterpret_cast<uint32_t*>(&y[((size_t)b * Nn + row_lo) * Dd + col]) =
                pk2(oacc[nt][0] * invlo, oacc[nt][1] * invlo);
        if (row_hi < Nn)
            *reinterpret_cast<uint32_t*>(&y[((size_t)b * Nn + row_hi) * Dd + col]) =
                pk2(oacc[nt][2] * invhi, oacc[nt][3] * invhi);
    }
}

// ---------------- launch -----------------------------------------------------
extern "C" void kernel_launch(void* const* d_in, const int* in_sizes, int n_in,
                              void* d_out, int out_size)
{
    const float* x    = (const float*)d_in[0];
    const float* Qb   = (const float*)d_in[1];
    const float* Wq   = (const float*)d_in[2];
    const float* Wctx = (const float*)d_in[3];
    const float* bctx = (const float*)d_in[4];
    const float* Wout = (const float*)d_in[5];
    const float* bout = (const float*)d_in[6];
    const float* cent = (const float*)d_in[7];
    float* out = (float*)d_out;

    __half *p_xh, *p_wqT, *p_wctxT, *p_woutT, *p_qctx, *p_probs, *p_ctx, *p_kv, *p_q, *p_y;
    float *p_scores;
    cudaGetSymbolAddress((void**)&p_xh,     g_xh);
    cudaGetSymbolAddress((void**)&p_wqT,    g_wqT);
    cudaGetSymbolAddress((void**)&p_wctxT,  g_wctxT);
    cudaGetSymbolAddress((void**)&p_woutT,  g_woutT);
    cudaGetSymbolAddress((void**)&p_qctx,   g_qctx);
    cudaGetSymbolAddress((void**)&p_scores, g_scores);
    cudaGetSymbolAddress((void**)&p_probs,  g_probs);
    cudaGetSymbolAddress((void**)&p_ctx,    g_ctx);
    cudaGetSymbolAddress((void**)&p_kv,     g_kv);
    cudaGetSymbolAddress((void**)&p_q,      g_q);
    cudaGetSymbolAddress((void**)&p_y,      g_y);

    const int SMEM_NT  = (3 * 128 * 20 + 3 * 128 * 20) * 4;   // 61440
    const int SMEM_NN  = (3 * 128 * 20 + 3 * 32 * 68) * 4;    // 56832
    const int ATTN_SMEM = (128 * 36 + 136 * 36 + 64 * 77 + 128 * 76) * 4;  // 96640
    cudaFuncSetAttribute((const void*)hgemm<true,  false, false>, cudaFuncAttributeMaxDynamicSharedMemorySize, SMEM_NT);
    cudaFuncSetAttribute((const void*)hgemm<true,  false, true >, cudaFuncAttributeMaxDynamicSharedMemorySize, SMEM_NT);
    cudaFuncSetAttribute((const void*)hgemm<true,  true,  true >, cudaFuncAttributeMaxDynamicSharedMemorySize, SMEM_NT);
    cudaFuncSetAttribute((const void*)hgemm<true,  true,  false>, cudaFuncAttributeMaxDynamicSharedMemorySize, SMEM_NT);
    cudaFuncSetAttribute((const void*)hgemm<false, false, true >, cudaFuncAttributeMaxDynamicSharedMemorySize, SMEM_NN);
    cudaFuncSetAttribute((const void*)attn_mma, cudaFuncAttributeMaxDynamicSharedMemorySize, ATTN_SMEM);

    const size_t main_sz = (size_t)Bsz * Nn * Dd;
    float* cls_out = nullptr;
    float* idx_out = nullptr;
    if ((size_t)out_size >= main_sz + (size_t)Bsz * Dd + Bsz) {
        cls_out = out + main_sz;
        idx_out = out + main_sz + (size_t)Bsz * Dd;
    }

    // 0) convert x -> half; transpose weights -> half [N,K]
    {
        int n4 = (int)(main_sz / 4);
        f2h_kernel<<<(n4 + 255) / 256, 256>>>((const float4*)x, (uint2*)p_xh, n4);
        transpose_h<<<dim3(Dd / 32, Dd / 32), dim3(32, 8)>>>(Wq,   p_wqT,   Dd, Dd);
        transpose_h<<<dim3(2 * Dd / 32, Dd / 32), dim3(32, 8)>>>(Wctx, p_wctxT, Dd, 2 * Dd);
        transpose_h<<<dim3(Dd / 32, Dd / 32), dim3(32, 8)>>>(Wout, p_woutT, Dd, Dd);
    }

    // 1) cls / argmax (exact fp32)
    cls_kernel<<<Bsz, 256>>>(x, cent, cls_out, idx_out);

    // 2) gather (half) + xreg copy
    gather_qctx_kernel<<<4096, 256>>>(Qb);
    xreg_kernel<<<(Bsz * Rr * Dd / 2 + 255) / 256, 256>>>();

    // 3) scores = q_ctx @ xp^T (NT, batched, fp32 out)
    hgemm<true, false, false><<<dim3(Pp / 128, 1, Bsz), 256, SMEM_NT>>>(
        p_qctx, p_xh + (size_t)Rr * Dd, nullptr, p_scores,
        Kk, Pp, Dd, Dd, Dd, Pp,
        (long long)Kk * Dd, (long long)Nn * Dd, (long long)Kk * Pp);

    // 4) softmax -> half probs
    softmax_kernel<<<Bsz * Kk, 256>>>(p_scores, p_probs);

    // 5) ctx_p = probs @ xp (NN, batched, half out)
    hgemm<false, false, true><<<dim3(Dd / 128, 1, Bsz), 256, SMEM_NN>>>(
        p_probs, p_xh + (size_t)Rr * Dd, nullptr, p_ctx + (size_t)Rr * Dd,
        Kk, Dd, Pp, Pp, Dd, Dd,
        (long long)Kk * Pp, (long long)Nn * Dd, (long long)CTX * Dd);

    // 6) kv = ctx @ Wctx + bctx (NT via Wctx^T, half out)
    hgemm<true, true, true><<<dim3((2 * Dd) / 128, (Bsz * CTX + 127) / 128, 1), 256, SMEM_NT>>>(
        p_ctx, p_wctxT, bctx, p_kv,
        Bsz * CTX, 2 * Dd, Dd, Dd, Dd, 2 * Dd, 0, 0, 0);

    // 7) q = x @ Wq (NT via Wq^T, half out)
    hgemm<true, false, true><<<dim3(Dd / 128, (Bsz * Nn + 127) / 128, 1), 256, SMEM_NT>>>(
        p_xh, p_wqT, nullptr, p_q,
        Bsz * Nn, Dd, Dd, Dd, Dd, Dd, 0, 0, 0);

    // 8) fused fp16 attention -> y (half)
    attn_mma<<<dim3((Nn + 127) / 128, Bsz * Hh), 256, ATTN_SMEM>>>(p_y);

    // 9) out = y @ Wout + bout (NT via Wout^T, fp32 out)
    hgemm<true, true, false><<<dim3(Dd / 128, (Bsz * Nn + 127) / 128, 1), 256, SMEM_NT>>>(
        p_y, p_woutT, bout, out,
        Bsz * Nn, Dd, Dd, Dd, Dd, Dd, 0, 0, 0);
}

// round 6
// speedup vs baseline: 4.7706x; 1.0187x over previous
#include <cuda_runtime.h>
#include <cuda_fp16.h>
#include <math.h>
#include <stdint.h>

#define Bsz 64
#define Nn  1029
#define Dd  768
#define Hh  12
#define dh  64
#define Kk  128
#define Rr  5
#define Mm  4
#define Pp  1024          // N - R
#define CTX 133           // R + K

// ---------------- scratch (static device globals: allocation-free) ----------
__device__ int    g_idx[Bsz];
__device__ __half g_xh[(size_t)Bsz * Nn * Dd];
__device__ __half g_wqT[Dd * Dd];
__device__ __half g_wctxT[2 * Dd * Dd];
__device__ __half g_woutT[Dd * Dd];
__device__ __half g_qctx[(size_t)Bsz * Kk * Dd];
__device__ float  g_scores[(size_t)Bsz * Kk * Pp];
__device__ __half g_probs[(size_t)Bsz * Kk * Pp];
__device__ __half g_ctx[(size_t)Bsz * CTX * Dd];
__device__ __half g_kv[(size_t)Bsz * CTX * 2 * Dd];
__device__ __half g_q[(size_t)Bsz * Nn * Dd];
__device__ __half g_y[(size_t)Bsz * Nn * Dd];

// ---------------- helpers ----------------------------------------------------
__device__ __forceinline__ uint32_t pk2(float a, float b) {
    __half2 h = __floats2half2_rn(a, b);
    return *reinterpret_cast<uint32_t*>(&h);
}

__device__ __forceinline__ void mma_f16(float* c, const uint32_t* a, const uint32_t* b) {
    asm volatile(
        "mma.sync.aligned.m16n8k16.row.col.f32.f16.f16.f32 "
        "{%0,%1,%2,%3}, {%4,%5,%6,%7}, {%8,%9}, {%0,%1,%2,%3};\n"
        : "+f"(c[0]), "+f"(c[1]), "+f"(c[2]), "+f"(c[3])
        : "r"(a[0]), "r"(a[1]), "r"(a[2]), "r"(a[3]), "r"(b[0]), "r"(b[1]));
}

__device__ __forceinline__ void ldsm4(uint32_t& r0, uint32_t& r1, uint32_t& r2,
                                      uint32_t& r3, uint32_t a) {
    asm volatile("ldmatrix.sync.aligned.m8n8.x4.shared.b16 {%0,%1,%2,%3}, [%4];"
                 : "=r"(r0), "=r"(r1), "=r"(r2), "=r"(r3) : "r"(a));
}
__device__ __forceinline__ void ldsm4t(uint32_t& r0, uint32_t& r1, uint32_t& r2,
                                       uint32_t& r3, uint32_t a) {
    asm volatile("ldmatrix.sync.aligned.m8n8.x4.trans.shared.b16 {%0,%1,%2,%3}, [%4];"
                 : "=r"(r0), "=r"(r1), "=r"(r2), "=r"(r3) : "r"(a));
}

__device__ __forceinline__ void cp16(void* smem_dst, const void* gsrc, unsigned bytes) {
    unsigned saddr = (unsigned)__cvta_generic_to_shared(smem_dst);
    asm volatile("cp.async.cg.shared.global [%0], [%1], 16, %2;\n"
                 :: "r"(saddr), "l"(gsrc), "r"(bytes));
}
__device__ __forceinline__ void cp_commit() { asm volatile("cp.async.commit_group;\n"); }
template<int N> __device__ __forceinline__ void cp_wait() {
    asm volatile("cp.async.wait_group %0;\n" :: "n"(N));
}

// ---------------- conversion kernels ------------------------------------------
__global__ void f2h_kernel(const float4* __restrict__ src, uint2* __restrict__ dst, int n4)
{
    int i = blockIdx.x * blockDim.x + threadIdx.x;
    if (i < n4) {
        float4 v = src[i];
        uint2 o;
        o.x = pk2(v.x, v.y);
        o.y = pk2(v.z, v.w);
        dst[i] = o;
    }
}

__global__ void transpose_h(const float* __restrict__ src, __half* __restrict__ dst,
                            int K, int N)
{
    __shared__ float t[32][33];
    int k0 = blockIdx.y * 32, n0 = blockIdx.x * 32;
    int tx = threadIdx.x, ty = threadIdx.y;   // 32 x 8
    for (int i = ty; i < 32; i += 8)
        t[i][tx] = src[(size_t)(k0 + i) * N + n0 + tx];
    __syncthreads();
    for (int i = ty; i < 32; i += 8)
        dst[(size_t)(n0 + i) * K + k0 + tx] = __float2half_rn(t[tx][i]);
}

// ---------------- cls_n, sims, argmax (fp32 exact) ---------------------------
__global__ void cls_kernel(const float* __restrict__ x,
                           const float* __restrict__ cent,
                           float* __restrict__ cls_out,
                           float* __restrict__ idx_out)
{
    int b = blockIdx.x;
    int tid = threadIdx.x;
    __shared__ float xs[Dd];
    __shared__ float red[256];
    __shared__ float sims[Mm];
    __shared__ float inv_s;

    float ss = 0.f;
    for (int i = tid; i < Dd; i += 256) {
        float v = x[(size_t)b * Nn * Dd + i];
        xs[i] = v;
        ss += v * v;
    }
    red[tid] = ss; __syncthreads();
    for (int s = 128; s > 0; s >>= 1) { if (tid < s) red[tid] += red[tid + s]; __syncthreads(); }
    if (tid == 0) inv_s = 1.f / fmaxf(sqrtf(red[0]), 1e-12f);
    __syncthreads();
    float inv = inv_s;

    for (int m = 0; m < Mm; m++) {
        float p = 0.f;
        for (int i = tid; i < Dd; i += 256) p += xs[i] * cent[m * Dd + i];
        red[tid] = p; __syncthreads();
        for (int s = 128; s > 0; s >>= 1) { if (tid < s) red[tid] += red[tid + s]; __syncthreads(); }
        if (tid == 0) sims[m] = red[0] * inv;
        __syncthreads();
    }
    if (tid == 0) {
        int best = 0; float bv = sims[0];
        for (int m = 1; m < Mm; m++) if (sims[m] > bv) { bv = sims[m]; best = m; }
        g_idx[b] = best;
        if (idx_out) idx_out[b] = (float)best;
    }
    if (cls_out)
        for (int i = tid; i < Dd; i += 256)
            cls_out[(size_t)b * Dd + i] = xs[i] * inv;
}

// ---------------- gather Q_banks[idx] (half) + xreg --------------------------
__global__ void gather_qctx_kernel(const float* __restrict__ Qb)
{
    size_t total = (size_t)Bsz * Kk * Dd;
    for (size_t i = (size_t)blockIdx.x * blockDim.x + threadIdx.x; i < total;
         i += (size_t)gridDim.x * blockDim.x) {
        int b = (int)(i / ((size_t)Kk * Dd));
        size_t r = i - (size_t)b * Kk * Dd;
        g_qctx[i] = __float2half_rn(Qb[(size_t)g_idx[b] * Kk * Dd + r]);
    }
}

__global__ void xreg_kernel()
{
    int i = blockIdx.x * blockDim.x + threadIdx.x;       // u32 units
    const int total = Bsz * Rr * Dd / 2;
    if (i < total) {
        int b = i / (Rr * Dd / 2);
        int r = i - b * (Rr * Dd / 2);
        reinterpret_cast<uint32_t*>(g_ctx)[(size_t)b * CTX * Dd / 2 + r] =
            reinterpret_cast<const uint32_t*>(g_xh)[(size_t)b * Nn * Dd / 2 + r];
    }
}

// ---------------- fp16 tensor-core GEMM, 3-stage cp.async + ldmatrix --------
// C[M,N] = A[M,Kd] @ op(B) (+bias). op = B[Kd,N] (NN) or B[N,Kd]^T (NT).
// Block 128x128x32 halfs, 256 threads (8 warps 4x2), warp tile 32x64,
// mma m16n8k16 f16 -> f32. N%128==0, Kd%32==0; M guarded.
template<bool TRANSB, bool BIAS, bool OUTHALF>
__global__ __launch_bounds__(256, 2)
void hgemm(const __half* __restrict__ A, const __half* __restrict__ Bm,
           const float* __restrict__ bias, void* __restrict__ Cv,
           int M, int N, int Kd, int lda, int ldb, int ldc,
           long long sA, long long sB, long long sC)
{
    extern __shared__ uint32_t smu[];
    const int ASTG = 128 * 20;                        // u32 per A stage (pitch 20 u32)
    const int BSTG = TRANSB ? 128 * 20 : 32 * 68;     // NN: [32 k][136 halfs]
    uint32_t* smA = smu;
    uint32_t* smB = smu + 3 * ASTG;
    const uint32_t sbA = (uint32_t)__cvta_generic_to_shared(smA);
    const uint32_t sbB = (uint32_t)__cvta_generic_to_shared(smB);

    const __half* Ab = A  + (long long)blockIdx.z * sA;
    const __half* Bb = Bm + (long long)blockIdx.z * sB;

    const int row0 = blockIdx.y * 128;
    const int col0 = blockIdx.x * 128;
    const int tid  = threadIdx.x;
    const int lane = tid & 31;
    const int warp = tid >> 5;
    const int wm = warp >> 1;
    const int wn = warp & 1;
    const int g   = lane >> 2;
    const int tig = lane & 3;

    // ldmatrix per-lane offsets (bytes within a stage)
    const int lrow = ((lane >> 3) & 1) * 8 + (lane & 7);
    const int lk8  = (lane >> 4) * 8;                 // 0 or 8 (halfs)
    uint32_t aoff[2], boff[4];
#pragma unroll
    for (int im = 0; im < 2; im++)
        aoff[im] = (uint32_t)(((wm * 32 + im * 16 + lrow) * 40 + lk8) * 2);
#pragma unroll
    for (int p = 0; p < 4; p++) {
        if (TRANSB)
            boff[p] = (uint32_t)(((wn * 64 + p * 16 + lrow) * 40 + lk8) * 2);
        else
            boff[p] = (uint32_t)(((((lane >> 4) & 1) * 8 + (lane & 7)) * 136
                                  + wn * 64 + p * 16 + ((lane >> 3) & 1) * 8) * 2);
    }

    float acc[2][8][4];
#pragma unroll
    for (int im = 0; im < 2; im++)
#pragma unroll
        for (int in = 0; in < 8; in++)
#pragma unroll
            for (int j = 0; j < 4; j++) acc[im][in][j] = 0.f;

    auto loadA = [&](int stg, int k0) {
        uint32_t* dst = smA + stg * ASTG;
#pragma unroll
        for (int it = 0; it < 2; it++) {
            int id = tid + it * 256;
            int r  = id >> 2;
            int c  = (id & 3) * 4;
            int gr = row0 + r;
            unsigned ok = (gr < M) ? 16u : 0u;
            const __half* src = Ab + (size_t)(gr < M ? gr : 0) * lda + k0 + c * 2;
            cp16(dst + r * 20 + c, src, ok);
        }
    };
    auto loadB = [&](int stg, int k0) {
        uint32_t* dst = smB + stg * BSTG;
#pragma unroll
        for (int it = 0; it < 2; it++) {
            int id = tid + it * 256;
            if (TRANSB) {
                int n = id >> 2;
                int c = (id & 3) * 4;
                cp16(dst + n * 20 + c, Bb + (size_t)(col0 + n) * ldb + k0 + c * 2, 16u);
            } else {
                int kr = id >> 4;
                int ch = id & 15;
                cp16(dst + kr * 68 + ch * 4, Bb + (size_t)(k0 + kr) * ldb + col0 + ch * 8, 16u);
            }
        }
    };

    loadA(0, 0); loadB(0, 0); cp_commit();
    loadA(1, 32); loadB(1, 32); cp_commit();

    const int nk = Kd >> 5;
    for (int i = 0; i < nk; i++) {
        if (i + 1 < nk) cp_wait<1>(); else cp_wait<0>();
        __syncthreads();
        if (i + 2 < nk) {
            int s3 = (i + 2) % 3;
            loadA(s3, (i + 2) * 32);
            loadB(s3, (i + 2) * 32);
            cp_commit();
        }

        const uint32_t baA = sbA + (uint32_t)((i % 3) * ASTG * 4);
        const uint32_t baB = sbB + (uint32_t)((i % 3) * BSTG * 4);

#pragma unroll
        for (int s = 0; s < 2; s++) {             // two k16 steps per 32-k block
            uint32_t afr[2][4], bfr[8][2];
#pragma unroll
            for (int im = 0; im < 2; im++)
                ldsm4(afr[im][0], afr[im][1], afr[im][2], afr[im][3],
                      baA + aoff[im] + s * 32);
#pragma unroll
            for (int p = 0; p < 4; p++) {
                if (TRANSB)
                    ldsm4(bfr[2 * p][0], bfr[2 * p + 1][0], bfr[2 * p][1], bfr[2 * p + 1][1],
                          baB + boff[p] + s * 32);
                else
                    ldsm4t(bfr[2 * p][0], bfr[2 * p + 1][0], bfr[2 * p][1], bfr[2 * p + 1][1],
                           baB + boff[p] + s * 4352);
            }
#pragma unroll
            for (int im = 0; im < 2; im++)
#pragma unroll
                for (int in = 0; in < 8; in++)
                    mma_f16(acc[im][in], afr[im], bfr[in]);
        }
        __syncthreads();
    }

    // ---- epilogue ----------------------------------------------------------
#pragma unroll
    for (int im = 0; im < 2; im++) {
        int rb = row0 + wm * 32 + im * 16 + g;
#pragma unroll
        for (int in = 0; in < 8; in++) {
            int cb = col0 + wn * 64 + in * 8 + 2 * tig;
            float b0 = BIAS ? bias[cb] : 0.f;
            float b1 = BIAS ? bias[cb + 1] : 0.f;
            float v0 = acc[im][in][0] + b0, v1 = acc[im][in][1] + b1;
            float v2 = acc[im][in][2] + b0, v3 = acc[im][in][3] + b1;
            if (OUTHALF) {
                __half* C = (__half*)Cv + (long long)blockIdx.z * sC;
                if (rb < M)
                    *reinterpret_cast<uint32_t*>(&C[(size_t)rb * ldc + cb]) = pk2(v0, v1);
                if (rb + 8 < M)
                    *reinterpret_cast<uint32_t*>(&C[(size_t)(rb + 8) * ldc + cb]) = pk2(v2, v3);
            } else {
                float* C = (float*)Cv + (long long)blockIdx.z * sC;
                if (rb < M)
                    *reinterpret_cast<float2*>(&C[(size_t)rb * ldc + cb]) = make_float2(v0, v1);
                if (rb + 8 < M)
                    *reinterpret_cast<float2*>(&C[(size_t)(rb + 8) * ldc + cb]) = make_float2(v2, v3);
            }
        }
    }
}

// ---------------- row softmax over P=1024: fp32 in, half out ------------------
__global__ void softmax_kernel(const float* __restrict__ s, __half* __restrict__ pr)
{
    int row = blockIdx.x;
    const float4* p4 = reinterpret_cast<const float4*>(s + (size_t)row * Pp);
    uint32_t* o2 = reinterpret_cast<uint32_t*>(pr + (size_t)row * Pp);
    int tid = threadIdx.x;
    __shared__ float red[256];

    float4 v = p4[tid];
    float mx = fmaxf(fmaxf(v.x, v.y), fmaxf(v.z, v.w));
    red[tid] = mx; __syncthreads();
    for (int st = 128; st > 0; st >>= 1) { if (tid < st) red[tid] = fmaxf(red[tid], red[tid + st]); __syncthreads(); }
    mx = red[0]; __syncthreads();

    v.x = __expf(v.x - mx); v.y = __expf(v.y - mx);
    v.z = __expf(v.z - mx); v.w = __expf(v.w - mx);
    float sm = v.x + v.y + v.z + v.w;
    red[tid] = sm; __syncthreads();
    for (int st = 128; st > 0; st >>= 1) { if (tid < st) red[tid] += red[tid + st]; __syncthreads(); }
    float inv = 1.f / red[0];
    o2[2 * tid]     = pk2(v.x * inv, v.y * inv);
    o2[2 * tid + 1] = pk2(v.z * inv, v.w * inv);
}

// ---------------- fp16 tensor-core fused attention (ldmatrix) -----------------
// grid (9, B*H), 256 threads (8 warps x 16 query rows). Keys padded to 144.
__global__ __launch_bounds__(256)
void attn_mma(__half* __restrict__ y)
{
    extern __shared__ uint32_t smu[];
    uint32_t* Qs = smu;                    // [128][36] u32  (72-half pitch)
    uint32_t* Ks = smu + 128 * 36;         // [144][36]
    uint32_t* Vt = Ks + 144 * 36;          // [64 d][76] u32 (152-half pitch)
    uint32_t* Ps = Vt + 64 * 76;           // [128][76] u32  (152-half pitch)
    const uint32_t sQ = (uint32_t)__cvta_generic_to_shared(Qs);
    const uint32_t sK = (uint32_t)__cvta_generic_to_shared(Ks);
    const uint32_t sV = (uint32_t)__cvta_generic_to_shared(Vt);
    const uint32_t sP = (uint32_t)__cvta_generic_to_shared(Ps);

    const int bh = blockIdx.y;
    const int b = bh / Hh, h = bh % Hh;
    const int n0 = blockIdx.x * 128;
    const int tid = threadIdx.x;
    const int lane = tid & 31;
    const int w = tid >> 5;
    const int g = lane >> 2;
    const int tig = lane & 3;
    const int rbase = w * 16;

    const int lrow = ((lane >> 3) & 1) * 8 + (lane & 7);
    const int lk8  = (lane >> 4) * 8;

    // ---- Q tile 128x64 halfs -------------------------------------------------
#pragma unroll
    for (int it = 0; it < 4; it++) {
        int id = tid + it * 256;
        int r  = id >> 3;
        int ch = id & 7;
        int n  = n0 + r;
        unsigned ok = (n < Nn) ? 16u : 0u;
        const __half* src = g_q + ((size_t)b * Nn + (n < Nn ? n : 0)) * Dd + h * dh + ch * 8;
        cp16(Qs + r * 36 + ch * 4, src, ok);
    }
    // ---- K tile 144x64 halfs (rows >= CTX zero-filled) ------------------------
#pragma unroll
    for (int it = 0; it < 5; it++) {
        int id = tid + it * 256;
        if (id < 144 * 8) {
            int key = id >> 3;
            int ch  = id & 7;
            unsigned ok = (key < CTX) ? 16u : 0u;
            const __half* src = g_kv + ((size_t)b * CTX + (key < CTX ? key : 0)) * (2 * Dd)
                              + h * dh + ch * 8;
            cp16(Ks + key * 36 + ch * 4, src, ok);
        }
    }
    cp_commit();

    // ---- V transposed into Vt_half[d][key] ------------------------------------
    unsigned short* Vth = reinterpret_cast<unsigned short*>(Vt);
    for (int id = tid; id < CTX * 32; id += 256) {
        int key = id >> 5;
        int dp  = id & 31;
        uint32_t v = *reinterpret_cast<const uint32_t*>(
            g_kv + ((size_t)b * CTX + key) * (2 * Dd) + Dd + h * dh + 2 * dp);
        Vth[(2 * dp) * 152 + key]     = (unsigned short)(v & 0xffff);
        Vth[(2 * dp + 1) * 152 + key] = (unsigned short)(v >> 16);
    }
    for (int id = tid; id < 64 * 11; id += 256) {   // zero keys 133..143
        int d = id / 11, key = CTX + id % 11;
        Vth[d * 152 + key] = 0;
    }
    cp_wait<0>();
    __syncthreads();

    // ---- phase 1: S = Q K^T (4 k-steps of 16 over d=64) -----------------------
    uint32_t afr[4][4];
#pragma unroll
    for (int ks = 0; ks < 4; ks++)
        ldsm4(afr[ks][0], afr[ks][1], afr[ks][2], afr[ks][3],
              sQ + (uint32_t)((((rbase + lrow) * 72 + lk8) * 2) + ks * 32));

    float sacc[18][4];
#pragma unroll
    for (int nt = 0; nt < 18; nt++)
#pragma unroll
        for (int j = 0; j < 4; j++) sacc[nt][j] = 0.f;

    const uint32_t koff = sK + (uint32_t)((lrow * 72 + lk8) * 2);
#pragma unroll
    for (int ntp = 0; ntp < 9; ntp++) {
#pragma unroll
        for (int ks = 0; ks < 4; ks++) {
            uint32_t bfr[2][2];
            ldsm4(bfr[0][0], bfr[1][0], bfr[0][1], bfr[1][1],
                  koff + (uint32_t)(ntp * 2304 + ks * 32));
            mma_f16(sacc[2 * ntp],     afr[ks], bfr[0]);
            mma_f16(sacc[2 * ntp + 1], afr[ks], bfr[1]);
        }
    }

    // ---- exact softmax over 133 keys (pad cols -> 0) ---------------------------
    const float scale = 0.125f;
    float mlo = -1e30f, mhi = -1e30f;
#pragma unroll
    for (int nt = 0; nt < 18; nt++) {
        int c0 = nt * 8 + 2 * tig;
        float s0 = (c0     < CTX) ? sacc[nt][0] * scale : -1e30f;
        float s1 = (c0 + 1 < CTX) ? sacc[nt][1] * scale : -1e30f;
        float s2 = (c0     < CTX) ? sacc[nt][2] * scale : -1e30f;
        float s3 = (c0 + 1 < CTX) ? sacc[nt][3] * scale : -1e30f;
        sacc[nt][0] = s0; sacc[nt][1] = s1; sacc[nt][2] = s2; sacc[nt][3] = s3;
        mlo = fmaxf(mlo, fmaxf(s0, s1));
        mhi = fmaxf(mhi, fmaxf(s2, s3));
    }
    mlo = fmaxf(mlo, __shfl_xor_sync(0xffffffffu, mlo, 1));
    mlo = fmaxf(mlo, __shfl_xor_sync(0xffffffffu, mlo, 2));
    mhi = fmaxf(mhi, __shfl_xor_sync(0xffffffffu, mhi, 1));
    mhi = fmaxf(mhi, __shfl_xor_sync(0xffffffffu, mhi, 2));

    float llo = 0.f, lhi = 0.f;
#pragma unroll
    for (int nt = 0; nt < 18; nt++) {
        float p0 = __expf(sacc[nt][0] - mlo);
        float p1 = __expf(sacc[nt][1] - mlo);
        float p2 = __expf(sacc[nt][2] - mhi);
        float p3 = __expf(sacc[nt][3] - mhi);
        llo += p0 + p1; lhi += p2 + p3;
        sacc[nt][0] = p0; sacc[nt][1] = p1; sacc[nt][2] = p2; sacc[nt][3] = p3;
    }
    llo += __shfl_xor_sync(0xffffffffu, llo, 1);
    llo += __shfl_xor_sync(0xffffffffu, llo, 2);
    lhi += __shfl_xor_sync(0xffffffffu, lhi, 1);
    lhi += __shfl_xor_sync(0xffffffffu, lhi, 2);

    // ---- P -> smem (half pairs, 144 cols incl. zero pad) -----------------------
#pragma unroll
    for (int nt = 0; nt < 18; nt++) {
        Ps[(rbase + g) * 76 + nt * 4 + tig]     = pk2(sacc[nt][0], sacc[nt][1]);
        Ps[(rbase + g + 8) * 76 + nt * 4 + tig] = pk2(sacc[nt][2], sacc[nt][3]);
    }
    __syncwarp();

    // ---- phase 2: O = P V (9 k-steps of 16 over 144 keys) ----------------------
    float oacc[8][4];
#pragma unroll
    for (int nt = 0; nt < 8; nt++)
#pragma unroll
        for (int j = 0; j < 4; j++) oacc[nt][j] = 0.f;

    const uint32_t poff = sP + (uint32_t)(((rbase + lrow) * 152 + lk8) * 2);
    const uint32_t voff = sV + (uint32_t)((lrow * 152 + lk8) * 2);
#pragma unroll
    for (int ks = 0; ks < 9; ks++) {
        uint32_t a2[4];
        ldsm4(a2[0], a2[1], a2[2], a2[3], poff + (uint32_t)(ks * 32));
#pragma unroll
        for (int ntp = 0; ntp < 4; ntp++) {
            uint32_t bfr[2][2];
            ldsm4(bfr[0][0], bfr[1][0], bfr[0][1], bfr[1][1],
                  voff + (uint32_t)(ntp * 4864 + ks * 32));
            mma_f16(oacc[2 * ntp],     a2, bfr[0]);
            mma_f16(oacc[2 * ntp + 1], a2, bfr[1]);
        }
    }

    // ---- output y (half) -------------------------------------------------------
    float invlo = 1.f / llo, invhi = 1.f / lhi;
    int row_lo = n0 + rbase + g;
    int row_hi = row_lo + 8;
#pragma unroll
    for (int nt = 0; nt < 8; nt++) {
        int col = h * dh + nt * 8 + 2 * tig;
        if (row_lo < Nn)
            *reinterpret_cast<uint32_t*>(&y[((size_t)b * Nn + row_lo) * Dd + col]) =
                pk2(oacc[nt][0] * invlo, oacc[nt][1] * invlo);
        if (row_hi < Nn)
            *reinterpret_cast<uint32_t*>(&y[((size_t)b * Nn + row_hi) * Dd + col]) =
                pk2(oacc[nt][2] * invhi, oacc[nt][3] * invhi);
    }
}

// ---------------- launch -----------------------------------------------------
extern "C" void kernel_launch(void* const* d_in, const int* in_sizes, int n_in,
                              void* d_out, int out_size)
{
    const float* x    = (const float*)d_in[0];
    const float* Qb   = (const float*)d_in[1];
    const float* Wq   = (const float*)d_in[2];
    const float* Wctx = (const float*)d_in[3];
    const float* bctx = (const float*)d_in[4];
    const float* Wout = (const float*)d_in[5];
    const float* bout = (const float*)d_in[6];
    const float* cent = (const float*)d_in[7];
    float* out = (float*)d_out;

    __half *p_xh, *p_wqT, *p_wctxT, *p_woutT, *p_qctx, *p_probs, *p_ctx, *p_kv, *p_q, *p_y;
    float *p_scores;
    cudaGetSymbolAddress((void**)&p_xh,     g_xh);
    cudaGetSymbolAddress((void**)&p_wqT,    g_wqT);
    cudaGetSymbolAddress((void**)&p_wctxT,  g_wctxT);
    cudaGetSymbolAddress((void**)&p_woutT,  g_woutT);
    cudaGetSymbolAddress((void**)&p_qctx,   g_qctx);
    cudaGetSymbolAddress((void**)&p_scores, g_scores);
    cudaGetSymbolAddress((void**)&p_probs,  g_probs);
    cudaGetSymbolAddress((void**)&p_ctx,    g_ctx);
    cudaGetSymbolAddress((void**)&p_kv,     g_kv);
    cudaGetSymbolAddress((void**)&p_q,      g_q);
    cudaGetSymbolAddress((void**)&p_y,      g_y);

    const int SMEM_NT  = (3 * 128 * 20 + 3 * 128 * 20) * 4;   // 61440
    const int SMEM_NN  = (3 * 128 * 20 + 3 * 32 * 68) * 4;    // 56832
    const int ATTN_SMEM = (128 * 36 + 144 * 36 + 64 * 76 + 128 * 76) * 4;  // 97920
    cudaFuncSetAttribute((const void*)hgemm<true,  false, false>, cudaFuncAttributeMaxDynamicSharedMemorySize, SMEM_NT);
    cudaFuncSetAttribute((const void*)hgemm<true,  false, true >, cudaFuncAttributeMaxDynamicSharedMemorySize, SMEM_NT);
    cudaFuncSetAttribute((const void*)hgemm<true,  true,  true >, cudaFuncAttributeMaxDynamicSharedMemorySize, SMEM_NT);
    cudaFuncSetAttribute((const void*)hgemm<true,  true,  false>, cudaFuncAttributeMaxDynamicSharedMemorySize, SMEM_NT);
    cudaFuncSetAttribute((const void*)hgemm<false, false, true >, cudaFuncAttributeMaxDynamicSharedMemorySize, SMEM_NN);
    cudaFuncSetAttribute((const void*)attn_mma, cudaFuncAttributeMaxDynamicSharedMemorySize, ATTN_SMEM);

    const size_t main_sz = (size_t)Bsz * Nn * Dd;
    float* cls_out = nullptr;
    float* idx_out = nullptr;
    if ((size_t)out_size >= main_sz + (size_t)Bsz * Dd + Bsz) {
        cls_out = out + main_sz;
        idx_out = out + main_sz + (size_t)Bsz * Dd;
    }

    // 0) convert x -> half; transpose weights -> half [N,K]
    {
        int n4 = (int)(main_sz / 4);
        f2h_kernel<<<(n4 + 255) / 256, 256>>>((const float4*)x, (uint2*)p_xh, n4);
        transpose_h<<<dim3(Dd / 32, Dd / 32), dim3(32, 8)>>>(Wq,   p_wqT,   Dd, Dd);
        transpose_h<<<dim3(2 * Dd / 32, Dd / 32), dim3(32, 8)>>>(Wctx, p_wctxT, Dd, 2 * Dd);
        transpose_h<<<dim3(Dd / 32, Dd / 32), dim3(32, 8)>>>(Wout, p_woutT, Dd, Dd);
    }

    // 1) cls / argmax (exact fp32)
    cls_kernel<<<Bsz, 256>>>(x, cent, cls_out, idx_out);

    // 2) gather (half) + xreg copy
    gather_qctx_kernel<<<4096, 256>>>(Qb);
    xreg_kernel<<<(Bsz * Rr * Dd / 2 + 255) / 256, 256>>>();

    // 3) scores = q_ctx @ xp^T (NT, batched, fp32 out)
    hgemm<true, false, false><<<dim3(Pp / 128, 1, Bsz), 256, SMEM_NT>>>(
        p_qctx, p_xh + (size_t)Rr * Dd, nullptr, p_scores,
        Kk, Pp, Dd, Dd, Dd, Pp,
        (long long)Kk * Dd, (long long)Nn * Dd, (long long)Kk * Pp);

    // 4) softmax -> half probs
    softmax_kernel<<<Bsz * Kk, 256>>>(p_scores, p_probs);

    // 5) ctx_p = probs @ xp (NN, batched, half out)
    hgemm<false, false, true><<<dim3(Dd / 128, 1, Bsz), 256, SMEM_NN>>>(
        p_probs, p_xh + (size_t)Rr * Dd, nullptr, p_ctx + (size_t)Rr * Dd,
        Kk, Dd, Pp, Pp, Dd, Dd,
        (long long)Kk * Pp, (long long)Nn * Dd, (long long)CTX * Dd);

    // 6) kv = ctx @ Wctx + bctx (NT via Wctx^T, half out)
    hgemm<true, true, true><<<dim3((2 * Dd) / 128, (Bsz * CTX + 127) / 128, 1), 256, SMEM_NT>>>(
        p_ctx, p_wctxT, bctx, p_kv,
        Bsz * CTX, 2 * Dd, Dd, Dd, Dd, 2 * Dd, 0, 0, 0);

    // 7) q = x @ Wq (NT via Wq^T, half out)
    hgemm<true, false, true><<<dim3(Dd / 128, (Bsz * Nn + 127) / 128, 1), 256, SMEM_NT>>>(
        p_xh, p_wqT, nullptr, p_q,
        Bsz * Nn, Dd, Dd, Dd, Dd, Dd, 0, 0, 0);

    // 8) fused fp16 attention -> y (half)
    attn_mma<<<dim3((Nn + 127) / 128, Bsz * Hh), 256, ATTN_SMEM>>>(p_y);

    // 9) out = y @ Wout + bout (NT via Wout^T, fp32 out)
    hgemm<true, true, false><<<dim3(Dd / 128, (Bsz * Nn + 127) / 128, 1), 256, SMEM_NT>>>(
        p_y, p_woutT, bout, out,
        Bsz * Nn, Dd, Dd, Dd, Dd, Dd, 0, 0, 0);
}

// round 7
// speedup vs baseline: 5.4258x; 1.1373x over previous
#include <cuda_runtime.h>
#include <cuda_fp16.h>
#include <math.h>
#include <stdint.h>

#define Bsz 64
#define Nn  1029
#define Dd  768
#define Hh  12
#define dh  64
#define Kk  128
#define Rr  5
#define Mm  4
#define Pp  1024          // N - R
#define CTX 133           // R + K

// ---------------- scratch (static device globals: allocation-free) ----------
__device__ int    g_idx[Bsz];
__device__ __half g_xh[(size_t)Bsz * Nn * Dd];
__device__ __half g_wqT[Dd * Dd];
__device__ __half g_wctxT[2 * Dd * Dd];
__device__ __half g_woutT[Dd * Dd];
__device__ __half g_qctx[(size_t)Bsz * Kk * Dd];
__device__ float  g_scores[(size_t)Bsz * Kk * Pp];
__device__ __half g_probs[(size_t)Bsz * Kk * Pp];
__device__ __half g_ctx[(size_t)Bsz * CTX * Dd];
__device__ __half g_kv[(size_t)Bsz * CTX * 2 * Dd];
__device__ __half g_q[(size_t)Bsz * Nn * Dd];
__device__ __half g_y[(size_t)Bsz * Nn * Dd];

// ---------------- helpers ----------------------------------------------------
__device__ __forceinline__ uint32_t pk2(float a, float b) {
    __half2 h = __floats2half2_rn(a, b);
    return *reinterpret_cast<uint32_t*>(&h);
}

__device__ __forceinline__ void mma_f16(float* c, const uint32_t* a, const uint32_t* b) {
    asm volatile(
        "mma.sync.aligned.m16n8k16.row.col.f32.f16.f16.f32 "
        "{%0,%1,%2,%3}, {%4,%5,%6,%7}, {%8,%9}, {%0,%1,%2,%3};\n"
        : "+f"(c[0]), "+f"(c[1]), "+f"(c[2]), "+f"(c[3])
        : "r"(a[0]), "r"(a[1]), "r"(a[2]), "r"(a[3]), "r"(b[0]), "r"(b[1]));
}

__device__ __forceinline__ void ldsm4(uint32_t& r0, uint32_t& r1, uint32_t& r2,
                                      uint32_t& r3, uint32_t a) {
    asm volatile("ldmatrix.sync.aligned.m8n8.x4.shared.b16 {%0,%1,%2,%3}, [%4];"
                 : "=r"(r0), "=r"(r1), "=r"(r2), "=r"(r3) : "r"(a));
}
__device__ __forceinline__ void ldsm4t(uint32_t& r0, uint32_t& r1, uint32_t& r2,
                                       uint32_t& r3, uint32_t a) {
    asm volatile("ldmatrix.sync.aligned.m8n8.x4.trans.shared.b16 {%0,%1,%2,%3}, [%4];"
                 : "=r"(r0), "=r"(r1), "=r"(r2), "=r"(r3) : "r"(a));
}

__device__ __forceinline__ void cp16(void* smem_dst, const void* gsrc, unsigned bytes) {
    unsigned saddr = (unsigned)__cvta_generic_to_shared(smem_dst);
    asm volatile("cp.async.cg.shared.global [%0], [%1], 16, %2;\n"
                 :: "r"(saddr), "l"(gsrc), "r"(bytes));
}
__device__ __forceinline__ void cp_commit() { asm volatile("cp.async.commit_group;\n"); }
template<int N> __device__ __forceinline__ void cp_wait() {
    asm volatile("cp.async.wait_group %0;\n" :: "n"(N));
}

// ---------------- conversion kernels ------------------------------------------
__global__ void f2h_kernel(const float4* __restrict__ src, uint2* __restrict__ dst, int n4)
{
    int i = blockIdx.x * blockDim.x + threadIdx.x;
    if (i < n4) {
        float4 v = src[i];
        uint2 o;
        o.x = pk2(v.x, v.y);
        o.y = pk2(v.z, v.w);
        dst[i] = o;
    }
}

__global__ void transpose_h(const float* __restrict__ src, __half* __restrict__ dst,
                            int K, int N)
{
    __shared__ float t[32][33];
    int k0 = blockIdx.y * 32, n0 = blockIdx.x * 32;
    int tx = threadIdx.x, ty = threadIdx.y;   // 32 x 8
    for (int i = ty; i < 32; i += 8)
        t[i][tx] = src[(size_t)(k0 + i) * N + n0 + tx];
    __syncthreads();
    for (int i = ty; i < 32; i += 8)
        dst[(size_t)(n0 + i) * K + k0 + tx] = __float2half_rn(t[tx][i]);
}

// ---------------- cls_n, sims, argmax (fp32 exact) ---------------------------
__global__ void cls_kernel(const float* __restrict__ x,
                           const float* __restrict__ cent,
                           float* __restrict__ cls_out,
                           float* __restrict__ idx_out)
{
    int b = blockIdx.x;
    int tid = threadIdx.x;
    __shared__ float xs[Dd];
    __shared__ float red[256];
    __shared__ float sims[Mm];
    __shared__ float inv_s;

    float ss = 0.f;
    for (int i = tid; i < Dd; i += 256) {
        float v = x[(size_t)b * Nn * Dd + i];
        xs[i] = v;
        ss += v * v;
    }
    red[tid] = ss; __syncthreads();
    for (int s = 128; s > 0; s >>= 1) { if (tid < s) red[tid] += red[tid + s]; __syncthreads(); }
    if (tid == 0) inv_s = 1.f / fmaxf(sqrtf(red[0]), 1e-12f);
    __syncthreads();
    float inv = inv_s;

    for (int m = 0; m < Mm; m++) {
        float p = 0.f;
        for (int i = tid; i < Dd; i += 256) p += xs[i] * cent[m * Dd + i];
        red[tid] = p; __syncthreads();
        for (int s = 128; s > 0; s >>= 1) { if (tid < s) red[tid] += red[tid + s]; __syncthreads(); }
        if (tid == 0) sims[m] = red[0] * inv;
        __syncthreads();
    }
    if (tid == 0) {
        int best = 0; float bv = sims[0];
        for (int m = 1; m < Mm; m++) if (sims[m] > bv) { bv = sims[m]; best = m; }
        g_idx[b] = best;
        if (idx_out) idx_out[b] = (float)best;
    }
    if (cls_out)
        for (int i = tid; i < Dd; i += 256)
            cls_out[(size_t)b * Dd + i] = xs[i] * inv;
}

// ---------------- gather Q_banks[idx] (half) + xreg --------------------------
__global__ void gather_qctx_kernel(const float* __restrict__ Qb)
{
    size_t total = (size_t)Bsz * Kk * Dd;
    for (size_t i = (size_t)blockIdx.x * blockDim.x + threadIdx.x; i < total;
         i += (size_t)gridDim.x * blockDim.x) {
        int b = (int)(i / ((size_t)Kk * Dd));
        size_t r = i - (size_t)b * Kk * Dd;
        g_qctx[i] = __float2half_rn(Qb[(size_t)g_idx[b] * Kk * Dd + r]);
    }
}

__global__ void xreg_kernel()
{
    int i = blockIdx.x * blockDim.x + threadIdx.x;       // u32 units
    const int total = Bsz * Rr * Dd / 2;
    if (i < total) {
        int b = i / (Rr * Dd / 2);
        int r = i - b * (Rr * Dd / 2);
        reinterpret_cast<uint32_t*>(g_ctx)[(size_t)b * CTX * Dd / 2 + r] =
            reinterpret_cast<const uint32_t*>(g_xh)[(size_t)b * Nn * Dd / 2 + r];
    }
}

// ---------------- fp16 tensor-core GEMM, 4-stage cp.async + ldmatrix --------
// C[M,N] = A[M,Kd] @ op(B) (+bias). op = B[Kd,N] (NN) or B[N,Kd]^T (NT).
// Block 128x128x32 halfs, 256 threads (8 warps 4x2), warp tile 32x64,
// mma m16n8k16 f16 -> f32. N%128==0, Kd%32==0, Kd>=96; M guarded.
template<bool TRANSB, bool BIAS, bool OUTHALF>
__global__ __launch_bounds__(256, 2)
void hgemm(const __half* __restrict__ A, const __half* __restrict__ Bm,
           const float* __restrict__ bias, void* __restrict__ Cv,
           int M, int N, int Kd, int lda, int ldb, int ldc,
           long long sA, long long sB, long long sC)
{
    extern __shared__ uint32_t smu[];
    const int ASTG = 128 * 20;                        // u32 per A stage (pitch 20 u32)
    const int BSTG = TRANSB ? 128 * 20 : 32 * 68;     // NN: [32 k][136 halfs]
    uint32_t* smA = smu;
    uint32_t* smB = smu + 4 * ASTG;
    const uint32_t sbA = (uint32_t)__cvta_generic_to_shared(smA);
    const uint32_t sbB = (uint32_t)__cvta_generic_to_shared(smB);

    const __half* Ab = A  + (long long)blockIdx.z * sA;
    const __half* Bb = Bm + (long long)blockIdx.z * sB;

    const int row0 = blockIdx.y * 128;
    const int col0 = blockIdx.x * 128;
    const int tid  = threadIdx.x;
    const int lane = tid & 31;
    const int warp = tid >> 5;
    const int wm = warp >> 1;
    const int wn = warp & 1;
    const int g   = lane >> 2;
    const int tig = lane & 3;

    const int lrow = ((lane >> 3) & 1) * 8 + (lane & 7);
    const int lk8  = (lane >> 4) * 8;
    uint32_t aoff[2], boff[4];
#pragma unroll
    for (int im = 0; im < 2; im++)
        aoff[im] = (uint32_t)(((wm * 32 + im * 16 + lrow) * 40 + lk8) * 2);
#pragma unroll
    for (int p = 0; p < 4; p++) {
        if (TRANSB)
            boff[p] = (uint32_t)(((wn * 64 + p * 16 + lrow) * 40 + lk8) * 2);
        else
            boff[p] = (uint32_t)(((((lane >> 4) & 1) * 8 + (lane & 7)) * 136
                                  + wn * 64 + p * 16 + ((lane >> 3) & 1) * 8) * 2);
    }

    float acc[2][8][4];
#pragma unroll
    for (int im = 0; im < 2; im++)
#pragma unroll
        for (int in = 0; in < 8; in++)
#pragma unroll
            for (int j = 0; j < 4; j++) acc[im][in][j] = 0.f;

    auto loadA = [&](int stg, int k0) {
        uint32_t* dst = smA + stg * ASTG;
#pragma unroll
        for (int it = 0; it < 2; it++) {
            int id = tid + it * 256;
            int r  = id >> 2;
            int c  = (id & 3) * 4;
            int gr = row0 + r;
            unsigned ok = (gr < M) ? 16u : 0u;
            const __half* src = Ab + (size_t)(gr < M ? gr : 0) * lda + k0 + c * 2;
            cp16(dst + r * 20 + c, src, ok);
        }
    };
    auto loadB = [&](int stg, int k0) {
        uint32_t* dst = smB + stg * BSTG;
#pragma unroll
        for (int it = 0; it < 2; it++) {
            int id = tid + it * 256;
            if (TRANSB) {
                int n = id >> 2;
                int c = (id & 3) * 4;
                cp16(dst + n * 20 + c, Bb + (size_t)(col0 + n) * ldb + k0 + c * 2, 16u);
            } else {
                int kr = id >> 4;
                int ch = id & 15;
                cp16(dst + kr * 68 + ch * 4, Bb + (size_t)(k0 + kr) * ldb + col0 + ch * 8, 16u);
            }
        }
    };

    loadA(0, 0);  loadB(0, 0);  cp_commit();
    loadA(1, 32); loadB(1, 32); cp_commit();
    loadA(2, 64); loadB(2, 64); cp_commit();

    const int nk = Kd >> 5;
    for (int i = 0; i < nk; i++) {
        int rem = nk - 1 - i;
        if (rem >= 2)      cp_wait<2>();
        else if (rem == 1) cp_wait<1>();
        else               cp_wait<0>();
        __syncthreads();
        if (i + 3 < nk) {
            int s4 = (i + 3) & 3;
            loadA(s4, (i + 3) * 32);
            loadB(s4, (i + 3) * 32);
            cp_commit();
        }

        const uint32_t baA = sbA + (uint32_t)((i & 3) * ASTG * 4);
        const uint32_t baB = sbB + (uint32_t)((i & 3) * BSTG * 4);

#pragma unroll
        for (int s = 0; s < 2; s++) {             // two k16 steps per 32-k block
            uint32_t afr[2][4], bfr[8][2];
#pragma unroll
            for (int im = 0; im < 2; im++)
                ldsm4(afr[im][0], afr[im][1], afr[im][2], afr[im][3],
                      baA + aoff[im] + s * 32);
#pragma unroll
            for (int p = 0; p < 4; p++) {
                if (TRANSB)
                    ldsm4(bfr[2 * p][0], bfr[2 * p + 1][0], bfr[2 * p][1], bfr[2 * p + 1][1],
                          baB + boff[p] + s * 32);
                else
                    ldsm4t(bfr[2 * p][0], bfr[2 * p + 1][0], bfr[2 * p][1], bfr[2 * p + 1][1],
                           baB + boff[p] + s * 4352);
            }
#pragma unroll
            for (int im = 0; im < 2; im++)
#pragma unroll
                for (int in = 0; in < 8; in++)
                    mma_f16(acc[im][in], afr[im], bfr[in]);
        }
        // no trailing __syncthreads: next iteration's leading barrier protects
        // the stage ring (writes at iter i target stage (i+3)&3 == (i-1)&3,
        // whose readers all passed this iteration's leading barrier).
    }

    // ---- epilogue ----------------------------------------------------------
#pragma unroll
    for (int im = 0; im < 2; im++) {
        int rb = row0 + wm * 32 + im * 16 + g;
#pragma unroll
        for (int in = 0; in < 8; in++) {
            int cb = col0 + wn * 64 + in * 8 + 2 * tig;
            float b0 = BIAS ? bias[cb] : 0.f;
            float b1 = BIAS ? bias[cb + 1] : 0.f;
            float v0 = acc[im][in][0] + b0, v1 = acc[im][in][1] + b1;
            float v2 = acc[im][in][2] + b0, v3 = acc[im][in][3] + b1;
            if (OUTHALF) {
                __half* C = (__half*)Cv + (long long)blockIdx.z * sC;
                if (rb < M)
                    *reinterpret_cast<uint32_t*>(&C[(size_t)rb * ldc + cb]) = pk2(v0, v1);
                if (rb + 8 < M)
                    *reinterpret_cast<uint32_t*>(&C[(size_t)(rb + 8) * ldc + cb]) = pk2(v2, v3);
            } else {
                float* C = (float*)Cv + (long long)blockIdx.z * sC;
                if (rb < M)
                    *reinterpret_cast<float2*>(&C[(size_t)rb * ldc + cb]) = make_float2(v0, v1);
                if (rb + 8 < M)
                    *reinterpret_cast<float2*>(&C[(size_t)(rb + 8) * ldc + cb]) = make_float2(v2, v3);
            }
        }
    }
}

// ---------------- row softmax over P=1024: fp32 in, half out ------------------
__global__ void softmax_kernel(const float* __restrict__ s, __half* __restrict__ pr)
{
    int row = blockIdx.x;
    const float4* p4 = reinterpret_cast<const float4*>(s + (size_t)row * Pp);
    uint32_t* o2 = reinterpret_cast<uint32_t*>(pr + (size_t)row * Pp);
    int tid = threadIdx.x;
    __shared__ float red[256];

    float4 v = p4[tid];
    float mx = fmaxf(fmaxf(v.x, v.y), fmaxf(v.z, v.w));
    red[tid] = mx; __syncthreads();
    for (int st = 128; st > 0; st >>= 1) { if (tid < st) red[tid] = fmaxf(red[tid], red[tid + st]); __syncthreads(); }
    mx = red[0]; __syncthreads();

    v.x = __expf(v.x - mx); v.y = __expf(v.y - mx);
    v.z = __expf(v.z - mx); v.w = __expf(v.w - mx);
    float sm = v.x + v.y + v.z + v.w;
    red[tid] = sm; __syncthreads();
    for (int st = 128; st > 0; st >>= 1) { if (tid < st) red[tid] += red[tid + st]; __syncthreads(); }
    float inv = 1.f / red[0];
    o2[2 * tid]     = pk2(v.x * inv, v.y * inv);
    o2[2 * tid + 1] = pk2(v.z * inv, v.w * inv);
}

// ---------------- fp16 tensor-core fused attention (ldmatrix) -----------------
// grid (9, B*H), 256 threads (8 warps x 16 query rows). Keys padded to 144.
// V loaded K-major like K; phase-2 B fragments via ldmatrix.trans (no manual
// transpose).
__global__ __launch_bounds__(256)
void attn_mma(__half* __restrict__ y)
{
    extern __shared__ uint32_t smu[];
    uint32_t* Qs = smu;                    // [128][36] u32  (72-half pitch)
    uint32_t* Ks = smu + 128 * 36;         // [144][36]
    uint32_t* Vs = Ks + 144 * 36;          // [144][36]  (rows = keys, cols = d)
    uint32_t* Ps = Vs + 144 * 36;          // [128][76] u32  (152-half pitch)
    const uint32_t sQ = (uint32_t)__cvta_generic_to_shared(Qs);
    const uint32_t sK = (uint32_t)__cvta_generic_to_shared(Ks);
    const uint32_t sV = (uint32_t)__cvta_generic_to_shared(Vs);
    const uint32_t sP = (uint32_t)__cvta_generic_to_shared(Ps);

    const int bh = blockIdx.y;
    const int b = bh / Hh, h = bh % Hh;
    const int n0 = blockIdx.x * 128;
    const int tid = threadIdx.x;
    const int lane = tid & 31;
    const int w = tid >> 5;
    const int g = lane >> 2;
    const int tig = lane & 3;
    const int rbase = w * 16;

    const int lrow = ((lane >> 3) & 1) * 8 + (lane & 7);
    const int lk8  = (lane >> 4) * 8;

    // ---- Q tile 128x64 halfs -------------------------------------------------
#pragma unroll
    for (int it = 0; it < 4; it++) {
        int id = tid + it * 256;
        int r  = id >> 3;
        int ch = id & 7;
        int n  = n0 + r;
        unsigned ok = (n < Nn) ? 16u : 0u;
        const __half* src = g_q + ((size_t)b * Nn + (n < Nn ? n : 0)) * Dd + h * dh + ch * 8;
        cp16(Qs + r * 36 + ch * 4, src, ok);
    }
    // ---- K and V tiles 144x64 halfs (rows >= CTX zero-filled) ------------------
#pragma unroll
    for (int it = 0; it < 9; it++) {
        int id = tid + it * 256;           // 0..2303 need 144*8*2 = 2304
        int half = id & 1;                 // 0 = K, 1 = V
        int key  = (id >> 1) >> 3;         // 0..143
        int ch   = (id >> 1) & 7;
        unsigned ok = (key < CTX) ? 16u : 0u;
        const __half* src = g_kv + ((size_t)b * CTX + (key < CTX ? key : 0)) * (2 * Dd)
                          + half * Dd + h * dh + ch * 8;
        uint32_t* dst = (half ? Vs : Ks) + key * 36 + ch * 4;
        cp16(dst, src, ok);
    }
    cp_commit();
    cp_wait<0>();
    __syncthreads();

    // ---- phase 1: S = Q K^T (4 k-steps of 16 over d=64) -----------------------
    uint32_t afr[4][4];
#pragma unroll
    for (int ks = 0; ks < 4; ks++)
        ldsm4(afr[ks][0], afr[ks][1], afr[ks][2], afr[ks][3],
              sQ + (uint32_t)((((rbase + lrow) * 72 + lk8) * 2) + ks * 32));

    float sacc[18][4];
#pragma unroll
    for (int nt = 0; nt < 18; nt++)
#pragma unroll
        for (int j = 0; j < 4; j++) sacc[nt][j] = 0.f;

    const uint32_t koff = sK + (uint32_t)((lrow * 72 + lk8) * 2);
#pragma unroll
    for (int ntp = 0; ntp < 9; ntp++) {
#pragma unroll
        for (int ks = 0; ks < 4; ks++) {
            uint32_t bfr[2][2];
            ldsm4(bfr[0][0], bfr[1][0], bfr[0][1], bfr[1][1],
                  koff + (uint32_t)(ntp * 2304 + ks * 32));
            mma_f16(sacc[2 * ntp],     afr[ks], bfr[0]);
            mma_f16(sacc[2 * ntp + 1], afr[ks], bfr[1]);
        }
    }

    // ---- exact softmax over 133 keys (pad cols -> 0) ---------------------------
    const float scale = 0.125f;
    float mlo = -1e30f, mhi = -1e30f;
#pragma unroll
    for (int nt = 0; nt < 18; nt++) {
        int c0 = nt * 8 + 2 * tig;
        float s0 = (c0     < CTX) ? sacc[nt][0] * scale : -1e30f;
        float s1 = (c0 + 1 < CTX) ? sacc[nt][1] * scale : -1e30f;
        float s2 = (c0     < CTX) ? sacc[nt][2] * scale : -1e30f;
        float s3 = (c0 + 1 < CTX) ? sacc[nt][3] * scale : -1e30f;
        sacc[nt][0] = s0; sacc[nt][1] = s1; sacc[nt][2] = s2; sacc[nt][3] = s3;
        mlo = fmaxf(mlo, fmaxf(s0, s1));
        mhi = fmaxf(mhi, fmaxf(s2, s3));
    }
    mlo = fmaxf(mlo, __shfl_xor_sync(0xffffffffu, mlo, 1));
    mlo = fmaxf(mlo, __shfl_xor_sync(0xffffffffu, mlo, 2));
    mhi = fmaxf(mhi, __shfl_xor_sync(0xffffffffu, mhi, 1));
    mhi = fmaxf(mhi, __shfl_xor_sync(0xffffffffu, mhi, 2));

    float llo = 0.f, lhi = 0.f;
#pragma unroll
    for (int nt = 0; nt < 18; nt++) {
        float p0 = __expf(sacc[nt][0] - mlo);
        float p1 = __expf(sacc[nt][1] - mlo);
        float p2 = __expf(sacc[nt][2] - mhi);
        float p3 = __expf(sacc[nt][3] - mhi);
        llo += p0 + p1; lhi += p2 + p3;
        sacc[nt][0] = p0; sacc[nt][1] = p1; sacc[nt][2] = p2; sacc[nt][3] = p3;
    }
    llo += __shfl_xor_sync(0xffffffffu, llo, 1);
    llo += __shfl_xor_sync(0xffffffffu, llo, 2);
    lhi += __shfl_xor_sync(0xffffffffu, lhi, 1);
    lhi += __shfl_xor_sync(0xffffffffu, lhi, 2);

    // ---- P -> smem (half pairs, 144 cols; pads are exp(-inf)=0) ----------------
#pragma unroll
    for (int nt = 0; nt < 18; nt++) {
        Ps[(rbase + g) * 76 + nt * 4 + tig]     = pk2(sacc[nt][0], sacc[nt][1]);
        Ps[(rbase + g + 8) * 76 + nt * 4 + tig] = pk2(sacc[nt][2], sacc[nt][3]);
    }
    __syncwarp();

    // ---- phase 2: O = P V (9 k-steps of 16 over 144 keys, V via ldsm.trans) ----
    float oacc[8][4];
#pragma unroll
    for (int nt = 0; nt < 8; nt++)
#pragma unroll
        for (int j = 0; j < 4; j++) oacc[nt][j] = 0.f;

    const uint32_t poff = sP + (uint32_t)(((rbase + lrow) * 152 + lk8) * 2);
    const uint32_t voff = sV + (uint32_t)(((((lane >> 4) & 1) * 8 + (lane & 7)) * 72
                                           + ((lane >> 3) & 1) * 8) * 2);
#pragma unroll
    for (int ks = 0; ks < 9; ks++) {
        uint32_t a2[4];
        ldsm4(a2[0], a2[1], a2[2], a2[3], poff + (uint32_t)(ks * 32));
#pragma unroll
        for (int ntp = 0; ntp < 4; ntp++) {
            uint32_t bfr[2][2];
            ldsm4t(bfr[0][0], bfr[1][0], bfr[0][1], bfr[1][1],
                   voff + (uint32_t)(ks * 2304 + ntp * 32));
            mma_f16(oacc[2 * ntp],     a2, bfr[0]);
            mma_f16(oacc[2 * ntp + 1], a2, bfr[1]);
        }
    }

    // ---- output y (half) -------------------------------------------------------
    float invlo = 1.f / llo, invhi = 1.f / lhi;
    int row_lo = n0 + rbase + g;
    int row_hi = row_lo + 8;
#pragma unroll
    for (int nt = 0; nt < 8; nt++) {
        int col = h * dh + nt * 8 + 2 * tig;
        if (row_lo < Nn)
            *reinterpret_cast<uint32_t*>(&y[((size_t)b * Nn + row_lo) * Dd + col]) =
                pk2(oacc[nt][0] * invlo, oacc[nt][1] * invlo);
        if (row_hi < Nn)
            *reinterpret_cast<uint32_t*>(&y[((size_t)b * Nn + row_hi) * Dd + col]) =
                pk2(oacc[nt][2] * invhi, oacc[nt][3] * invhi);
    }
}

// ---------------- launch -----------------------------------------------------
extern "C" void kernel_launch(void* const* d_in, const int* in_sizes, int n_in,
                              void* d_out, int out_size)
{
    const float* x    = (const float*)d_in[0];
    const float* Qb   = (const float*)d_in[1];
    const float* Wq   = (const float*)d_in[2];
    const float* Wctx = (const float*)d_in[3];
    const float* bctx = (const float*)d_in[4];
    const float* Wout = (const float*)d_in[5];
    const float* bout = (const float*)d_in[6];
    const float* cent = (const float*)d_in[7];
    float* out = (float*)d_out;

    __half *p_xh, *p_wqT, *p_wctxT, *p_woutT, *p_qctx, *p_probs, *p_ctx, *p_kv, *p_q, *p_y;
    float *p_scores;
    cudaGetSymbolAddress((void**)&p_xh,     g_xh);
    cudaGetSymbolAddress((void**)&p_wqT,    g_wqT);
    cudaGetSymbolAddress((void**)&p_wctxT,  g_wctxT);
    cudaGetSymbolAddress((void**)&p_woutT,  g_woutT);
    cudaGetSymbolAddress((void**)&p_qctx,   g_qctx);
    cudaGetSymbolAddress((void**)&p_scores, g_scores);
    cudaGetSymbolAddress((void**)&p_probs,  g_probs);
    cudaGetSymbolAddress((void**)&p_ctx,    g_ctx);
    cudaGetSymbolAddress((void**)&p_kv,     g_kv);
    cudaGetSymbolAddress((void**)&p_q,      g_q);
    cudaGetSymbolAddress((void**)&p_y,      g_y);

    const int SMEM_NT  = (4 * 128 * 20 + 4 * 128 * 20) * 4;   // 81920
    const int SMEM_NN  = (4 * 128 * 20 + 4 * 32 * 68) * 4;    // 75776
    const int ATTN_SMEM = (128 * 36 + 144 * 36 + 144 * 36 + 128 * 76) * 4;  // 98816
    cudaFuncSetAttribute((const void*)hgemm<true,  false, false>, cudaFuncAttributeMaxDynamicSharedMemorySize, SMEM_NT);
    cudaFuncSetAttribute((const void*)hgemm<true,  false, true >, cudaFuncAttributeMaxDynamicSharedMemorySize, SMEM_NT);
    cudaFuncSetAttribute((const void*)hgemm<true,  true,  true >, cudaFuncAttributeMaxDynamicSharedMemorySize, SMEM_NT);
    cudaFuncSetAttribute((const void*)hgemm<true,  true,  false>, cudaFuncAttributeMaxDynamicSharedMemorySize, SMEM_NT);
    cudaFuncSetAttribute((const void*)hgemm<false, false, true >, cudaFuncAttributeMaxDynamicSharedMemorySize, SMEM_NN);
    cudaFuncSetAttribute((const void*)attn_mma, cudaFuncAttributeMaxDynamicSharedMemorySize, ATTN_SMEM);

    const size_t main_sz = (size_t)Bsz * Nn * Dd;
    float* cls_out = nullptr;
    float* idx_out = nullptr;
    if ((size_t)out_size >= main_sz + (size_t)Bsz * Dd + Bsz) {
        cls_out = out + main_sz;
        idx_out = out + main_sz + (size_t)Bsz * Dd;
    }

    // 0) convert x -> half; transpose weights -> half [N,K]
    {
        int n4 = (int)(main_sz / 4);
        f2h_kernel<<<(n4 + 255) / 256, 256>>>((const float4*)x, (uint2*)p_xh, n4);
        transpose_h<<<dim3(Dd / 32, Dd / 32), dim3(32, 8)>>>(Wq,   p_wqT,   Dd, Dd);
        transpose_h<<<dim3(2 * Dd / 32, Dd / 32), dim3(32, 8)>>>(Wctx, p_wctxT, Dd, 2 * Dd);
        transpose_h<<<dim3(Dd / 32, Dd / 32), dim3(32, 8)>>>(Wout, p_woutT, Dd, Dd);
    }

    // 1) cls / argmax (exact fp32)
    cls_kernel<<<Bsz, 256>>>(x, cent, cls_out, idx_out);

    // 2) gather (half) + xreg copy
    gather_qctx_kernel<<<4096, 256>>>(Qb);
    xreg_kernel<<<(Bsz * Rr * Dd / 2 + 255) / 256, 256>>>();

    // 3) scores = q_ctx @ xp^T (NT, batched, fp32 out)
    hgemm<true, false, false><<<dim3(Pp / 128, 1, Bsz), 256, SMEM_NT>>>(
        p_qctx, p_xh + (size_t)Rr * Dd, nullptr, p_scores,
        Kk, Pp, Dd, Dd, Dd, Pp,
        (long long)Kk * Dd, (long long)Nn * Dd, (long long)Kk * Pp);

    // 4) softmax -> half probs
    softmax_kernel<<<Bsz * Kk, 256>>>(p_scores, p_probs);

    // 5) ctx_p = probs @ xp (NN, batched, half out)
    hgemm<false, false, true><<<dim3(Dd / 128, 1, Bsz), 256, SMEM_NN>>>(
        p_probs, p_xh + (size_t)Rr * Dd, nullptr, p_ctx + (size_t)Rr * Dd,
        Kk, Dd, Pp, Pp, Dd, Dd,
        (long long)Kk * Pp, (long long)Nn * Dd, (long long)CTX * Dd);

    // 6) kv = ctx @ Wctx + bctx (NT via Wctx^T, half out)
    hgemm<true, true, true><<<dim3((2 * Dd) / 128, (Bsz * CTX + 127) / 128, 1), 256, SMEM_NT>>>(
        p_ctx, p_wctxT, bctx, p_kv,
        Bsz * CTX, 2 * Dd, Dd, Dd, Dd, 2 * Dd, 0, 0, 0);

    // 7) q = x @ Wq (NT via Wq^T, half out)
    hgemm<true, false, true><<<dim3(Dd / 128, (Bsz * Nn + 127) / 128, 1), 256, SMEM_NT>>>(
        p_xh, p_wqT, nullptr, p_q,
        Bsz * Nn, Dd, Dd, Dd, Dd, Dd, 0, 0, 0);

    // 8) fused fp16 attention -> y (half)
    attn_mma<<<dim3((Nn + 127) / 128, Bsz * Hh), 256, ATTN_SMEM>>>(p_y);

    // 9) out = y @ Wout + bout (NT via Wout^T, fp32 out)
    hgemm<true, true, false><<<dim3(Dd / 128, (Bsz * Nn + 127) / 128, 1), 256, SMEM_NT>>>(
        p_y, p_woutT, bout, out,
        Bsz * Nn, Dd, Dd, Dd, Dd, Dd, 0, 0, 0);
}

// round 8
// speedup vs baseline: 5.5591x; 1.0246x over previous
#include <cuda_runtime.h>
#include <cuda_fp16.h>
#include <math.h>
#include <stdint.h>

#define Bsz 64
#define Nn  1029
#define Dd  768
#define Hh  12
#define dh  64
#define Kk  128
#define Rr  5
#define Mm  4
#define Pp  1024          // N - R
#define CTX 133           // R + K

// ---------------- scratch (static device globals: allocation-free) ----------
__device__ int    g_idx[Bsz];
__device__ __half g_xh[(size_t)Bsz * Nn * Dd];
__device__ __half g_wqT[Dd * Dd];
__device__ __half g_wctxT[2 * Dd * Dd];
__device__ __half g_woutT[Dd * Dd];
__device__ __half g_qctx[(size_t)Bsz * Kk * Dd];
__device__ __half g_probs[(size_t)Bsz * Kk * Pp];   // scores (half) -> softmax in-place
__device__ __half g_ctx[(size_t)Bsz * CTX * Dd];
__device__ __half g_kv[(size_t)Bsz * CTX * 2 * Dd];
__device__ __half g_q[(size_t)Bsz * Nn * Dd];
__device__ __half g_y[(size_t)Bsz * Nn * Dd];

// ---------------- helpers ----------------------------------------------------
__device__ __forceinline__ uint32_t pk2(float a, float b) {
    __half2 h = __floats2half2_rn(a, b);
    return *reinterpret_cast<uint32_t*>(&h);
}

__device__ __forceinline__ void mma_f16(float* c, const uint32_t* a, const uint32_t* b) {
    asm volatile(
        "mma.sync.aligned.m16n8k16.row.col.f32.f16.f16.f32 "
        "{%0,%1,%2,%3}, {%4,%5,%6,%7}, {%8,%9}, {%0,%1,%2,%3};\n"
        : "+f"(c[0]), "+f"(c[1]), "+f"(c[2]), "+f"(c[3])
        : "r"(a[0]), "r"(a[1]), "r"(a[2]), "r"(a[3]), "r"(b[0]), "r"(b[1]));
}

__device__ __forceinline__ void ldsm4(uint32_t& r0, uint32_t& r1, uint32_t& r2,
                                      uint32_t& r3, uint32_t a) {
    asm volatile("ldmatrix.sync.aligned.m8n8.x4.shared.b16 {%0,%1,%2,%3}, [%4];"
                 : "=r"(r0), "=r"(r1), "=r"(r2), "=r"(r3) : "r"(a));
}
__device__ __forceinline__ void ldsm4t(uint32_t& r0, uint32_t& r1, uint32_t& r2,
                                       uint32_t& r3, uint32_t a) {
    asm volatile("ldmatrix.sync.aligned.m8n8.x4.trans.shared.b16 {%0,%1,%2,%3}, [%4];"
                 : "=r"(r0), "=r"(r1), "=r"(r2), "=r"(r3) : "r"(a));
}

__device__ __forceinline__ void cp16(void* smem_dst, const void* gsrc, unsigned bytes) {
    unsigned saddr = (unsigned)__cvta_generic_to_shared(smem_dst);
    asm volatile("cp.async.cg.shared.global [%0], [%1], 16, %2;\n"
                 :: "r"(saddr), "l"(gsrc), "r"(bytes));
}
__device__ __forceinline__ void cp_commit() { asm volatile("cp.async.commit_group;\n"); }
template<int N> __device__ __forceinline__ void cp_wait() {
    asm volatile("cp.async.wait_group %0;\n" :: "n"(N));
}

// ---------------- conversion kernels ------------------------------------------
__global__ void f2h_kernel(const float4* __restrict__ src, uint2* __restrict__ dst, int n4)
{
    int i = blockIdx.x * blockDim.x + threadIdx.x;
    if (i < n4) {
        float4 v = src[i];
        uint2 o;
        o.x = pk2(v.x, v.y);
        o.y = pk2(v.z, v.w);
        dst[i] = o;
    }
}

__global__ void transpose_h(const float* __restrict__ src, __half* __restrict__ dst,
                            int K, int N)
{
    __shared__ float t[32][33];
    int k0 = blockIdx.y * 32, n0 = blockIdx.x * 32;
    int tx = threadIdx.x, ty = threadIdx.y;   // 32 x 8
    for (int i = ty; i < 32; i += 8)
        t[i][tx] = src[(size_t)(k0 + i) * N + n0 + tx];
    __syncthreads();
    for (int i = ty; i < 32; i += 8)
        dst[(size_t)(n0 + i) * K + k0 + tx] = __float2half_rn(t[tx][i]);
}

// ---------------- cls_n, sims, argmax (fp32 exact) ---------------------------
__global__ void cls_kernel(const float* __restrict__ x,
                           const float* __restrict__ cent,
                           float* __restrict__ cls_out,
                           float* __restrict__ idx_out)
{
    int b = blockIdx.x;
    int tid = threadIdx.x;
    __shared__ float xs[Dd];
    __shared__ float red[256];
    __shared__ float sims[Mm];
    __shared__ float inv_s;

    float ss = 0.f;
    for (int i = tid; i < Dd; i += 256) {
        float v = x[(size_t)b * Nn * Dd + i];
        xs[i] = v;
        ss += v * v;
    }
    red[tid] = ss; __syncthreads();
    for (int s = 128; s > 0; s >>= 1) { if (tid < s) red[tid] += red[tid + s]; __syncthreads(); }
    if (tid == 0) inv_s = 1.f / fmaxf(sqrtf(red[0]), 1e-12f);
    __syncthreads();
    float inv = inv_s;

    for (int m = 0; m < Mm; m++) {
        float p = 0.f;
        for (int i = tid; i < Dd; i += 256) p += xs[i] * cent[m * Dd + i];
        red[tid] = p; __syncthreads();
        for (int s = 128; s > 0; s >>= 1) { if (tid < s) red[tid] += red[tid + s]; __syncthreads(); }
        if (tid == 0) sims[m] = red[0] * inv;
        __syncthreads();
    }
    if (tid == 0) {
        int best = 0; float bv = sims[0];
        for (int m = 1; m < Mm; m++) if (sims[m] > bv) { bv = sims[m]; best = m; }
        g_idx[b] = best;
        if (idx_out) idx_out[b] = (float)best;
    }
    if (cls_out)
        for (int i = tid; i < Dd; i += 256)
            cls_out[(size_t)b * Dd + i] = xs[i] * inv;
}

// ---------------- gather Q_banks[idx] (half) + xreg --------------------------
__global__ void gather_qctx_kernel(const float* __restrict__ Qb)
{
    size_t total = (size_t)Bsz * Kk * Dd;
    for (size_t i = (size_t)blockIdx.x * blockDim.x + threadIdx.x; i < total;
         i += (size_t)gridDim.x * blockDim.x) {
        int b = (int)(i / ((size_t)Kk * Dd));
        size_t r = i - (size_t)b * Kk * Dd;
        g_qctx[i] = __float2half_rn(Qb[(size_t)g_idx[b] * Kk * Dd + r]);
    }
}

__global__ void xreg_kernel()
{
    int i = blockIdx.x * blockDim.x + threadIdx.x;       // u32 units
    const int total = Bsz * Rr * Dd / 2;
    if (i < total) {
        int b = i / (Rr * Dd / 2);
        int r = i - b * (Rr * Dd / 2);
        reinterpret_cast<uint32_t*>(g_ctx)[(size_t)b * CTX * Dd / 2 + r] =
            reinterpret_cast<const uint32_t*>(g_xh)[(size_t)b * Nn * Dd / 2 + r];
    }
}

// ---------------- fp16 tensor-core GEMM, 4-stage cp.async + ldmatrix --------
template<bool TRANSB, bool BIAS, bool OUTHALF>
__global__ __launch_bounds__(256, 2)
void hgemm(const __half* __restrict__ A, const __half* __restrict__ Bm,
           const float* __restrict__ bias, void* __restrict__ Cv,
           int M, int N, int Kd, int lda, int ldb, int ldc,
           long long sA, long long sB, long long sC)
{
    extern __shared__ uint32_t smu[];
    const int ASTG = 128 * 20;
    const int BSTG = TRANSB ? 128 * 20 : 32 * 68;
    uint32_t* smA = smu;
    uint32_t* smB = smu + 4 * ASTG;
    const uint32_t sbA = (uint32_t)__cvta_generic_to_shared(smA);
    const uint32_t sbB = (uint32_t)__cvta_generic_to_shared(smB);

    const __half* Ab = A  + (long long)blockIdx.z * sA;
    const __half* Bb = Bm + (long long)blockIdx.z * sB;

    const int row0 = blockIdx.y * 128;
    const int col0 = blockIdx.x * 128;
    const int tid  = threadIdx.x;
    const int lane = tid & 31;
    const int warp = tid >> 5;
    const int wm = warp >> 1;
    const int wn = warp & 1;
    const int g   = lane >> 2;
    const int tig = lane & 3;

    const int lrow = ((lane >> 3) & 1) * 8 + (lane & 7);
    const int lk8  = (lane >> 4) * 8;
    uint32_t aoff[2], boff[4];
#pragma unroll
    for (int im = 0; im < 2; im++)
        aoff[im] = (uint32_t)(((wm * 32 + im * 16 + lrow) * 40 + lk8) * 2);
#pragma unroll
    for (int p = 0; p < 4; p++) {
        if (TRANSB)
            boff[p] = (uint32_t)(((wn * 64 + p * 16 + lrow) * 40 + lk8) * 2);
        else
            boff[p] = (uint32_t)(((((lane >> 4) & 1) * 8 + (lane & 7)) * 136
                                  + wn * 64 + p * 16 + ((lane >> 3) & 1) * 8) * 2);
    }

    float acc[2][8][4];
#pragma unroll
    for (int im = 0; im < 2; im++)
#pragma unroll
        for (int in = 0; in < 8; in++)
#pragma unroll
            for (int j = 0; j < 4; j++) acc[im][in][j] = 0.f;

    auto loadA = [&](int stg, int k0) {
        uint32_t* dst = smA + stg * ASTG;
#pragma unroll
        for (int it = 0; it < 2; it++) {
            int id = tid + it * 256;
            int r  = id >> 2;
            int c  = (id & 3) * 4;
            int gr = row0 + r;
            unsigned ok = (gr < M) ? 16u : 0u;
            const __half* src = Ab + (size_t)(gr < M ? gr : 0) * lda + k0 + c * 2;
            cp16(dst + r * 20 + c, src, ok);
        }
    };
    auto loadB = [&](int stg, int k0) {
        uint32_t* dst = smB + stg * BSTG;
#pragma unroll
        for (int it = 0; it < 2; it++) {
            int id = tid + it * 256;
            if (TRANSB) {
                int n = id >> 2;
                int c = (id & 3) * 4;
                cp16(dst + n * 20 + c, Bb + (size_t)(col0 + n) * ldb + k0 + c * 2, 16u);
            } else {
                int kr = id >> 4;
                int ch = id & 15;
                cp16(dst + kr * 68 + ch * 4, Bb + (size_t)(k0 + kr) * ldb + col0 + ch * 8, 16u);
            }
        }
    };

    loadA(0, 0);  loadB(0, 0);  cp_commit();
    loadA(1, 32); loadB(1, 32); cp_commit();
    loadA(2, 64); loadB(2, 64); cp_commit();

    const int nk = Kd >> 5;
    for (int i = 0; i < nk; i++) {
        int rem = nk - 1 - i;
        if (rem >= 2)      cp_wait<2>();
        else if (rem == 1) cp_wait<1>();
        else               cp_wait<0>();
        __syncthreads();
        if (i + 3 < nk) {
            int s4 = (i + 3) & 3;
            loadA(s4, (i + 3) * 32);
            loadB(s4, (i + 3) * 32);
            cp_commit();
        }

        const uint32_t baA = sbA + (uint32_t)((i & 3) * ASTG * 4);
        const uint32_t baB = sbB + (uint32_t)((i & 3) * BSTG * 4);

#pragma unroll
        for (int s = 0; s < 2; s++) {
            uint32_t afr[2][4], bfr[8][2];
#pragma unroll
            for (int im = 0; im < 2; im++)
                ldsm4(afr[im][0], afr[im][1], afr[im][2], afr[im][3],
                      baA + aoff[im] + s * 32);
#pragma unroll
            for (int p = 0; p < 4; p++) {
                if (TRANSB)
                    ldsm4(bfr[2 * p][0], bfr[2 * p + 1][0], bfr[2 * p][1], bfr[2 * p + 1][1],
                          baB + boff[p] + s * 32);
                else
                    ldsm4t(bfr[2 * p][0], bfr[2 * p + 1][0], bfr[2 * p][1], bfr[2 * p + 1][1],
                           baB + boff[p] + s * 4352);
            }
#pragma unroll
            for (int im = 0; im < 2; im++)
#pragma unroll
                for (int in = 0; in < 8; in++)
                    mma_f16(acc[im][in], afr[im], bfr[in]);
        }
        // trailing barrier elided: next iteration's leading barrier protects the ring
    }

#pragma unroll
    for (int im = 0; im < 2; im++) {
        int rb = row0 + wm * 32 + im * 16 + g;
#pragma unroll
        for (int in = 0; in < 8; in++) {
            int cb = col0 + wn * 64 + in * 8 + 2 * tig;
            float b0 = BIAS ? bias[cb] : 0.f;
            float b1 = BIAS ? bias[cb + 1] : 0.f;
            float v0 = acc[im][in][0] + b0, v1 = acc[im][in][1] + b1;
            float v2 = acc[im][in][2] + b0, v3 = acc[im][in][3] + b1;
            if (OUTHALF) {
                __half* C = (__half*)Cv + (long long)blockIdx.z * sC;
                if (rb < M)
                    *reinterpret_cast<uint32_t*>(&C[(size_t)rb * ldc + cb]) = pk2(v0, v1);
                if (rb + 8 < M)
                    *reinterpret_cast<uint32_t*>(&C[(size_t)(rb + 8) * ldc + cb]) = pk2(v2, v3);
            } else {
                float* C = (float*)Cv + (long long)blockIdx.z * sC;
                if (rb < M)
                    *reinterpret_cast<float2*>(&C[(size_t)rb * ldc + cb]) = make_float2(v0, v1);
                if (rb + 8 < M)
                    *reinterpret_cast<float2*>(&C[(size_t)(rb + 8) * ldc + cb]) = make_float2(v2, v3);
            }
        }
    }
}

// ---------------- row softmax over P=1024: half in-place ----------------------
__global__ void softmax_kernel(__half* __restrict__ pr)
{
    int row = blockIdx.x;
    uint2* p2 = reinterpret_cast<uint2*>(pr + (size_t)row * Pp);
    int tid = threadIdx.x;
    __shared__ float red[256];

    uint2 u = p2[tid];
    __half2 h0 = *reinterpret_cast<__half2*>(&u.x);
    __half2 h1 = *reinterpret_cast<__half2*>(&u.y);
    float vx = __low2float(h0), vy = __high2float(h0);
    float vz = __low2float(h1), vw = __high2float(h1);

    float mx = fmaxf(fmaxf(vx, vy), fmaxf(vz, vw));
    red[tid] = mx; __syncthreads();
    for (int st = 128; st > 0; st >>= 1) { if (tid < st) red[tid] = fmaxf(red[tid], red[tid + st]); __syncthreads(); }
    mx = red[0]; __syncthreads();

    vx = __expf(vx - mx); vy = __expf(vy - mx);
    vz = __expf(vz - mx); vw = __expf(vw - mx);
    float sm = vx + vy + vz + vw;
    red[tid] = sm; __syncthreads();
    for (int st = 128; st > 0; st >>= 1) { if (tid < st) red[tid] += red[tid + st]; __syncthreads(); }
    float inv = 1.f / red[0];
    uint2 o;
    o.x = pk2(vx * inv, vy * inv);
    o.y = pk2(vz * inv, vw * inv);
    p2[tid] = o;
}

// ---------------- fp16 tensor-core fused attention (ldmatrix) -----------------
__global__ __launch_bounds__(256)
void attn_mma(__half* __restrict__ y)
{
    extern __shared__ uint32_t smu[];
    uint32_t* Qs = smu;                    // [128][36] u32  (72-half pitch)
    uint32_t* Ks = smu + 128 * 36;         // [144][36]
    uint32_t* Vs = Ks + 144 * 36;          // [144][36]
    uint32_t* Ps = Vs + 144 * 36;          // [128][76] u32  (152-half pitch)
    const uint32_t sQ = (uint32_t)__cvta_generic_to_shared(Qs);
    const uint32_t sK = (uint32_t)__cvta_generic_to_shared(Ks);
    const uint32_t sV = (uint32_t)__cvta_generic_to_shared(Vs);
    const uint32_t sP = (uint32_t)__cvta_generic_to_shared(Ps);

    const int bh = blockIdx.y;
    const int b = bh / Hh, h = bh % Hh;
    const int n0 = blockIdx.x * 128;
    const int tid = threadIdx.x;
    const int lane = tid & 31;
    const int w = tid >> 5;
    const int g = lane >> 2;
    const int tig = lane & 3;
    const int rbase = w * 16;

    const int lrow = ((lane >> 3) & 1) * 8 + (lane & 7);
    const int lk8  = (lane >> 4) * 8;

#pragma unroll
    for (int it = 0; it < 4; it++) {
        int id = tid + it * 256;
        int r  = id >> 3;
        int ch = id & 7;
        int n  = n0 + r;
        unsigned ok = (n < Nn) ? 16u : 0u;
        const __half* src = g_q + ((size_t)b * Nn + (n < Nn ? n : 0)) * Dd + h * dh + ch * 8;
        cp16(Qs + r * 36 + ch * 4, src, ok);
    }
#pragma unroll
    for (int it = 0; it < 9; it++) {
        int id = tid + it * 256;
        int half = id & 1;
        int key  = (id >> 1) >> 3;
        int ch   = (id >> 1) & 7;
        unsigned ok = (key < CTX) ? 16u : 0u;
        const __half* src = g_kv + ((size_t)b * CTX + (key < CTX ? key : 0)) * (2 * Dd)
                          + half * Dd + h * dh + ch * 8;
        uint32_t* dst = (half ? Vs : Ks) + key * 36 + ch * 4;
        cp16(dst, src, ok);
    }
    cp_commit();
    cp_wait<0>();
    __syncthreads();

    uint32_t afr[4][4];
#pragma unroll
    for (int ks = 0; ks < 4; ks++)
        ldsm4(afr[ks][0], afr[ks][1], afr[ks][2], afr[ks][3],
              sQ + (uint32_t)((((rbase + lrow) * 72 + lk8) * 2) + ks * 32));

    float sacc[18][4];
#pragma unroll
    for (int nt = 0; nt < 18; nt++)
#pragma unroll
        for (int j = 0; j < 4; j++) sacc[nt][j] = 0.f;

    const uint32_t koff = sK + (uint32_t)((lrow * 72 + lk8) * 2);
#pragma unroll
    for (int ntp = 0; ntp < 9; ntp++) {
#pragma unroll
        for (int ks = 0; ks < 4; ks++) {
            uint32_t bfr[2][2];
            ldsm4(bfr[0][0], bfr[1][0], bfr[0][1], bfr[1][1],
                  koff + (uint32_t)(ntp * 2304 + ks * 32));
            mma_f16(sacc[2 * ntp],     afr[ks], bfr[0]);
            mma_f16(sacc[2 * ntp + 1], afr[ks], bfr[1]);
        }
    }

    const float scale = 0.125f;
    float mlo = -1e30f, mhi = -1e30f;
#pragma unroll
    for (int nt = 0; nt < 18; nt++) {
        int c0 = nt * 8 + 2 * tig;
        float s0 = (c0     < CTX) ? sacc[nt][0] * scale : -1e30f;
        float s1 = (c0 + 1 < CTX) ? sacc[nt][1] * scale : -1e30f;
        float s2 = (c0     < CTX) ? sacc[nt][2] * scale : -1e30f;
        float s3 = (c0 + 1 < CTX) ? sacc[nt][3] * scale : -1e30f;
        sacc[nt][0] = s0; sacc[nt][1] = s1; sacc[nt][2] = s2; sacc[nt][3] = s3;
        mlo = fmaxf(mlo, fmaxf(s0, s1));
        mhi = fmaxf(mhi, fmaxf(s2, s3));
    }
    mlo = fmaxf(mlo, __shfl_xor_sync(0xffffffffu, mlo, 1));
    mlo = fmaxf(mlo, __shfl_xor_sync(0xffffffffu, mlo, 2));
    mhi = fmaxf(mhi, __shfl_xor_sync(0xffffffffu, mhi, 1));
    mhi = fmaxf(mhi, __shfl_xor_sync(0xffffffffu, mhi, 2));

    float llo = 0.f, lhi = 0.f;
#pragma unroll
    for (int nt = 0; nt < 18; nt++) {
        float p0 = __expf(sacc[nt][0] - mlo);
        float p1 = __expf(sacc[nt][1] - mlo);
        float p2 = __expf(sacc[nt][2] - mhi);
        float p3 = __expf(sacc[nt][3] - mhi);
        llo += p0 + p1; lhi += p2 + p3;
        sacc[nt][0] = p0; sacc[nt][1] = p1; sacc[nt][2] = p2; sacc[nt][3] = p3;
    }
    llo += __shfl_xor_sync(0xffffffffu, llo, 1);
    llo += __shfl_xor_sync(0xffffffffu, llo, 2);
    lhi += __shfl_xor_sync(0xffffffffu, lhi, 1);
    lhi += __shfl_xor_sync(0xffffffffu, lhi, 2);

#pragma unroll
    for (int nt = 0; nt < 18; nt++) {
        Ps[(rbase + g) * 76 + nt * 4 + tig]     = pk2(sacc[nt][0], sacc[nt][1]);
        Ps[(rbase + g + 8) * 76 + nt * 4 + tig] = pk2(sacc[nt][2], sacc[nt][3]);
    }
    __syncwarp();

    float oacc[8][4];
#pragma unroll
    for (int nt = 0; nt < 8; nt++)
#pragma unroll
        for (int j = 0; j < 4; j++) oacc[nt][j] = 0.f;

    const uint32_t poff = sP + (uint32_t)(((rbase + lrow) * 152 + lk8) * 2);
    const uint32_t voff = sV + (uint32_t)(((((lane >> 4) & 1) * 8 + (lane & 7)) * 72
                                           + ((lane >> 3) & 1) * 8) * 2);
#pragma unroll
    for (int ks = 0; ks < 9; ks++) {
        uint32_t a2[4];
        ldsm4(a2[0], a2[1], a2[2], a2[3], poff + (uint32_t)(ks * 32));
#pragma unroll
        for (int ntp = 0; ntp < 4; ntp++) {
            uint32_t bfr[2][2];
            ldsm4t(bfr[0][0], bfr[1][0], bfr[0][1], bfr[1][1],
                   voff + (uint32_t)(ks * 2304 + ntp * 32));
            mma_f16(oacc[2 * ntp],     a2, bfr[0]);
            mma_f16(oacc[2 * ntp + 1], a2, bfr[1]);
        }
    }

    float invlo = 1.f / llo, invhi = 1.f / lhi;
    int row_lo = n0 + rbase + g;
    int row_hi = row_lo + 8;
#pragma unroll
    for (int nt = 0; nt < 8; nt++) {
        int col = h * dh + nt * 8 + 2 * tig;
        if (row_lo < Nn)
            *reinterpret_cast<uint32_t*>(&y[((size_t)b * Nn + row_lo) * Dd + col]) =
                pk2(oacc[nt][0] * invlo, oacc[nt][1] * invlo);
        if (row_hi < Nn)
            *reinterpret_cast<uint32_t*>(&y[((size_t)b * Nn + row_hi) * Dd + col]) =
                pk2(oacc[nt][2] * invhi, oacc[nt][3] * invhi);
    }
}

// ---------------- launch -----------------------------------------------------
extern "C" void kernel_launch(void* const* d_in, const int* in_sizes, int n_in,
                              void* d_out, int out_size)
{
    const float* x    = (const float*)d_in[0];
    const float* Qb   = (const float*)d_in[1];
    const float* Wq   = (const float*)d_in[2];
    const float* Wctx = (const float*)d_in[3];
    const float* bctx = (const float*)d_in[4];
    const float* Wout = (const float*)d_in[5];
    const float* bout = (const float*)d_in[6];
    const float* cent = (const float*)d_in[7];
    float* out = (float*)d_out;

    __half *p_xh, *p_wqT, *p_wctxT, *p_woutT, *p_qctx, *p_probs, *p_ctx, *p_kv, *p_q, *p_y;
    cudaGetSymbolAddress((void**)&p_xh,     g_xh);
    cudaGetSymbolAddress((void**)&p_wqT,    g_wqT);
    cudaGetSymbolAddress((void**)&p_wctxT,  g_wctxT);
    cudaGetSymbolAddress((void**)&p_woutT,  g_woutT);
    cudaGetSymbolAddress((void**)&p_qctx,   g_qctx);
    cudaGetSymbolAddress((void**)&p_probs,  g_probs);
    cudaGetSymbolAddress((void**)&p_ctx,    g_ctx);
    cudaGetSymbolAddress((void**)&p_kv,     g_kv);
    cudaGetSymbolAddress((void**)&p_q,      g_q);
    cudaGetSymbolAddress((void**)&p_y,      g_y);

    const int SMEM_NT  = (4 * 128 * 20 + 4 * 128 * 20) * 4;   // 81920
    const int SMEM_NN  = (4 * 128 * 20 + 4 * 32 * 68) * 4;    // 75776
    const int ATTN_SMEM = (128 * 36 + 144 * 36 + 144 * 36 + 128 * 76) * 4;  // 98816
    cudaFuncSetAttribute((const void*)hgemm<true,  false, true >, cudaFuncAttributeMaxDynamicSharedMemorySize, SMEM_NT);
    cudaFuncSetAttribute((const void*)hgemm<true,  true,  true >, cudaFuncAttributeMaxDynamicSharedMemorySize, SMEM_NT);
    cudaFuncSetAttribute((const void*)hgemm<true,  true,  false>, cudaFuncAttributeMaxDynamicSharedMemorySize, SMEM_NT);
    cudaFuncSetAttribute((const void*)hgemm<false, false, true >, cudaFuncAttributeMaxDynamicSharedMemorySize, SMEM_NN);
    cudaFuncSetAttribute((const void*)attn_mma, cudaFuncAttributeMaxDynamicSharedMemorySize, ATTN_SMEM);

    const size_t main_sz = (size_t)Bsz * Nn * Dd;
    float* cls_out = nullptr;
    float* idx_out = nullptr;
    if ((size_t)out_size >= main_sz + (size_t)Bsz * Dd + Bsz) {
        cls_out = out + main_sz;
        idx_out = out + main_sz + (size_t)Bsz * Dd;
    }

    // ---- stream fork: q-projection chain runs concurrently with ctx chain ----
    cudaStream_t s2;
    cudaStreamCreateWithFlags(&s2, cudaStreamNonBlocking);
    cudaEvent_t e1, e2;
    cudaEventCreateWithFlags(&e1, cudaEventDisableTiming);
    cudaEventCreateWithFlags(&e2, cudaEventDisableTiming);

    // 0) convert x -> half (both chains need it)
    {
        int n4 = (int)(main_sz / 4);
        f2h_kernel<<<(n4 + 255) / 256, 256>>>((const float4*)x, (uint2*)p_xh, n4);
    }
    cudaEventRecord(e1, 0);
    cudaStreamWaitEvent(s2, e1, 0);

    // ---- side chain (s2): Wq^T then q = x @ Wq ----
    transpose_h<<<dim3(Dd / 32, Dd / 32), dim3(32, 8), 0, s2>>>(Wq, p_wqT, Dd, Dd);
    hgemm<true, false, true><<<dim3(Dd / 128, (Bsz * Nn + 127) / 128, 1), 256, SMEM_NT, s2>>>(
        p_xh, p_wqT, nullptr, p_q,
        Bsz * Nn, Dd, Dd, Dd, Dd, Dd, 0, 0, 0);
    cudaEventRecord(e2, s2);

    // ---- main chain: ctx pipeline ----
    transpose_h<<<dim3(2 * Dd / 32, Dd / 32), dim3(32, 8)>>>(Wctx, p_wctxT, Dd, 2 * Dd);
    transpose_h<<<dim3(Dd / 32, Dd / 32), dim3(32, 8)>>>(Wout, p_woutT, Dd, Dd);

    cls_kernel<<<Bsz, 256>>>(x, cent, cls_out, idx_out);
    gather_qctx_kernel<<<4096, 256>>>(Qb);
    xreg_kernel<<<(Bsz * Rr * Dd / 2 + 255) / 256, 256>>>();

    // scores = q_ctx @ xp^T (NT, batched) -> half, straight into probs buffer
    hgemm<true, false, true><<<dim3(Pp / 128, 1, Bsz), 256, SMEM_NT>>>(
        p_qctx, p_xh + (size_t)Rr * Dd, nullptr, p_probs,
        Kk, Pp, Dd, Dd, Dd, Pp,
        (long long)Kk * Dd, (long long)Nn * Dd, (long long)Kk * Pp);

    // softmax in-place (half)
    softmax_kernel<<<Bsz * Kk, 256>>>(p_probs);

    // ctx_p = probs @ xp (NN, batched, half out)
    hgemm<false, false, true><<<dim3(Dd / 128, 1, Bsz), 256, SMEM_NN>>>(
        p_probs, p_xh + (size_t)Rr * Dd, nullptr, p_ctx + (size_t)Rr * Dd,
        Kk, Dd, Pp, Pp, Dd, Dd,
        (long long)Kk * Pp, (long long)Nn * Dd, (long long)CTX * Dd);

    // kv = ctx @ Wctx + bctx (NT via Wctx^T, half out)
    hgemm<true, true, true><<<dim3((2 * Dd) / 128, (Bsz * CTX + 127) / 128, 1), 256, SMEM_NT>>>(
        p_ctx, p_wctxT, bctx, p_kv,
        Bsz * CTX, 2 * Dd, Dd, Dd, Dd, 2 * Dd, 0, 0, 0);

    // ---- join: attention needs q (s2) + kv (main) ----
    cudaStreamWaitEvent(0, e2, 0);

    attn_mma<<<dim3((Nn + 127) / 128, Bsz * Hh), 256, ATTN_SMEM>>>(p_y);

    // out = y @ Wout + bout (NT via Wout^T, fp32 out)
    hgemm<true, true, false><<<dim3(Dd / 128, (Bsz * Nn + 127) / 128, 1), 256, SMEM_NT>>>(
        p_y, p_woutT, bout, out,
        Bsz * Nn, Dd, Dd, Dd, Dd, Dd, 0, 0, 0);

    cudaEventDestroy(e1);
    cudaEventDestroy(e2);
    cudaStreamDestroy(s2);
}

// round 10
// speedup vs baseline: 5.6509x; 1.0165x over previous
#include <cuda_runtime.h>
#include <cuda_fp16.h>
#include <math.h>
#include <stdint.h>

#define Bsz 64
#define Nn  1029
#define Dd  768
#define Hh  12
#define dh  64
#define Kk  128
#define Rr  5
#define Mm  4
#define Pp  1024          // N - R
#define CTX 133           // R + K

// ---------------- scratch (static device globals: allocation-free) ----------
__device__ int    g_idx[Bsz];
__device__ __half g_xh[(size_t)Bsz * Nn * Dd];
__device__ __half g_wqT[Dd * Dd];
__device__ __half g_wctxT[2 * Dd * Dd];
__device__ __half g_woutT[Dd * Dd];
__device__ __half g_qctx[(size_t)Bsz * Kk * Dd];
__device__ __half g_probs[(size_t)Bsz * Kk * Pp];
__device__ __half g_ctx[(size_t)Bsz * CTX * Dd];
__device__ __half g_kv[(size_t)Bsz * CTX * 2 * Dd];
__device__ __half g_q[(size_t)Bsz * Nn * Dd];
__device__ __half g_y[(size_t)Bsz * Nn * Dd];

// ---------------- helpers ----------------------------------------------------
__device__ __forceinline__ uint32_t pk2(float a, float b) {
    __half2 h = __floats2half2_rn(a, b);
    return *reinterpret_cast<uint32_t*>(&h);
}

__device__ __forceinline__ void mma_f16(float* c, const uint32_t* a, const uint32_t* b) {
    asm volatile(
        "mma.sync.aligned.m16n8k16.row.col.f32.f16.f16.f32 "
        "{%0,%1,%2,%3}, {%4,%5,%6,%7}, {%8,%9}, {%0,%1,%2,%3};\n"
        : "+f"(c[0]), "+f"(c[1]), "+f"(c[2]), "+f"(c[3])
        : "r"(a[0]), "r"(a[1]), "r"(a[2]), "r"(a[3]), "r"(b[0]), "r"(b[1]));
}

__device__ __forceinline__ void ldsm4(uint32_t& r0, uint32_t& r1, uint32_t& r2,
                                      uint32_t& r3, uint32_t a) {
    asm volatile("ldmatrix.sync.aligned.m8n8.x4.shared.b16 {%0,%1,%2,%3}, [%4];"
                 : "=r"(r0), "=r"(r1), "=r"(r2), "=r"(r3) : "r"(a));
}
__device__ __forceinline__ void ldsm4t(uint32_t& r0, uint32_t& r1, uint32_t& r2,
                                       uint32_t& r3, uint32_t a) {
    asm volatile("ldmatrix.sync.aligned.m8n8.x4.trans.shared.b16 {%0,%1,%2,%3}, [%4];"
                 : "=r"(r0), "=r"(r1), "=r"(r2), "=r"(r3) : "r"(a));
}

__device__ __forceinline__ void cp16(void* smem_dst, const void* gsrc, unsigned bytes) {
    unsigned saddr = (unsigned)__cvta_generic_to_shared(smem_dst);
    asm volatile("cp.async.cg.shared.global [%0], [%1], 16, %2;\n"
                 :: "r"(saddr), "l"(gsrc), "r"(bytes));
}
__device__ __forceinline__ void cp_commit() { asm volatile("cp.async.commit_group;\n"); }
template<int N> __device__ __forceinline__ void cp_wait() {
    asm volatile("cp.async.wait_group %0;\n" :: "n"(N));
}

// ---------------- conversion kernels ------------------------------------------
__global__ void f2h_kernel(const float4* __restrict__ src, uint2* __restrict__ dst, int n4)
{
    int i = blockIdx.x * blockDim.x + threadIdx.x;
    if (i < n4) {
        float4 v = src[i];
        uint2 o;
        o.x = pk2(v.x, v.y);
        o.y = pk2(v.z, v.w);
        dst[i] = o;
    }
}

__global__ void transpose_h(const float* __restrict__ src, __half* __restrict__ dst,
                            int K, int N)
{
    __shared__ float t[32][33];
    int k0 = blockIdx.y * 32, n0 = blockIdx.x * 32;
    int tx = threadIdx.x, ty = threadIdx.y;   // 32 x 8
    for (int i = ty; i < 32; i += 8)
        t[i][tx] = src[(size_t)(k0 + i) * N + n0 + tx];
    __syncthreads();
    for (int i = ty; i < 32; i += 8)
        dst[(size_t)(n0 + i) * K + k0 + tx] = __float2half_rn(t[tx][i]);
}

// ---------------- cls_n, sims, argmax (fp32 exact) ---------------------------
__global__ void cls_kernel(const float* __restrict__ x,
                           const float* __restrict__ cent,
                           float* __restrict__ cls_out,
                           float* __restrict__ idx_out)
{
    int b = blockIdx.x;
    int tid = threadIdx.x;
    __shared__ float xs[Dd];
    __shared__ float red[256];
    __shared__ float sims[Mm];
    __shared__ float inv_s;

    float ss = 0.f;
    for (int i = tid; i < Dd; i += 256) {
        float v = x[(size_t)b * Nn * Dd + i];
        xs[i] = v;
        ss += v * v;
    }
    red[tid] = ss; __syncthreads();
    for (int s = 128; s > 0; s >>= 1) { if (tid < s) red[tid] += red[tid + s]; __syncthreads(); }
    if (tid == 0) inv_s = 1.f / fmaxf(sqrtf(red[0]), 1e-12f);
    __syncthreads();
    float inv = inv_s;

    for (int m = 0; m < Mm; m++) {
        float p = 0.f;
        for (int i = tid; i < Dd; i += 256) p += xs[i] * cent[m * Dd + i];
        red[tid] = p; __syncthreads();
        for (int s = 128; s > 0; s >>= 1) { if (tid < s) red[tid] += red[tid + s]; __syncthreads(); }
        if (tid == 0) sims[m] = red[0] * inv;
        __syncthreads();
    }
    if (tid == 0) {
        int best = 0; float bv = sims[0];
        for (int m = 1; m < Mm; m++) if (sims[m] > bv) { bv = sims[m]; best = m; }
        g_idx[b] = best;
        if (idx_out) idx_out[b] = (float)best;
    }
    if (cls_out)
        for (int i = tid; i < Dd; i += 256)
            cls_out[(size_t)b * Dd + i] = xs[i] * inv;
}

// ---------------- gather Q_banks[idx] (half) + xreg --------------------------
__global__ void gather_qctx_kernel(const float* __restrict__ Qb)
{
    size_t total = (size_t)Bsz * Kk * Dd;
    for (size_t i = (size_t)blockIdx.x * blockDim.x + threadIdx.x; i < total;
         i += (size_t)gridDim.x * blockDim.x) {
        int b = (int)(i / ((size_t)Kk * Dd));
        size_t r = i - (size_t)b * Kk * Dd;
        g_qctx[i] = __float2half_rn(Qb[(size_t)g_idx[b] * Kk * Dd + r]);
    }
}

__global__ void xreg_kernel()
{
    int i = blockIdx.x * blockDim.x + threadIdx.x;       // u32 units
    const int total = Bsz * Rr * Dd / 2;
    if (i < total) {
        int b = i / (Rr * Dd / 2);
        int r = i - b * (Rr * Dd / 2);
        reinterpret_cast<uint32_t*>(g_ctx)[(size_t)b * CTX * Dd / 2 + r] =
            reinterpret_cast<const uint32_t*>(g_xh)[(size_t)b * Nn * Dd / 2 + r];
    }
}

// ---------------- fp16 tensor-core GEMM, 4-stage cp.async + ldmatrix --------
template<bool TRANSB, bool BIAS, bool OUTHALF>
__global__ __launch_bounds__(256, 2)
void hgemm(const __half* __restrict__ A, const __half* __restrict__ Bm,
           const float* __restrict__ bias, void* __restrict__ Cv,
           int M, int N, int Kd, int lda, int ldb, int ldc,
           long long sA, long long sB, long long sC)
{
    extern __shared__ uint32_t smu[];
    const int ASTG = 128 * 20;
    const int BSTG = TRANSB ? 128 * 20 : 32 * 68;
    uint32_t* smA = smu;
    uint32_t* smB = smu + 4 * ASTG;
    const uint32_t sbA = (uint32_t)__cvta_generic_to_shared(smA);
    const uint32_t sbB = (uint32_t)__cvta_generic_to_shared(smB);

    const __half* Ab = A  + (long long)blockIdx.z * sA;
    const __half* Bb = Bm + (long long)blockIdx.z * sB;

    const int row0 = blockIdx.y * 128;
    const int col0 = blockIdx.x * 128;
    const int tid  = threadIdx.x;
    const int lane = tid & 31;
    const int warp = tid >> 5;
    const int wm = warp >> 1;
    const int wn = warp & 1;
    const int g   = lane >> 2;
    const int tig = lane & 3;

    const int lrow = ((lane >> 3) & 1) * 8 + (lane & 7);
    const int lk8  = (lane >> 4) * 8;
    uint32_t aoff[2], boff[4];
#pragma unroll
    for (int im = 0; im < 2; im++)
        aoff[im] = (uint32_t)(((wm * 32 + im * 16 + lrow) * 40 + lk8) * 2);
#pragma unroll
    for (int p = 0; p < 4; p++) {
        if (TRANSB)
            boff[p] = (uint32_t)(((wn * 64 + p * 16 + lrow) * 40 + lk8) * 2);
        else
            boff[p] = (uint32_t)(((((lane >> 4) & 1) * 8 + (lane & 7)) * 136
                                  + wn * 64 + p * 16 + ((lane >> 3) & 1) * 8) * 2);
    }

    float acc[2][8][4];
#pragma unroll
    for (int im = 0; im < 2; im++)
#pragma unroll
        for (int in = 0; in < 8; in++)
#pragma unroll
            for (int j = 0; j < 4; j++) acc[im][in][j] = 0.f;

    auto loadA = [&](int stg, int k0) {
        uint32_t* dst = smA + stg * ASTG;
#pragma unroll
        for (int it = 0; it < 2; it++) {
            int id = tid + it * 256;
            int r  = id >> 2;
            int c  = (id & 3) * 4;
            int gr = row0 + r;
            unsigned ok = (gr < M) ? 16u : 0u;
            const __half* src = Ab + (size_t)(gr < M ? gr : 0) * lda + k0 + c * 2;
            cp16(dst + r * 20 + c, src, ok);
        }
    };
    auto loadB = [&](int stg, int k0) {
        uint32_t* dst = smB + stg * BSTG;
#pragma unroll
        for (int it = 0; it < 2; it++) {
            int id = tid + it * 256;
            if (TRANSB) {
                int n = id >> 2;
                int c = (id & 3) * 4;
                cp16(dst + n * 20 + c, Bb + (size_t)(col0 + n) * ldb + k0 + c * 2, 16u);
            } else {
                int kr = id >> 4;
                int ch = id & 15;
                cp16(dst + kr * 68 + ch * 4, Bb + (size_t)(k0 + kr) * ldb + col0 + ch * 8, 16u);
            }
        }
    };

    loadA(0, 0);  loadB(0, 0);  cp_commit();
    loadA(1, 32); loadB(1, 32); cp_commit();
    loadA(2, 64); loadB(2, 64); cp_commit();

    const int nk = Kd >> 5;
    for (int i = 0; i < nk; i++) {
        int rem = nk - 1 - i;
        if (rem >= 2)      cp_wait<2>();
        else if (rem == 1) cp_wait<1>();
        else               cp_wait<0>();
        __syncthreads();
        if (i + 3 < nk) {
            int s4 = (i + 3) & 3;
            loadA(s4, (i + 3) * 32);
            loadB(s4, (i + 3) * 32);
            cp_commit();
        }

        const uint32_t baA = sbA + (uint32_t)((i & 3) * ASTG * 4);
        const uint32_t baB = sbB + (uint32_t)((i & 3) * BSTG * 4);

#pragma unroll
        for (int s = 0; s < 2; s++) {
            uint32_t afr[2][4], bfr[8][2];
#pragma unroll
            for (int im = 0; im < 2; im++)
                ldsm4(afr[im][0], afr[im][1], afr[im][2], afr[im][3],
                      baA + aoff[im] + s * 32);
#pragma unroll
            for (int p = 0; p < 4; p++) {
                if (TRANSB)
                    ldsm4(bfr[2 * p][0], bfr[2 * p + 1][0], bfr[2 * p][1], bfr[2 * p + 1][1],
                          baB + boff[p] + s * 32);
                else
                    ldsm4t(bfr[2 * p][0], bfr[2 * p + 1][0], bfr[2 * p][1], bfr[2 * p + 1][1],
                           baB + boff[p] + s * 4352);
            }
#pragma unroll
            for (int im = 0; im < 2; im++)
#pragma unroll
                for (int in = 0; in < 8; in++)
                    mma_f16(acc[im][in], afr[im], bfr[in]);
        }
        // trailing barrier elided: next iteration's leading barrier protects the ring
    }

#pragma unroll
    for (int im = 0; im < 2; im++) {
        int rb = row0 + wm * 32 + im * 16 + g;
#pragma unroll
        for (int in = 0; in < 8; in++) {
            int cb = col0 + wn * 64 + in * 8 + 2 * tig;
            float b0 = BIAS ? bias[cb] : 0.f;
            float b1 = BIAS ? bias[cb + 1] : 0.f;
            float v0 = acc[im][in][0] + b0, v1 = acc[im][in][1] + b1;
            float v2 = acc[im][in][2] + b0, v3 = acc[im][in][3] + b1;
            if (OUTHALF) {
                __half* C = (__half*)Cv + (long long)blockIdx.z * sC;
                if (rb < M)
                    *reinterpret_cast<uint32_t*>(&C[(size_t)rb * ldc + cb]) = pk2(v0, v1);
                if (rb + 8 < M)
                    *reinterpret_cast<uint32_t*>(&C[(size_t)(rb + 8) * ldc + cb]) = pk2(v2, v3);
            } else {
                float* C = (float*)Cv + (long long)blockIdx.z * sC;
                if (rb < M)
                    *reinterpret_cast<float2*>(&C[(size_t)rb * ldc + cb]) = make_float2(v0, v1);
                if (rb + 8 < M)
                    *reinterpret_cast<float2*>(&C[(size_t)(rb + 8) * ldc + cb]) = make_float2(v2, v3);
            }
        }
    }
}

// ---------------- row softmax over P=1024: half in-place ----------------------
__global__ void softmax_kernel(__half* __restrict__ pr)
{
    int row = blockIdx.x;
    uint2* p2 = reinterpret_cast<uint2*>(pr + (size_t)row * Pp);
    int tid = threadIdx.x;
    __shared__ float red[256];

    uint2 u = p2[tid];
    __half2 h0 = *reinterpret_cast<__half2*>(&u.x);
    __half2 h1 = *reinterpret_cast<__half2*>(&u.y);
    float vx = __low2float(h0), vy = __high2float(h0);
    float vz = __low2float(h1), vw = __high2float(h1);

    float mx = fmaxf(fmaxf(vx, vy), fmaxf(vz, vw));
    red[tid] = mx; __syncthreads();
    for (int st = 128; st > 0; st >>= 1) { if (tid < st) red[tid] = fmaxf(red[tid], red[tid + st]); __syncthreads(); }
    mx = red[0]; __syncthreads();

    vx = __expf(vx - mx); vy = __expf(vy - mx);
    vz = __expf(vz - mx); vw = __expf(vw - mx);
    float sm = vx + vy + vz + vw;
    red[tid] = sm; __syncthreads();
    for (int st = 128; st > 0; st >>= 1) { if (tid < st) red[tid] += red[tid + st]; __syncthreads(); }
    float inv = 1.f / red[0];
    uint2 o;
    o.x = pk2(vx * inv, vy * inv);
    o.y = pk2(vz * inv, vw * inv);
    p2[tid] = o;
}

// ---------------- fp16 tensor-core fused attention ----------------------------
// grid (17, B*H), 128 threads (4 warps x 16 query rows = 64 queries/CTA).
// 3 CTAs/SM for latency hiding. Keys padded to 144.
__global__ __launch_bounds__(128, 3)
void attn_mma(__half* __restrict__ y)
{
    extern __shared__ uint32_t smu[];
    uint32_t* Qs = smu;                    // [64][36] u32  (72-half pitch)
    uint32_t* Ks = smu + 64 * 36;          // [144][36]
    uint32_t* Vs = Ks + 144 * 36;          // [144][36]
    uint32_t* Ps = Vs + 144 * 36;          // [64][76] u32  (152-half pitch)
    const uint32_t sQ = (uint32_t)__cvta_generic_to_shared(Qs);
    const uint32_t sK = (uint32_t)__cvta_generic_to_shared(Ks);
    const uint32_t sV = (uint32_t)__cvta_generic_to_shared(Vs);
    const uint32_t sP = (uint32_t)__cvta_generic_to_shared(Ps);

    const int bh = blockIdx.y;
    const int b = bh / Hh, h = bh % Hh;
    const int n0 = blockIdx.x * 64;
    const int tid = threadIdx.x;
    const int lane = tid & 31;
    const int w = tid >> 5;                // 0..3
    const int g = lane >> 2;
    const int tig = lane & 3;
    const int rbase = w * 16;

    const int lrow = ((lane >> 3) & 1) * 8 + (lane & 7);
    const int lk8  = (lane >> 4) * 8;

    // ---- Q tile 64x64 halfs ----------------------------------------------------
#pragma unroll
    for (int it = 0; it < 4; it++) {
        int id = tid + it * 128;           // 0..511
        int r  = id >> 3;                  // 0..63
        int ch = id & 7;
        int n  = n0 + r;
        unsigned ok = (n < Nn) ? 16u : 0u;
        const __half* src = g_q + ((size_t)b * Nn + (n < Nn ? n : 0)) * Dd + h * dh + ch * 8;
        cp16(Qs + r * 36 + ch * 4, src, ok);
    }
    // ---- K and V tiles 144x64 halfs (rows >= CTX zero-filled) -------------------
#pragma unroll
    for (int it = 0; it < 18; it++) {
        int id = tid + it * 128;           // 0..2303
        int half = id & 1;                 // 0 = K, 1 = V
        int key  = (id >> 1) >> 3;         // 0..143
        int ch   = (id >> 1) & 7;
        unsigned ok = (key < CTX) ? 16u : 0u;
        const __half* src = g_kv + ((size_t)b * CTX + (key < CTX ? key : 0)) * (2 * Dd)
                          + half * Dd + h * dh + ch * 8;
        uint32_t* dst = (half ? Vs : Ks) + key * 36 + ch * 4;
        cp16(dst, src, ok);
    }
    cp_commit();
    cp_wait<0>();
    __syncthreads();

    // ---- phase 1: S = Q K^T -----------------------------------------------------
    uint32_t afr[4][4];
#pragma unroll
    for (int ks = 0; ks < 4; ks++)
        ldsm4(afr[ks][0], afr[ks][1], afr[ks][2], afr[ks][3],
              sQ + (uint32_t)((((rbase + lrow) * 72 + lk8) * 2) + ks * 32));

    float sacc[18][4];
#pragma unroll
    for (int nt = 0; nt < 18; nt++)
#pragma unroll
        for (int j = 0; j < 4; j++) sacc[nt][j] = 0.f;

    const uint32_t koff = sK + (uint32_t)((lrow * 72 + lk8) * 2);
#pragma unroll
    for (int ntp = 0; ntp < 9; ntp++) {
#pragma unroll
        for (int ks = 0; ks < 4; ks++) {
            uint32_t bfr[2][2];
            ldsm4(bfr[0][0], bfr[1][0], bfr[0][1], bfr[1][1],
                  koff + (uint32_t)(ntp * 2304 + ks * 32));
            mma_f16(sacc[2 * ntp],     afr[ks], bfr[0]);
            mma_f16(sacc[2 * ntp + 1], afr[ks], bfr[1]);
        }
    }

    // ---- exact softmax over 133 keys --------------------------------------------
    const float scale = 0.125f;
    float mlo = -1e30f, mhi = -1e30f;
#pragma unroll
    for (int nt = 0; nt < 18; nt++) {
        int c0 = nt * 8 + 2 * tig;
        float s0 = (c0     < CTX) ? sacc[nt][0] * scale : -1e30f;
        float s1 = (c0 + 1 < CTX) ? sacc[nt][1] * scale : -1e30f;
        float s2 = (c0     < CTX) ? sacc[nt][2] * scale : -1e30f;
        float s3 = (c0 + 1 < CTX) ? sacc[nt][3] * scale : -1e30f;
        sacc[nt][0] = s0; sacc[nt][1] = s1; sacc[nt][2] = s2; sacc[nt][3] = s3;
        mlo = fmaxf(mlo, fmaxf(s0, s1));
        mhi = fmaxf(mhi, fmaxf(s2, s3));
    }
    mlo = fmaxf(mlo, __shfl_xor_sync(0xffffffffu, mlo, 1));
    mlo = fmaxf(mlo, __shfl_xor_sync(0xffffffffu, mlo, 2));
    mhi = fmaxf(mhi, __shfl_xor_sync(0xffffffffu, mhi, 1));
    mhi = fmaxf(mhi, __shfl_xor_sync(0xffffffffu, mhi, 2));

    float llo = 0.f, lhi = 0.f;
#pragma unroll
    for (int nt = 0; nt < 18; nt++) {
        float p0 = __expf(sacc[nt][0] - mlo);
        float p1 = __expf(sacc[nt][1] - mlo);
        float p2 = __expf(sacc[nt][2] - mhi);
        float p3 = __expf(sacc[nt][3] - mhi);
        llo += p0 + p1; lhi += p2 + p3;
        sacc[nt][0] = p0; sacc[nt][1] = p1; sacc[nt][2] = p2; sacc[nt][3] = p3;
    }
    llo += __shfl_xor_sync(0xffffffffu, llo, 1);
    llo += __shfl_xor_sync(0xffffffffu, llo, 2);
    lhi += __shfl_xor_sync(0xffffffffu, lhi, 1);
    lhi += __shfl_xor_sync(0xffffffffu, lhi, 2);

    // ---- P -> smem (half pairs, 144 cols; pads are exp(-inf)=0) ------------------
#pragma unroll
    for (int nt = 0; nt < 18; nt++) {
        Ps[(rbase + g) * 76 + nt * 4 + tig]     = pk2(sacc[nt][0], sacc[nt][1]);
        Ps[(rbase + g + 8) * 76 + nt * 4 + tig] = pk2(sacc[nt][2], sacc[nt][3]);
    }
    __syncwarp();

    // ---- phase 2: O = P V (V via ldsm.trans) ------------------------------------
    float oacc[8][4];
#pragma unroll
    for (int nt = 0; nt < 8; nt++)
#pragma unroll
        for (int j = 0; j < 4; j++) oacc[nt][j] = 0.f;

    const uint32_t poff = sP + (uint32_t)(((rbase + lrow) * 152 + lk8) * 2);
    const uint32_t voff = sV + (uint32_t)(((((lane >> 4) & 1) * 8 + (lane & 7)) * 72
                                           + ((lane >> 3) & 1) * 8) * 2);
#pragma unroll
    for (int ks = 0; ks < 9; ks++) {
        uint32_t a2[4];
        ldsm4(a2[0], a2[1], a2[2], a2[3], poff + (uint32_t)(ks * 32));
#pragma unroll
        for (int ntp = 0; ntp < 4; ntp++) {
            uint32_t bfr[2][2];
            ldsm4t(bfr[0][0], bfr[1][0], bfr[0][1], bfr[1][1],
                   voff + (uint32_t)(ks * 2304 + ntp * 32));
            mma_f16(oacc[2 * ntp],     a2, bfr[0]);
            mma_f16(oacc[2 * ntp + 1], a2, bfr[1]);
        }
    }

    // ---- output y (half) ---------------------------------------------------------
    float invlo = 1.f / llo, invhi = 1.f / lhi;
    int row_lo = n0 + rbase + g;
    int row_hi = row_lo + 8;
#pragma unroll
    for (int nt = 0; nt < 8; nt++) {
        int col = h * dh + nt * 8 + 2 * tig;
        if (row_lo < Nn)
            *reinterpret_cast<uint32_t*>(&y[((size_t)b * Nn + row_lo) * Dd + col]) =
                pk2(oacc[nt][0] * invlo, oacc[nt][1] * invlo);
        if (row_hi < Nn)
            *reinterpret_cast<uint32_t*>(&y[((size_t)b * Nn + row_hi) * Dd + col]) =
                pk2(oacc[nt][2] * invhi, oacc[nt][3] * invhi);
    }
}

// ---------------- launch -----------------------------------------------------
extern "C" void kernel_launch(void* const* d_in, const int* in_sizes, int n_in,
                              void* d_out, int out_size)
{
    const float* x    = (const float*)d_in[0];
    const float* Qb   = (const float*)d_in[1];
    const float* Wq   = (const float*)d_in[2];
    const float* Wctx = (const float*)d_in[3];
    const float* bctx = (const float*)d_in[4];
    const float* Wout = (const float*)d_in[5];
    const float* bout = (const float*)d_in[6];
    const float* cent = (const float*)d_in[7];
    float* out = (float*)d_out;

    __half *p_xh, *p_wqT, *p_wctxT, *p_woutT, *p_qctx, *p_probs, *p_ctx, *p_kv, *p_q, *p_y;
    cudaGetSymbolAddress((void**)&p_xh,     g_xh);
    cudaGetSymbolAddress((void**)&p_wqT,    g_wqT);
    cudaGetSymbolAddress((void**)&p_wctxT,  g_wctxT);
    cudaGetSymbolAddress((void**)&p_woutT,  g_woutT);
    cudaGetSymbolAddress((void**)&p_qctx,   g_qctx);
    cudaGetSymbolAddress((void**)&p_probs,  g_probs);
    cudaGetSymbolAddress((void**)&p_ctx,    g_ctx);
    cudaGetSymbolAddress((void**)&p_kv,     g_kv);
    cudaGetSymbolAddress((void**)&p_q,      g_q);
    cudaGetSymbolAddress((void**)&p_y,      g_y);

    const int SMEM_NT  = (4 * 128 * 20 + 4 * 128 * 20) * 4;   // 81920
    const int SMEM_NN  = (4 * 128 * 20 + 4 * 32 * 68) * 4;    // 75776
    const int ATTN_SMEM = (64 * 36 + 144 * 36 + 144 * 36 + 64 * 76) * 4;  // 70144
    cudaFuncSetAttribute((const void*)hgemm<true,  false, true >, cudaFuncAttributeMaxDynamicSharedMemorySize, SMEM_NT);
    cudaFuncSetAttribute((const void*)hgemm<true,  true,  true >, cudaFuncAttributeMaxDynamicSharedMemorySize, SMEM_NT);
    cudaFuncSetAttribute((const void*)hgemm<true,  true,  false>, cudaFuncAttributeMaxDynamicSharedMemorySize, SMEM_NT);
    cudaFuncSetAttribute((const void*)hgemm<false, false, true >, cudaFuncAttributeMaxDynamicSharedMemorySize, SMEM_NN);
    cudaFuncSetAttribute((const void*)attn_mma, cudaFuncAttributeMaxDynamicSharedMemorySize, ATTN_SMEM);

    const size_t main_sz = (size_t)Bsz * Nn * Dd;
    float* cls_out = nullptr;
    float* idx_out = nullptr;
    if ((size_t)out_size >= main_sz + (size_t)Bsz * Dd + Bsz) {
        cls_out = out + main_sz;
        idx_out = out + main_sz + (size_t)Bsz * Dd;
    }

    cudaStream_t s2;
    cudaStreamCreateWithFlags(&s2, cudaStreamNonBlocking);
    cudaEvent_t e0, e1, e2, e3;
    cudaEventCreateWithFlags(&e0, cudaEventDisableTiming);
    cudaEventCreateWithFlags(&e1, cudaEventDisableTiming);
    cudaEventCreateWithFlags(&e2, cudaEventDisableTiming);
    cudaEventCreateWithFlags(&e3, cudaEventDisableTiming);

    // ---- legal capture fork: record on capturing stream FIRST, then s2 waits ----
    cudaEventRecord(e0, 0);
    cudaStreamWaitEvent(s2, e0, 0);

    // main: convert x -> half
    {
        int n4 = (int)(main_sz / 4);
        f2h_kernel<<<(n4 + 255) / 256, 256>>>((const float4*)x, (uint2*)p_xh, n4);
    }
    cudaEventRecord(e1, 0);

    // ---- side chain (s2): f2h-independent prologue, then q GEMM ----
    transpose_h<<<dim3(Dd / 32, Dd / 32), dim3(32, 8), 0, s2>>>(Wq, p_wqT, Dd, Dd);
    cls_kernel<<<Bsz, 256, 0, s2>>>(x, cent, cls_out, idx_out);
    gather_qctx_kernel<<<4096, 256, 0, s2>>>(Qb);
    cudaEventRecord(e3, s2);                  // qctx ready
    cudaStreamWaitEvent(s2, e1, 0);           // need xh for q GEMM
    hgemm<true, false, true><<<dim3(Dd / 128, (Bsz * Nn + 127) / 128, 1), 256, SMEM_NT, s2>>>(
        p_xh, p_wqT, nullptr, p_q,
        Bsz * Nn, Dd, Dd, Dd, Dd, Dd, 0, 0, 0);
    cudaEventRecord(e2, s2);

    // ---- main chain: ctx pipeline ----
    transpose_h<<<dim3(2 * Dd / 32, Dd / 32), dim3(32, 8)>>>(Wctx, p_wctxT, Dd, 2 * Dd);
    transpose_h<<<dim3(Dd / 32, Dd / 32), dim3(32, 8)>>>(Wout, p_woutT, Dd, Dd);
    xreg_kernel<<<(Bsz * Rr * Dd / 2 + 255) / 256, 256>>>();

    cudaStreamWaitEvent(0, e3, 0);            // need qctx

    hgemm<true, false, true><<<dim3(Pp / 128, 1, Bsz), 256, SMEM_NT>>>(
        p_qctx, p_xh + (size_t)Rr * Dd, nullptr, p_probs,
        Kk, Pp, Dd, Dd, Dd, Pp,
        (long long)Kk * Dd, (long long)Nn * Dd, (long long)Kk * Pp);

    softmax_kernel<<<Bsz * Kk, 256>>>(p_probs);

    hgemm<false, false, true><<<dim3(Dd / 128, 1, Bsz), 256, SMEM_NN>>>(
        p_probs, p_xh + (size_t)Rr * Dd, nullptr, p_ctx + (size_t)Rr * Dd,
        Kk, Dd, Pp, Pp, Dd, Dd,
        (long long)Kk * Pp, (long long)Nn * Dd, (long long)CTX * Dd);

    hgemm<true, true, true><<<dim3((2 * Dd) / 128, (Bsz * CTX + 127) / 128, 1), 256, SMEM_NT>>>(
        p_ctx, p_wctxT, bctx, p_kv,
        Bsz * CTX, 2 * Dd, Dd, Dd, Dd, 2 * Dd, 0, 0, 0);

    // ---- join: attention needs q (s2) + kv (main) ----
    cudaStreamWaitEvent(0, e2, 0);

    attn_mma<<<dim3((Nn + 63) / 64, Bsz * Hh), 128, ATTN_SMEM>>>(p_y);

    hgemm<true, true, false><<<dim3(Dd / 128, (Bsz * Nn + 127) / 128, 1), 256, SMEM_NT>>>(
        p_y, p_woutT, bout, out,
        Bsz * Nn, Dd, Dd, Dd, Dd, Dd, 0, 0, 0);

    cudaEventDestroy(e0);
    cudaEventDestroy(e1);
    cudaEventDestroy(e2);
    cudaEventDestroy(e3);
    cudaStreamDestroy(s2);
}